// round 7
// baseline (speedup 1.0000x reference)
#include <cuda_runtime.h>
#include <cuda_fp16.h>
#include <cstdint>

// ---------------- constants ----------------
#define IMG   224
#define BATCH 32
#define NPIX1 12544
#define NPIX2 3136
#define N1F   401408.0f
#define N2F   100352.0f

// conv1 smem geometry (unchanged from R5)
#define RSTRIDE 80
#define ATERM   10240
#define BOFF    20480
#define BTERM   5120
#define STAGE1  30720
#define DYN1    61440

// conv2 new geometry: swizzled, 3-stage
#define C2_BOFF  16384         // Ah 8192 + Al 8192
#define C2_STAGE 20480         // + B 32*128
#define C2_DYN   (3*C2_STAGE)  // 61440

// padded activation plane: 58 rows x 64 cols
#define PSTRIDE 64
#define PPLANE  3712           // 58*64
#define GUARD   128

// ---------------- scratch ----------------
__device__ __half g_out1[BATCH*128*NPIX1];
__device__ __half g_hp[GUARD + BATCH*128*PPLANE + GUARD];
__device__ __half g_hs[GUARD + BATCH*128*PPLANE + GUARD];   // g_hs[j] = g_hp[j+1]
__device__ __half g_w1h[128*160], g_w1l[128*160];
__device__ __half g_w2h[128*1152], g_w2l[128*1152];
__device__ int   g_win[28*8];
__device__ float g_sum1[128], g_sq1[128], g_sum2[128], g_sq2[128];

// ---------------- helpers ----------------
__device__ __forceinline__ uint32_t smem_u32(const void* p) {
    uint32_t a;
    asm("{ .reg .u64 t; cvta.to.shared.u64 t, %1; cvt.u32.u64 %0, t; }" : "=r"(a) : "l"(p));
    return a;
}
__device__ __forceinline__ void ldsm4(uint32_t addr, uint32_t* r) {
    asm volatile("ldmatrix.sync.aligned.m8n8.x4.shared.b16 {%0,%1,%2,%3}, [%4];"
        : "=r"(r[0]), "=r"(r[1]), "=r"(r[2]), "=r"(r[3]) : "r"(addr));
}
__device__ __forceinline__ void ldsm4t(uint32_t addr, uint32_t* r) {
    asm volatile("ldmatrix.sync.aligned.m8n8.x4.trans.shared.b16 {%0,%1,%2,%3}, [%4];"
        : "=r"(r[0]), "=r"(r[1]), "=r"(r[2]), "=r"(r[3]) : "r"(addr));
}
__device__ __forceinline__ void mma16816(float* c, const uint32_t* a, const uint32_t* b) {
    asm volatile("mma.sync.aligned.m16n8k16.row.col.f32.f16.f16.f32 "
        "{%0,%1,%2,%3}, {%4,%5,%6,%7}, {%8,%9}, {%0,%1,%2,%3};"
        : "+f"(c[0]), "+f"(c[1]), "+f"(c[2]), "+f"(c[3])
        : "r"(a[0]), "r"(a[1]), "r"(a[2]), "r"(a[3]), "r"(b[0]), "r"(b[1]));
}
__device__ __forceinline__ uint32_t hpack(float v0, float v1) {
    __half2 h = __floats2half2_rn(v0, v1);
    return *(uint32_t*)&h;
}
#define CP16(dst, src) \
    asm volatile("cp.async.cg.shared.global [%0], [%1], 16;" :: "r"(dst), "l"(src) : "memory")
#define CP4(dst, src) \
    asm volatile("cp.async.ca.shared.global [%0], [%1], 4;" :: "r"(dst), "l"(src) : "memory")
#define CPCOMMIT() asm volatile("cp.async.commit_group;" ::: "memory")
#define CPWAIT(n)  asm volatile("cp.async.wait_group %0;" :: "n"(n) : "memory")

// conv1 A staging (R5 layout, padded rows)
#define CPA(WH, WL, KDIM, s, buf, STAGE) do { \
    _Pragma("unroll") for (int i = 0; i < 4; i++) { \
        int id = tid + i*256, term = id >> 9, rem = id & 511, row = rem >> 2, c = rem & 3; \
        const __half* src = (term ? (WL) : (WH)) + row*(KDIM) + (s)*32 + c*8; \
        uint32_t dst = sb + (buf)*(STAGE) + term*ATERM + row*RSTRIDE + c*16; \
        CP16(dst, src); } \
    CPCOMMIT(); } while (0)

// ---------------- init ----------------
__global__ void k_init(const float* __restrict__ w1, const float* __restrict__ w2) {
    int tid = blockIdx.x * blockDim.x + threadIdx.x;
    if (tid < 128) { g_sum1[tid] = 0.f; g_sq1[tid] = 0.f; g_sum2[tid] = 0.f; g_sq2[tid] = 0.f; }
    if (tid < 128*160) {
        int oc = tid / 160, k = tid - oc*160;
        float v = (k < 147) ? w1[oc*147 + k] : 0.f;
        __half h = __float2half_rn(v);
        g_w1h[tid] = h;
        g_w1l[tid] = __float2half_rn(v - __half2float(h));
    }
    if (tid < 128*1152) {
        float v = w2[tid];
        __half h = __float2half_rn(v);
        g_w2h[tid] = h;
        g_w2l[tid] = __float2half_rn(v - __half2float(h));
    }
    if (blockIdx.x == 0 && threadIdx.x < 28) {
        int s = threadIdx.x >> 2, w = threadIdx.x & 3;
        int a = 16*s, b = a + 16, c = 224 - b, d = 224 - a;
        int t, l, bt, r;
        if      (w == 0) { t = a; l = a; bt = b; r = c; }
        else if (w == 1) { t = b; l = a; bt = d; r = b; }
        else if (w == 2) { t = c; l = b; bt = d; r = d; }
        else             { t = a; l = c; bt = c; r = d; }
        float scale = (float)(2.0 - (double)s / 6.0);
        int ti = (int)__fdiv_rn((float)(t  + 6), scale) - 3;
        int li = (int)__fdiv_rn((float)(l  + 6), scale) - 3;
        int bi = (int)__fdiv_rn((float)(bt + 6), scale) + 3;
        int ri = (int)__fdiv_rn((float)(r  + 6), scale) + 3;
        int to = t >> 1, lo = l >> 1;
        int oh = (bt >> 1) - to, oww = (r >> 1) - lo;
        int fh = (bi - ti - 7) / 2 + 1, fw = (ri - li - 7) / 2 + 1;
        int* p = g_win + threadIdx.x * 8;
        p[0]=ti; p[1]=li; p[2]=to; p[3]=lo; p[4]=oh; p[5]=oww; p[6]=fh; p[7]=fw;
    }
}

// ---------------- conv1: fp16x3, 32x32 warp tiles, cp.async A (R5, unchanged) ----------------
__global__ void __launch_bounds__(256, 2) k_conv1m(const float* __restrict__ inp) {
    extern __shared__ __align__(128) char dsm[];
    __shared__ int s_win[224];
    __shared__ int t_c[160];
    __shared__ signed char t_ky[160], t_kx[160];
    __shared__ float s_red[256];

    int tid = threadIdx.x, lane = tid & 31, wid = tid >> 5;
    int warp_m = wid & 3, warp_n = wid >> 2;

    if (tid < 224) s_win[tid] = g_win[tid];
    if (tid < 160) {
        int k = tid;
        if (k < 147) {
            int c = k / 49, r = k - c*49, ky = r / 7, kx = r - ky*7;
            t_c[k] = c * 50176; t_ky[k] = (signed char)ky; t_kx[k] = (signed char)kx;
        } else { t_c[k] = -1; t_ky[k] = 0; t_kx[k] = 0; }
    }
    s_red[tid] = 0.f;
    __syncthreads();

    int img = blockIdx.x / 196;
    int pixbase = (blockIdx.x - img*196) * 64;
    int pix = pixbase + (tid >> 2);
    int y = pix / 112, x = pix - y*112;
    int kq = tid & 3;

    int bi = y >> 3, bj = x >> 3;
    int sS = min(min(bi, bj), min(13 - bi, 13 - bj));
    int b2 = 8 * (sS + 1), c2v = 112 - b2;
    int w = (y < b2 && x < c2v) ? 0 : (x < b2 ? 1 : (y >= c2v ? 2 : 3));
    const int* wp = s_win + (sS*4 + w)*8;
    int iy0 = wp[0] + 2 * (((y - wp[2]) * wp[6]) / wp[4]) - 3;
    int ix0 = wp[1] + 2 * (((x - wp[3]) * wp[7]) / wp[5]) - 3;
    const float* ibase = inp + img * 150528;

    uint32_t sb = smem_u32(dsm);
    uint32_t Aln = (lane & 15)*RSTRIDE + (lane >> 4)*16;
    uint32_t Bln = ((lane >> 4)*8 + (lane & 7))*RSTRIDE + ((lane >> 3) & 1)*16;
    uint32_t bsts = (tid >> 2)*RSTRIDE + kq*16;

    uint32_t hw[4], lw[4];
    #define C1_LDGB(s) do { int kb = (s)*32 + kq*8; \
        float bv[8]; \
        _Pragma("unroll") for (int j = 0; j < 8; j++) { \
            int k = kb + j; \
            int iy = iy0 + t_ky[k], ix = ix0 + t_kx[k]; \
            bool v = (t_c[k] >= 0) && ((unsigned)iy < 224u) && ((unsigned)ix < 224u); \
            bv[j] = v ? __ldg(ibase + t_c[k] + iy*224 + ix) : 0.f; } \
        _Pragma("unroll") for (int j = 0; j < 4; j++) { \
            __half h0 = __float2half_rn(bv[2*j]), h1 = __float2half_rn(bv[2*j+1]); \
            float l0 = bv[2*j] - __half2float(h0), l1 = bv[2*j+1] - __half2float(h1); \
            hw[j] = ((uint32_t)__half_as_ushort(h1) << 16) | __half_as_ushort(h0); \
            lw[j] = hpack(l0, l1); } } while (0)
    #define C1_STSB(buf) do { \
        char* bp = dsm + (buf)*STAGE1 + BOFF + bsts; \
        *(uint4*)bp           = make_uint4(hw[0], hw[1], hw[2], hw[3]); \
        *(uint4*)(bp + BTERM) = make_uint4(lw[0], lw[1], lw[2], lw[3]); } while (0)

    float acc[2][4][4];
    #pragma unroll
    for (int a = 0; a < 2; a++)
        #pragma unroll
        for (int b = 0; b < 4; b++)
            #pragma unroll
            for (int c = 0; c < 4; c++) acc[a][b][c] = 0.f;

    CPA(g_w1h, g_w1l, 160, 0, 0, STAGE1);
    CPA(g_w1h, g_w1l, 160, 1, 1, STAGE1);
    C1_LDGB(0);
    CPWAIT(1);
    C1_STSB(0);
    __syncthreads();

    for (int s = 0; s < 5; s++) {
        int buf = s & 1;
        if (s < 4) C1_LDGB(s + 1);
        {
            uint32_t Ab = sb + buf*STAGE1 + warp_m*(32*RSTRIDE);
            uint32_t Bb = sb + buf*STAGE1 + BOFF + warp_n*(32*RSTRIDE);
            #pragma unroll
            for (int h = 0; h < 2; h++) {
                uint32_t ab = Ab + h*32 + Aln;
                uint32_t bb = Bb + h*32 + Bln;
                uint32_t am[2][4], bq[4][2], t[4];
                ldsm4(ab, am[0]); ldsm4(ab + 16*RSTRIDE, am[1]);
                ldsm4(bb, t); bq[0][0]=t[0]; bq[0][1]=t[1]; bq[1][0]=t[2]; bq[1][1]=t[3];
                ldsm4(bb + 16*RSTRIDE, t); bq[2][0]=t[0]; bq[2][1]=t[1]; bq[3][0]=t[2]; bq[3][1]=t[3];
                #pragma unroll
                for (int mt = 0; mt < 2; mt++)
                    #pragma unroll
                    for (int nt = 0; nt < 4; nt++) mma16816(acc[mt][nt], am[mt], bq[nt]);
                ldsm4(ab + ATERM, am[0]); ldsm4(ab + ATERM + 16*RSTRIDE, am[1]);
                #pragma unroll
                for (int mt = 0; mt < 2; mt++)
                    #pragma unroll
                    for (int nt = 0; nt < 4; nt++) mma16816(acc[mt][nt], am[mt], bq[nt]);
                ldsm4(ab, am[0]); ldsm4(ab + 16*RSTRIDE, am[1]);
                ldsm4(bb + BTERM, t); bq[0][0]=t[0]; bq[0][1]=t[1]; bq[1][0]=t[2]; bq[1][1]=t[3];
                ldsm4(bb + BTERM + 16*RSTRIDE, t); bq[2][0]=t[0]; bq[2][1]=t[1]; bq[3][0]=t[2]; bq[3][1]=t[3];
                #pragma unroll
                for (int mt = 0; mt < 2; mt++)
                    #pragma unroll
                    for (int nt = 0; nt < 4; nt++) mma16816(acc[mt][nt], am[mt], bq[nt]);
            }
        }
        if (s < 4) {
            CPWAIT(0);
            C1_STSB(buf ^ 1);
            __syncthreads();
            if (s + 2 < 5) CPA(g_w1h, g_w1l, 160, s + 2, buf, STAGE1);
        }
    }

    int g = lane >> 2, cp = (lane & 3) * 2;
    #pragma unroll
    for (int mt = 0; mt < 2; mt++) {
        #pragma unroll
        for (int hh = 0; hh < 2; hh++) {
            int oc = warp_m*32 + mt*16 + hh*8 + g;
            float sv = 0.f, qv = 0.f;
            __half* obase = g_out1 + (size_t)(img*128 + oc)*NPIX1 + pixbase;
            #pragma unroll
            for (int nt = 0; nt < 4; nt++) {
                float c0 = acc[mt][nt][hh*2], c1 = acc[mt][nt][hh*2 + 1];
                int pxl = warp_n*32 + nt*8 + cp;
                *(__half2*)(obase + pxl) = __floats2half2_rn(c0, c1);
                sv += c0 + c1; qv += c0*c0 + c1*c1;
            }
            atomicAdd(&s_red[oc], sv);
            atomicAdd(&s_red[128 + oc], qv);
        }
    }
    __syncthreads();
    if (tid < 128) {
        atomicAdd(&g_sum1[tid], s_red[tid]);
        atomicAdd(&g_sq1[tid],  s_red[128 + tid]);
    }
}

// ---------------- BN1 + ReLU + maxpool -> padded planes (hp + shifted hs) ----------------
__global__ void k_pool(const float* __restrict__ gamma, const float* __restrict__ beta) {
    int idx = blockIdx.x * 256 + threadIdx.x;
    if (idx >= BATCH * 128 * PPLANE) return;
    int nc = idx / PPLANE;
    int p  = idx - nc * PPLANE;
    int yp = p >> 6, xp = p & 63;
    float v = 0.f;
    if (yp >= 1 && yp <= 56 && xp >= 1 && xp <= 56) {
        int y = yp - 1, x = xp - 1;
        int c = nc & 127;
        float mean = g_sum1[c] * (1.f / N1F);
        float var  = g_sq1[c]  * (1.f / N1F) - mean * mean;
        float a = __ldg(gamma + c) * rsqrtf(var + 1e-5f);
        float b = __ldg(beta + c) - a * mean;
        const __half* src = g_out1 + (size_t)nc * NPIX1;
        float m = -1e30f;
        #pragma unroll
        for (int dy = 0; dy < 3; dy++) {
            int yy = 2*y - 1 + dy;
            if ((unsigned)yy >= 112u) continue;
            #pragma unroll
            for (int dx = 0; dx < 3; dx++) {
                int xx = 2*x - 1 + dx;
                if ((unsigned)xx >= 112u) continue;
                m = fmaxf(m, fmaf(a, __half2float(src[yy*112 + xx]), b));
            }
        }
        v = fmaxf(m, 0.f);
    }
    __half h = __float2half_rn(v);
    g_hp[GUARD + idx] = h;
    g_hs[GUARD + idx - 1] = h;
}

// ---------------- conv2: pure-async fp16x2 implicit GEMM over padded rows ----------------
// CTA = 128 oc x one padded row (64 px, xp 1..56 valid). K=1152 in 36 chunks of 32.
// 3-stage cp.async pipeline; swizzled smem; no LDG/STS in loop.
__global__ void __launch_bounds__(256, 3) k_conv2m(float* __restrict__ out) {
    extern __shared__ __align__(128) char dsm[];
    __shared__ int t_bo[1152];       // ((ic*PPLANE + even_off) << 1) | use_shifted
    __shared__ float s_red[256];

    int tid = threadIdx.x, lane = tid & 31, wid = tid >> 5;
    int warp_m = wid & 3, warp_n = wid >> 2;

    for (int k = tid; k < 1152; k += 256) {
        int ic = k / 9, r = k - ic*9;
        int dy = r/3 - 1, dx = r - (r/3)*3 - 1;
        int off = dy*PSTRIDE + dx;
        int sel = off & 1;
        t_bo[k] = ((ic*PPLANE + (off - sel)) << 1) | sel;
    }
    s_red[tid] = 0.f;
    __syncthreads();

    int img = blockIdx.x / 56;
    int yp  = (blockIdx.x - img*56) + 1;        // padded row 1..56
    int pp0 = yp * PSTRIDE;
    size_t ibase = (size_t)img * 128 * PPLANE;
    const __half* HP = g_hp + GUARD;
    const __half* HS = g_hs + GUARD;

    uint32_t sb = smem_u32(dsm);

    // ---- cp.async staging for one k-chunk ----
    #define C2_CPA(s, buf) do { \
        _Pragma("unroll") for (int i = 0; i < 4; i++) { \
            int id = tid + i*256, term = id >> 9, rem = id & 511, row = rem >> 2, c = rem & 3; \
            const __half* src = (term ? g_w2l : g_w2h) + row*1152 + (s)*32 + c*8; \
            uint32_t dst = sb + (buf)*C2_STAGE + term*8192 + row*64 + (((c ^ ((row>>1)&3)) << 4)); \
            CP16(dst, src); } } while (0)
    #define C2_CPB(s, buf) do { \
        _Pragma("unroll") for (int i = 0; i < 4; i++) { \
            int id = tid + i*256, krow = id >> 5, ch = id & 31; \
            int bo = t_bo[(s)*32 + krow]; \
            const __half* base = (bo & 1) ? HS : HP; \
            const __half* src = base + ibase + (bo >> 1) + pp0 + ch*2; \
            uint32_t dst = sb + (buf)*C2_STAGE + C2_BOFF + krow*128 \
                         + (((ch >> 2) ^ (krow & 7)) << 4) + ((ch & 3) << 2); \
            CP4(dst, src); } } while (0)

    // ---- per-thread ldmatrix addressing (swizzled) ----
    uint32_t arow = warp_m*32 + (lane & 15);
    uint32_t aswz = (arow >> 1) & 3;
    uint32_t arb  = arow * 64;
    uint32_t acol = lane >> 4;                         // 0/1 (k 16B-group)
    uint32_t brow = ((lane >> 3) & 1)*8 + (lane & 7);  // k row within 16
    uint32_t bswz = lane & 7;
    uint32_t bg0  = warp_n*4 + (lane >> 4);            // px 16B-group base

    float acc[2][4][4];
    #pragma unroll
    for (int a = 0; a < 2; a++)
        #pragma unroll
        for (int b = 0; b < 4; b++)
            #pragma unroll
            for (int c = 0; c < 4; c++) acc[a][b][c] = 0.f;

    // prologue: stages 0,1
    C2_CPA(0, 0); C2_CPB(0, 0); CPCOMMIT();
    C2_CPA(1, 1); C2_CPB(1, 1); CPCOMMIT();

    for (int s = 0; s < 36; s++) {
        CPWAIT(1);
        __syncthreads();
        int nb = (s + 2) % 3;
        if (s + 2 < 36) { C2_CPA(s + 2, nb); C2_CPB(s + 2, nb); }
        CPCOMMIT();

        uint32_t bufb = sb + (s % 3) * C2_STAGE;
        #pragma unroll
        for (int h = 0; h < 2; h++) {
            uint32_t t[4];
            uint32_t bq[4][2];
            uint32_t bbase = bufb + C2_BOFF + (h*16 + brow)*128;
            ldsm4t(bbase + ((bg0 ^ bswz) << 4), t);
            bq[0][0]=t[0]; bq[0][1]=t[1]; bq[1][0]=t[2]; bq[1][1]=t[3];
            ldsm4t(bbase + (((bg0 + 2) ^ bswz) << 4), t);
            bq[2][0]=t[0]; bq[2][1]=t[1]; bq[3][0]=t[2]; bq[3][1]=t[3];

            uint32_t ac = (((h*2) + acol) ^ aswz) << 4;
            uint32_t am[2][4];
            ldsm4(bufb + arb + ac, am[0]);
            ldsm4(bufb + arb + 1024 + ac, am[1]);
            #pragma unroll
            for (int mt = 0; mt < 2; mt++)
                #pragma unroll
                for (int nt = 0; nt < 4; nt++) mma16816(acc[mt][nt], am[mt], bq[nt]);
            ldsm4(bufb + 8192 + arb + ac, am[0]);
            ldsm4(bufb + 8192 + arb + 1024 + ac, am[1]);
            #pragma unroll
            for (int mt = 0; mt < 2; mt++)
                #pragma unroll
                for (int nt = 0; nt < 4; nt++) mma16816(acc[mt][nt], am[mt], bq[nt]);
        }
    }

    // epilogue: store valid pixels (xp 1..56) + BN2 stats
    int g = lane >> 2, cp = (lane & 3) * 2;
    #pragma unroll
    for (int mt = 0; mt < 2; mt++) {
        #pragma unroll
        for (int hh = 0; hh < 2; hh++) {
            int oc = warp_m*32 + mt*16 + hh*8 + g;
            float sv = 0.f, qv = 0.f;
            float* obase = out + (size_t)(img*128 + oc)*NPIX2 + (yp - 1)*56 - 1;
            #pragma unroll
            for (int nt = 0; nt < 4; nt++) {
                float c0 = acc[mt][nt][hh*2], c1 = acc[mt][nt][hh*2 + 1];
                int xp = warp_n*32 + nt*8 + cp;
                if (xp >= 1 && xp <= 56) { obase[xp] = c0; sv += c0; qv += c0*c0; }
                if (xp + 1 <= 56 && xp + 1 >= 1) { obase[xp + 1] = c1; sv += c1; qv += c1*c1; }
            }
            atomicAdd(&s_red[oc], sv);
            atomicAdd(&s_red[128 + oc], qv);
        }
    }
    __syncthreads();
    if (tid < 128) {
        atomicAdd(&g_sum2[tid], s_red[tid]);
        atomicAdd(&g_sq2[tid],  s_red[128 + tid]);
    }
}

// ---------------- BN2(inline) + ReLU in place ----------------
__global__ void k_bn2(float* __restrict__ out,
                      const float* __restrict__ gamma, const float* __restrict__ beta) {
    int idx = blockIdx.x * 256 + threadIdx.x;
    if (idx >= BATCH * 128 * NPIX2) return;
    int c = (idx / NPIX2) & 127;
    float mean = g_sum2[c] * (1.f / N2F);
    float var  = g_sq2[c]  * (1.f / N2F) - mean * mean;
    float a = __ldg(gamma + c) * rsqrtf(var + 1e-5f);
    float b = __ldg(beta + c) - a * mean;
    out[idx] = fmaxf(fmaf(a, out[idx], b), 0.f);
}

// ---------------- launch ----------------
extern "C" void kernel_launch(void* const* d_in, const int* in_sizes, int n_in,
                              void* d_out, int out_size) {
    const float* inp = (const float*)d_in[0];
    const float* w1  = (const float*)d_in[1];
    const float* g1  = (const float*)d_in[2];
    const float* b1  = (const float*)d_in[3];
    const float* w2  = (const float*)d_in[4];
    const float* g2  = (const float*)d_in[5];
    const float* b2  = (const float*)d_in[6];
    float* out = (float*)d_out;

    cudaFuncSetAttribute(k_conv1m, cudaFuncAttributeMaxDynamicSharedMemorySize, DYN1);
    cudaFuncSetAttribute(k_conv2m, cudaFuncAttributeMaxDynamicSharedMemorySize, C2_DYN);

    k_init<<<576, 256>>>(w1, w2);
    k_conv1m<<<6272, 256, DYN1>>>(inp);
    k_pool<<<(BATCH*128*PPLANE + 255) / 256, 256>>>(g1, b1);
    k_conv2m<<<BATCH*56, 256, C2_DYN>>>(out);
    k_bn2<<<(BATCH*128*NPIX2 + 255) / 256, 256>>>(out, g2, b2);
}

// round 8
// speedup vs baseline: 1.2796x; 1.2796x over previous
#include <cuda_runtime.h>
#include <cuda_fp16.h>
#include <cstdint>

// ---------------- constants ----------------
#define IMG   224
#define BATCH 32
#define NPIX1 12544
#define NPIX2 3136
#define N1F   401408.0f
#define N2F   100352.0f

// conv1 smem geometry
#define RSTRIDE 80
#define ATERM   10240
#define BOFF    20480
#define BTERM   5120
#define STAGE1  30720
#define DYN1    61440

// conv2 geometry (R7)
#define C2_BOFF  16384
#define C2_STAGE 20480
#define C2_DYN   (3*C2_STAGE)

// padded activation plane
#define PSTRIDE 64
#define PPLANE  3712
#define GUARD   128

// packed conv1 output
#define NPMAX 5376             // >= actual packed count (~4859), multiple of 64

struct Win { int ti, li, to, lo, oh, ow, fh, fw, base; };
struct WinTab { Win w[28]; };

// ---------------- scratch ----------------
__device__ __half g_fpk[BATCH*128*NPMAX];                 // packed conv1 out (44 MB)
__device__ __half g_hp[GUARD + BATCH*128*PPLANE + GUARD];
__device__ __half g_hs[GUARD + BATCH*128*PPLANE + GUARD];
__device__ __half g_w1h[128*160], g_w1l[128*160];
__device__ __half g_w2h[128*1152], g_w2l[128*1152];
__device__ int   g_map[NPIX1];
__device__ int   g_wgt[NPMAX];
__device__ int2  g_pc[NPMAX];
__device__ float g_sum1[128], g_sq1[128], g_sum2[128], g_sq2[128];

// ---------------- helpers ----------------
__device__ __forceinline__ uint32_t smem_u32(const void* p) {
    uint32_t a;
    asm("{ .reg .u64 t; cvta.to.shared.u64 t, %1; cvt.u32.u64 %0, t; }" : "=r"(a) : "l"(p));
    return a;
}
__device__ __forceinline__ void ldsm4(uint32_t addr, uint32_t* r) {
    asm volatile("ldmatrix.sync.aligned.m8n8.x4.shared.b16 {%0,%1,%2,%3}, [%4];"
        : "=r"(r[0]), "=r"(r[1]), "=r"(r[2]), "=r"(r[3]) : "r"(addr));
}
__device__ __forceinline__ void ldsm4t(uint32_t addr, uint32_t* r) {
    asm volatile("ldmatrix.sync.aligned.m8n8.x4.trans.shared.b16 {%0,%1,%2,%3}, [%4];"
        : "=r"(r[0]), "=r"(r[1]), "=r"(r[2]), "=r"(r[3]) : "r"(addr));
}
__device__ __forceinline__ void mma16816(float* c, const uint32_t* a, const uint32_t* b) {
    asm volatile("mma.sync.aligned.m16n8k16.row.col.f32.f16.f16.f32 "
        "{%0,%1,%2,%3}, {%4,%5,%6,%7}, {%8,%9}, {%0,%1,%2,%3};"
        : "+f"(c[0]), "+f"(c[1]), "+f"(c[2]), "+f"(c[3])
        : "r"(a[0]), "r"(a[1]), "r"(a[2]), "r"(a[3]), "r"(b[0]), "r"(b[1]));
}
__device__ __forceinline__ uint32_t hpack(float v0, float v1) {
    __half2 h = __floats2half2_rn(v0, v1);
    return *(uint32_t*)&h;
}
#define CP16(dst, src) \
    asm volatile("cp.async.cg.shared.global [%0], [%1], 16;" :: "r"(dst), "l"(src) : "memory")
#define CP4(dst, src) \
    asm volatile("cp.async.ca.shared.global [%0], [%1], 4;" :: "r"(dst), "l"(src) : "memory")
#define CPCOMMIT() asm volatile("cp.async.commit_group;" ::: "memory")
#define CPWAIT(n)  asm volatile("cp.async.wait_group %0;" :: "n"(n) : "memory")

#define CPA(WH, WL, KDIM, s, buf, STAGE) do { \
    _Pragma("unroll") for (int i = 0; i < 4; i++) { \
        int id = tid + i*256, term = id >> 9, rem = id & 511, row = rem >> 2, c = rem & 3; \
        const __half* src = (term ? (WL) : (WH)) + row*(KDIM) + (s)*32 + c*8; \
        uint32_t dst = sb + (buf)*(STAGE) + term*ATERM + row*RSTRIDE + c*16; \
        CP16(dst, src); } \
    CPCOMMIT(); } while (0)

// ---------------- init: weights split + table defaults ----------------
__global__ void k_init(const float* __restrict__ w1, const float* __restrict__ w2) {
    int tid = blockIdx.x * blockDim.x + threadIdx.x;
    if (tid < 128) { g_sum1[tid] = 0.f; g_sq1[tid] = 0.f; g_sum2[tid] = 0.f; g_sq2[tid] = 0.f; }
    if (tid < NPMAX) { g_wgt[tid] = 0; g_pc[tid] = make_int2(0, 0); }
    if (tid < 128*160) {
        int oc = tid / 160, k = tid - oc*160;
        float v = (k < 147) ? w1[oc*147 + k] : 0.f;
        __half h = __float2half_rn(v);
        g_w1h[tid] = h;
        g_w1l[tid] = __float2half_rn(v - __half2float(h));
    }
    if (tid < 128*1152) {
        float v = w2[tid];
        __half h = __float2half_rn(v);
        g_w2h[tid] = h;
        g_w2l[tid] = __float2half_rn(v - __half2float(h));
    }
}

// ---------------- map builder: output pixel -> packed id, weights, coords ----------------
__global__ void k_map(WinTab tab) {
    int pix = blockIdx.x * 256 + threadIdx.x;
    if (pix >= NPIX1) return;
    int y = pix / 112, x = pix - y*112;
    int bi = y >> 3, bj = x >> 3;
    int sS = min(min(bi, bj), min(13 - bi, 13 - bj));
    int b2 = 8 * (sS + 1), c2v = 112 - b2;
    int w = (y < b2 && x < c2v) ? 0 : (x < b2 ? 1 : (y >= c2v ? 2 : 3));
    Win W = tab.w[sS*4 + w];
    int fy = ((y - W.to) * W.fh) / W.oh;
    int fx = ((x - W.lo) * W.fw) / W.ow;
    int id = W.base + fy * W.fw + fx;
    g_map[pix] = id;
    atomicAdd(&g_wgt[id], 1);
    g_pc[id] = make_int2(W.ti + 2*fy - 3, W.li + 2*fx - 3);
}

// ---------------- conv1: fp16x3 over PACKED pixels ----------------
__global__ void __launch_bounds__(256, 2) k_conv1m(const float* __restrict__ inp) {
    extern __shared__ __align__(128) char dsm[];
    __shared__ int t_c[160];
    __shared__ signed char t_ky[160], t_kx[160];
    __shared__ float s_red[256];
    __shared__ float s_wgt[64];

    int tid = threadIdx.x, lane = tid & 31, wid = tid >> 5;
    int warp_m = wid & 3, warp_n = wid >> 2;

    if (tid < 160) {
        int k = tid;
        if (k < 147) {
            int c = k / 49, r = k - c*49, ky = r / 7, kx = r - ky*7;
            t_c[k] = c * 50176; t_ky[k] = (signed char)ky; t_kx[k] = (signed char)kx;
        } else { t_c[k] = -1; t_ky[k] = 0; t_kx[k] = 0; }
    }
    s_red[tid] = 0.f;

    int img = blockIdx.y;
    int pixbase = blockIdx.x * 64;
    if (tid < 64) s_wgt[tid] = (float)g_wgt[pixbase + tid];
    __syncthreads();

    int pix = pixbase + (tid >> 2);
    int kq = tid & 3;
    int2 pcv = g_pc[pix];
    int iy0 = pcv.x, ix0 = pcv.y;
    const float* ibase = inp + img * 150528;

    uint32_t sb = smem_u32(dsm);
    uint32_t Aln = (lane & 15)*RSTRIDE + (lane >> 4)*16;
    uint32_t Bln = ((lane >> 4)*8 + (lane & 7))*RSTRIDE + ((lane >> 3) & 1)*16;
    uint32_t bsts = (tid >> 2)*RSTRIDE + kq*16;

    uint32_t hw[4], lw[4];
    #define C1_LDGB(s) do { int kb = (s)*32 + kq*8; \
        float bv[8]; \
        _Pragma("unroll") for (int j = 0; j < 8; j++) { \
            int k = kb + j; \
            int iy = iy0 + t_ky[k], ix = ix0 + t_kx[k]; \
            bool v = (t_c[k] >= 0) && ((unsigned)iy < 224u) && ((unsigned)ix < 224u); \
            bv[j] = v ? __ldg(ibase + t_c[k] + iy*224 + ix) : 0.f; } \
        _Pragma("unroll") for (int j = 0; j < 4; j++) { \
            __half h0 = __float2half_rn(bv[2*j]), h1 = __float2half_rn(bv[2*j+1]); \
            float l0 = bv[2*j] - __half2float(h0), l1 = bv[2*j+1] - __half2float(h1); \
            hw[j] = ((uint32_t)__half_as_ushort(h1) << 16) | __half_as_ushort(h0); \
            lw[j] = hpack(l0, l1); } } while (0)
    #define C1_STSB(buf) do { \
        char* bp = dsm + (buf)*STAGE1 + BOFF + bsts; \
        *(uint4*)bp           = make_uint4(hw[0], hw[1], hw[2], hw[3]); \
        *(uint4*)(bp + BTERM) = make_uint4(lw[0], lw[1], lw[2], lw[3]); } while (0)

    float acc[2][4][4];
    #pragma unroll
    for (int a = 0; a < 2; a++)
        #pragma unroll
        for (int b = 0; b < 4; b++)
            #pragma unroll
            for (int c = 0; c < 4; c++) acc[a][b][c] = 0.f;

    CPA(g_w1h, g_w1l, 160, 0, 0, STAGE1);
    CPA(g_w1h, g_w1l, 160, 1, 1, STAGE1);
    C1_LDGB(0);
    CPWAIT(1);
    C1_STSB(0);
    __syncthreads();

    for (int s = 0; s < 5; s++) {
        int buf = s & 1;
        if (s < 4) C1_LDGB(s + 1);
        {
            uint32_t Ab = sb + buf*STAGE1 + warp_m*(32*RSTRIDE);
            uint32_t Bb = sb + buf*STAGE1 + BOFF + warp_n*(32*RSTRIDE);
            #pragma unroll
            for (int h = 0; h < 2; h++) {
                uint32_t ab = Ab + h*32 + Aln;
                uint32_t bb = Bb + h*32 + Bln;
                uint32_t am[2][4], bq[4][2], t[4];
                ldsm4(ab, am[0]); ldsm4(ab + 16*RSTRIDE, am[1]);
                ldsm4(bb, t); bq[0][0]=t[0]; bq[0][1]=t[1]; bq[1][0]=t[2]; bq[1][1]=t[3];
                ldsm4(bb + 16*RSTRIDE, t); bq[2][0]=t[0]; bq[2][1]=t[1]; bq[3][0]=t[2]; bq[3][1]=t[3];
                #pragma unroll
                for (int mt = 0; mt < 2; mt++)
                    #pragma unroll
                    for (int nt = 0; nt < 4; nt++) mma16816(acc[mt][nt], am[mt], bq[nt]);
                ldsm4(ab + ATERM, am[0]); ldsm4(ab + ATERM + 16*RSTRIDE, am[1]);
                #pragma unroll
                for (int mt = 0; mt < 2; mt++)
                    #pragma unroll
                    for (int nt = 0; nt < 4; nt++) mma16816(acc[mt][nt], am[mt], bq[nt]);
                ldsm4(ab, am[0]); ldsm4(ab + 16*RSTRIDE, am[1]);
                ldsm4(bb + BTERM, t); bq[0][0]=t[0]; bq[0][1]=t[1]; bq[1][0]=t[2]; bq[1][1]=t[3];
                ldsm4(bb + BTERM + 16*RSTRIDE, t); bq[2][0]=t[0]; bq[2][1]=t[1]; bq[3][0]=t[2]; bq[3][1]=t[3];
                #pragma unroll
                for (int mt = 0; mt < 2; mt++)
                    #pragma unroll
                    for (int nt = 0; nt < 4; nt++) mma16816(acc[mt][nt], am[mt], bq[nt]);
            }
        }
        if (s < 4) {
            CPWAIT(0);
            C1_STSB(buf ^ 1);
            __syncthreads();
            if (s + 2 < 5) CPA(g_w1h, g_w1l, 160, s + 2, buf, STAGE1);
        }
    }

    // epilogue: packed store + weighted BN1 stats
    int g = lane >> 2, cp = (lane & 3) * 2;
    #pragma unroll
    for (int mt = 0; mt < 2; mt++) {
        #pragma unroll
        for (int hh = 0; hh < 2; hh++) {
            int oc = warp_m*32 + mt*16 + hh*8 + g;
            float sv = 0.f, qv = 0.f;
            __half* obase = g_fpk + (size_t)(img*128 + oc)*NPMAX + pixbase;
            #pragma unroll
            for (int nt = 0; nt < 4; nt++) {
                float c0 = acc[mt][nt][hh*2], c1 = acc[mt][nt][hh*2 + 1];
                int pxl = warp_n*32 + nt*8 + cp;
                *(__half2*)(obase + pxl) = __floats2half2_rn(c0, c1);
                float w0 = s_wgt[pxl], w1 = s_wgt[pxl + 1];
                sv += w0*c0 + w1*c1; qv += w0*c0*c0 + w1*c1*c1;
            }
            atomicAdd(&s_red[oc], sv);
            atomicAdd(&s_red[128 + oc], qv);
        }
    }
    __syncthreads();
    if (tid < 128) {
        atomicAdd(&g_sum1[tid], s_red[tid]);
        atomicAdd(&g_sq1[tid],  s_red[128 + tid]);
    }
}

// ---------------- BN1 + ReLU + maxpool via map -> padded planes ----------------
__global__ void k_pool(const float* __restrict__ gamma, const float* __restrict__ beta) {
    int idx = blockIdx.x * 256 + threadIdx.x;
    if (idx >= BATCH * 128 * PPLANE) return;
    int nc = idx / PPLANE;
    int p  = idx - nc * PPLANE;
    int yp = p >> 6, xp = p & 63;
    float v = 0.f;
    if (yp >= 1 && yp <= 56 && xp >= 1 && xp <= 56) {
        int y = yp - 1, x = xp - 1;
        int c = nc & 127;
        float mean = g_sum1[c] * (1.f / N1F);
        float var  = g_sq1[c]  * (1.f / N1F) - mean * mean;
        float a = __ldg(gamma + c) * rsqrtf(var + 1e-5f);
        float b = __ldg(beta + c) - a * mean;
        const __half* src = g_fpk + (size_t)nc * NPMAX;
        float m = -1e30f;
        #pragma unroll
        for (int dy = 0; dy < 3; dy++) {
            int yy = 2*y - 1 + dy;
            if ((unsigned)yy >= 112u) continue;
            #pragma unroll
            for (int dx = 0; dx < 3; dx++) {
                int xx = 2*x - 1 + dx;
                if ((unsigned)xx >= 112u) continue;
                m = fmaxf(m, fmaf(a, __half2float(src[g_map[yy*112 + xx]]), b));
            }
        }
        v = fmaxf(m, 0.f);
    }
    __half h = __float2half_rn(v);
    g_hp[GUARD + idx] = h;
    g_hs[GUARD + idx - 1] = h;
}

// ---------------- conv2: pure-async fp16x2 implicit GEMM (R7, unchanged) ----------------
__global__ void __launch_bounds__(256, 3) k_conv2m(float* __restrict__ out) {
    extern __shared__ __align__(128) char dsm[];
    __shared__ int t_bo[1152];
    __shared__ float s_red[256];

    int tid = threadIdx.x, lane = tid & 31, wid = tid >> 5;
    int warp_m = wid & 3, warp_n = wid >> 2;

    for (int k = tid; k < 1152; k += 256) {
        int ic = k / 9, r = k - ic*9;
        int dy = r/3 - 1, dx = r - (r/3)*3 - 1;
        int off = dy*PSTRIDE + dx;
        int sel = off & 1;
        t_bo[k] = ((ic*PPLANE + (off - sel)) << 1) | sel;
    }
    s_red[tid] = 0.f;
    __syncthreads();

    int img = blockIdx.x / 56;
    int yp  = (blockIdx.x - img*56) + 1;
    int pp0 = yp * PSTRIDE;
    size_t ibase = (size_t)img * 128 * PPLANE;
    const __half* HP = g_hp + GUARD;
    const __half* HS = g_hs + GUARD;

    uint32_t sb = smem_u32(dsm);

    #define C2_CPA(s, buf) do { \
        _Pragma("unroll") for (int i = 0; i < 4; i++) { \
            int id = tid + i*256, term = id >> 9, rem = id & 511, row = rem >> 2, c = rem & 3; \
            const __half* src = (term ? g_w2l : g_w2h) + row*1152 + (s)*32 + c*8; \
            uint32_t dst = sb + (buf)*C2_STAGE + term*8192 + row*64 + (((c ^ ((row>>1)&3)) << 4)); \
            CP16(dst, src); } } while (0)
    #define C2_CPB(s, buf) do { \
        _Pragma("unroll") for (int i = 0; i < 4; i++) { \
            int id = tid + i*256, krow = id >> 5, ch = id & 31; \
            int bo = t_bo[(s)*32 + krow]; \
            const __half* base = (bo & 1) ? HS : HP; \
            const __half* src = base + ibase + (bo >> 1) + pp0 + ch*2; \
            uint32_t dst = sb + (buf)*C2_STAGE + C2_BOFF + krow*128 \
                         + (((ch >> 2) ^ (krow & 7)) << 4) + ((ch & 3) << 2); \
            CP4(dst, src); } } while (0)

    uint32_t arow = warp_m*32 + (lane & 15);
    uint32_t aswz = (arow >> 1) & 3;
    uint32_t arb  = arow * 64;
    uint32_t acol = lane >> 4;
    uint32_t brow = ((lane >> 3) & 1)*8 + (lane & 7);
    uint32_t bswz = lane & 7;
    uint32_t bg0  = warp_n*4 + (lane >> 4);

    float acc[2][4][4];
    #pragma unroll
    for (int a = 0; a < 2; a++)
        #pragma unroll
        for (int b = 0; b < 4; b++)
            #pragma unroll
            for (int c = 0; c < 4; c++) acc[a][b][c] = 0.f;

    C2_CPA(0, 0); C2_CPB(0, 0); CPCOMMIT();
    C2_CPA(1, 1); C2_CPB(1, 1); CPCOMMIT();

    for (int s = 0; s < 36; s++) {
        CPWAIT(1);
        __syncthreads();
        int nb = (s + 2) % 3;
        if (s + 2 < 36) { C2_CPA(s + 2, nb); C2_CPB(s + 2, nb); }
        CPCOMMIT();

        uint32_t bufb = sb + (s % 3) * C2_STAGE;
        #pragma unroll
        for (int h = 0; h < 2; h++) {
            uint32_t t[4];
            uint32_t bq[4][2];
            uint32_t bbase = bufb + C2_BOFF + (h*16 + brow)*128;
            ldsm4t(bbase + ((bg0 ^ bswz) << 4), t);
            bq[0][0]=t[0]; bq[0][1]=t[1]; bq[1][0]=t[2]; bq[1][1]=t[3];
            ldsm4t(bbase + (((bg0 + 2) ^ bswz) << 4), t);
            bq[2][0]=t[0]; bq[2][1]=t[1]; bq[3][0]=t[2]; bq[3][1]=t[3];

            uint32_t ac = (((h*2) + acol) ^ aswz) << 4;
            uint32_t am[2][4];
            ldsm4(bufb + arb + ac, am[0]);
            ldsm4(bufb + arb + 1024 + ac, am[1]);
            #pragma unroll
            for (int mt = 0; mt < 2; mt++)
                #pragma unroll
                for (int nt = 0; nt < 4; nt++) mma16816(acc[mt][nt], am[mt], bq[nt]);
            ldsm4(bufb + 8192 + arb + ac, am[0]);
            ldsm4(bufb + 8192 + arb + 1024 + ac, am[1]);
            #pragma unroll
            for (int mt = 0; mt < 2; mt++)
                #pragma unroll
                for (int nt = 0; nt < 4; nt++) mma16816(acc[mt][nt], am[mt], bq[nt]);
        }
    }

    int g = lane >> 2, cp = (lane & 3) * 2;
    #pragma unroll
    for (int mt = 0; mt < 2; mt++) {
        #pragma unroll
        for (int hh = 0; hh < 2; hh++) {
            int oc = warp_m*32 + mt*16 + hh*8 + g;
            float sv = 0.f, qv = 0.f;
            float* obase = out + (size_t)(img*128 + oc)*NPIX2 + (yp - 1)*56 - 1;
            #pragma unroll
            for (int nt = 0; nt < 4; nt++) {
                float c0 = acc[mt][nt][hh*2], c1 = acc[mt][nt][hh*2 + 1];
                int xp = warp_n*32 + nt*8 + cp;
                if (xp >= 1 && xp <= 56) { obase[xp] = c0; sv += c0; qv += c0*c0; }
                if (xp + 1 <= 56 && xp + 1 >= 1) { obase[xp + 1] = c1; sv += c1; qv += c1*c1; }
            }
            atomicAdd(&s_red[oc], sv);
            atomicAdd(&s_red[128 + oc], qv);
        }
    }
    __syncthreads();
    if (tid < 128) {
        atomicAdd(&g_sum2[tid], s_red[tid]);
        atomicAdd(&g_sq2[tid],  s_red[128 + tid]);
    }
}

// ---------------- BN2(inline) + ReLU in place ----------------
__global__ void k_bn2(float* __restrict__ out,
                      const float* __restrict__ gamma, const float* __restrict__ beta) {
    int idx = blockIdx.x * 256 + threadIdx.x;
    if (idx >= BATCH * 128 * NPIX2) return;
    int c = (idx / NPIX2) & 127;
    float mean = g_sum2[c] * (1.f / N2F);
    float var  = g_sq2[c]  * (1.f / N2F) - mean * mean;
    float a = __ldg(gamma + c) * rsqrtf(var + 1e-5f);
    float b = __ldg(beta + c) - a * mean;
    out[idx] = fmaxf(fmaf(a, out[idx], b), 0.f);
}

// ---------------- launch ----------------
extern "C" void kernel_launch(void* const* d_in, const int* in_sizes, int n_in,
                              void* d_out, int out_size) {
    const float* inp = (const float*)d_in[0];
    const float* w1  = (const float*)d_in[1];
    const float* g1  = (const float*)d_in[2];
    const float* b1  = (const float*)d_in[3];
    const float* w2  = (const float*)d_in[4];
    const float* g2  = (const float*)d_in[5];
    const float* b2  = (const float*)d_in[6];
    float* out = (float*)d_out;

    // host-side window table (identical float math to numpy reference)
    WinTab tab;
    int np = 0;
    for (int s = 0; s < 7; s++) {
        int a = 16*s, b = a + 16, c = 224 - b, d = 224 - a;
        float scale = (float)(2.0 - (double)s / 6.0);
        for (int w = 0; w < 4; w++) {
            int t, l, bt, r;
            if      (w == 0) { t = a; l = a; bt = b; r = c; }
            else if (w == 1) { t = b; l = a; bt = d; r = b; }
            else if (w == 2) { t = c; l = b; bt = d; r = d; }
            else             { t = a; l = c; bt = c; r = d; }
            Win& W = tab.w[s*4 + w];
            W.ti = (int)((float)(t  + 6) / scale) - 3;
            W.li = (int)((float)(l  + 6) / scale) - 3;
            int bi = (int)((float)(bt + 6) / scale) + 3;
            int ri = (int)((float)(r  + 6) / scale) + 3;
            W.to = t >> 1; W.lo = l >> 1;
            W.oh = (bt >> 1) - W.to; W.ow = (r >> 1) - W.lo;
            W.fh = (bi - W.ti - 7) / 2 + 1;
            W.fw = (ri - W.li - 7) / 2 + 1;
            W.base = np;
            np += W.fh * W.fw;
        }
    }
    int tpi = (np + 63) / 64;          // tiles per image (np ~4859 -> 76)

    cudaFuncSetAttribute(k_conv1m, cudaFuncAttributeMaxDynamicSharedMemorySize, DYN1);
    cudaFuncSetAttribute(k_conv2m, cudaFuncAttributeMaxDynamicSharedMemorySize, C2_DYN);

    k_init<<<576, 256>>>(w1, w2);
    k_map<<<(NPIX1 + 255) / 256, 256>>>(tab);
    k_conv1m<<<dim3(tpi, BATCH), 256, DYN1>>>(inp);
    k_pool<<<(BATCH*128*PPLANE + 255) / 256, 256>>>(g1, b1);
    k_conv2m<<<BATCH*56, 256, C2_DYN>>>(out);
    k_bn2<<<(BATCH*128*NPIX2 + 255) / 256, 256>>>(out, g2, b2);
}

// round 9
// speedup vs baseline: 1.3665x; 1.0680x over previous
#include <cuda_runtime.h>
#include <cuda_fp16.h>
#include <cstdint>

// ---------------- constants ----------------
#define IMG   224
#define BATCH 32
#define NPIX1 12544
#define NPIX2 3136
#define N1F   401408.0f
#define N2F   100352.0f

// conv1 smem geometry (fp16x2: Ah, Al, B)
#define RSTRIDE 80
#define ATERM   10240
#define BOFF    20480
#define STAGE1  25600
#define DYN1    51200

// conv2 geometry
#define C2_BOFF  16384
#define C2_STAGE 20480
#define C2_DYN   (3*C2_STAGE)

// padded activation plane
#define PSTRIDE 64
#define PPLANE  3712
#define GUARD   128

// packed conv1 output
#define NPMAX 5376

struct Win { int ti, li, to, lo, oh, ow, fh, fw, base; };
struct WinTab { Win w[28]; };

// ---------------- scratch ----------------
__device__ __half g_fpk[BATCH*128*NPMAX];
__device__ __half g_hp[GUARD + BATCH*128*PPLANE + GUARD];
__device__ __half g_hs[GUARD + BATCH*128*PPLANE + GUARD];
__device__ __half g_w1h[128*160], g_w1l[128*160];
__device__ __half g_w2h[128*1152], g_w2l[128*1152];
__device__ unsigned short g_map16[NPIX1];
__device__ int   g_wgt[NPMAX];
__device__ int2  g_pc[NPMAX];
__device__ float g_sum1[128], g_sq1[128], g_sum2[128], g_sq2[128];

// ---------------- helpers ----------------
__device__ __forceinline__ uint32_t smem_u32(const void* p) {
    uint32_t a;
    asm("{ .reg .u64 t; cvta.to.shared.u64 t, %1; cvt.u32.u64 %0, t; }" : "=r"(a) : "l"(p));
    return a;
}
__device__ __forceinline__ void ldsm4(uint32_t addr, uint32_t* r) {
    asm volatile("ldmatrix.sync.aligned.m8n8.x4.shared.b16 {%0,%1,%2,%3}, [%4];"
        : "=r"(r[0]), "=r"(r[1]), "=r"(r[2]), "=r"(r[3]) : "r"(addr));
}
__device__ __forceinline__ void ldsm4t(uint32_t addr, uint32_t* r) {
    asm volatile("ldmatrix.sync.aligned.m8n8.x4.trans.shared.b16 {%0,%1,%2,%3}, [%4];"
        : "=r"(r[0]), "=r"(r[1]), "=r"(r[2]), "=r"(r[3]) : "r"(addr));
}
__device__ __forceinline__ void mma16816(float* c, const uint32_t* a, const uint32_t* b) {
    asm volatile("mma.sync.aligned.m16n8k16.row.col.f32.f16.f16.f32 "
        "{%0,%1,%2,%3}, {%4,%5,%6,%7}, {%8,%9}, {%0,%1,%2,%3};"
        : "+f"(c[0]), "+f"(c[1]), "+f"(c[2]), "+f"(c[3])
        : "r"(a[0]), "r"(a[1]), "r"(a[2]), "r"(a[3]), "r"(b[0]), "r"(b[1]));
}
#define CP16(dst, src) \
    asm volatile("cp.async.cg.shared.global [%0], [%1], 16;" :: "r"(dst), "l"(src) : "memory")
#define CP4(dst, src) \
    asm volatile("cp.async.ca.shared.global [%0], [%1], 4;" :: "r"(dst), "l"(src) : "memory")
#define CPCOMMIT() asm volatile("cp.async.commit_group;" ::: "memory")
#define CPWAIT(n)  asm volatile("cp.async.wait_group %0;" :: "n"(n) : "memory")

#define CPA(WH, WL, KDIM, s, buf, STAGE) do { \
    _Pragma("unroll") for (int i = 0; i < 4; i++) { \
        int id = tid + i*256, term = id >> 9, rem = id & 511, row = rem >> 2, c = rem & 3; \
        const __half* src = (term ? (WL) : (WH)) + row*(KDIM) + (s)*32 + c*8; \
        uint32_t dst = sb + (buf)*(STAGE) + term*ATERM + row*RSTRIDE + c*16; \
        CP16(dst, src); } \
    CPCOMMIT(); } while (0)

// ---------------- init ----------------
__global__ void k_init(const float* __restrict__ w1, const float* __restrict__ w2) {
    int tid = blockIdx.x * blockDim.x + threadIdx.x;
    if (tid < 128) { g_sum1[tid] = 0.f; g_sq1[tid] = 0.f; g_sum2[tid] = 0.f; g_sq2[tid] = 0.f; }
    if (tid < NPMAX) { g_wgt[tid] = 0; g_pc[tid] = make_int2(0, 0); }
    if (tid < 128*160) {
        int oc = tid / 160, k = tid - oc*160;
        float v = (k < 147) ? w1[oc*147 + k] : 0.f;
        __half h = __float2half_rn(v);
        g_w1h[tid] = h;
        g_w1l[tid] = __float2half_rn(v - __half2float(h));
    }
    if (tid < 128*1152) {
        float v = w2[tid];
        __half h = __float2half_rn(v);
        g_w2h[tid] = h;
        g_w2l[tid] = __float2half_rn(v - __half2float(h));
    }
}

// ---------------- map builder ----------------
__global__ void k_map(WinTab tab) {
    int pix = blockIdx.x * 256 + threadIdx.x;
    if (pix >= NPIX1) return;
    int y = pix / 112, x = pix - y*112;
    int bi = y >> 3, bj = x >> 3;
    int sS = min(min(bi, bj), min(13 - bi, 13 - bj));
    int b2 = 8 * (sS + 1), c2v = 112 - b2;
    int w = (y < b2 && x < c2v) ? 0 : (x < b2 ? 1 : (y >= c2v ? 2 : 3));
    Win W = tab.w[sS*4 + w];
    int fy = ((y - W.to) * W.fh) / W.oh;
    int fx = ((x - W.lo) * W.fw) / W.ow;
    int id = W.base + fy * W.fw + fx;
    g_map16[pix] = (unsigned short)id;
    atomicAdd(&g_wgt[id], 1);
    g_pc[id] = make_int2(W.ti + 2*fy - 3, W.li + 2*fx - 3);
}

// ---------------- conv1: fp16x2 over packed pixels ----------------
__global__ void __launch_bounds__(256, 2) k_conv1m(const float* __restrict__ inp) {
    extern __shared__ __align__(128) char dsm[];
    __shared__ int t_c[160];
    __shared__ signed char t_ky[160], t_kx[160];
    __shared__ float s_red[256];
    __shared__ float s_wgt[64];

    int tid = threadIdx.x, lane = tid & 31, wid = tid >> 5;
    int warp_m = wid & 3, warp_n = wid >> 2;

    if (tid < 160) {
        int k = tid;
        if (k < 147) {
            int c = k / 49, r = k - c*49, ky = r / 7, kx = r - ky*7;
            t_c[k] = c * 50176; t_ky[k] = (signed char)ky; t_kx[k] = (signed char)kx;
        } else { t_c[k] = -1; t_ky[k] = 0; t_kx[k] = 0; }
    }
    s_red[tid] = 0.f;

    int img = blockIdx.y;
    int pixbase = blockIdx.x * 64;
    if (tid < 64) s_wgt[tid] = (float)g_wgt[pixbase + tid];
    __syncthreads();

    int pix = pixbase + (tid >> 2);
    int kq = tid & 3;
    int2 pcv = g_pc[pix];
    int iy0 = pcv.x, ix0 = pcv.y;
    const float* ibase = inp + img * 150528;

    uint32_t sb = smem_u32(dsm);
    uint32_t Aln = (lane & 15)*RSTRIDE + (lane >> 4)*16;
    uint32_t Bln = ((lane >> 4)*8 + (lane & 7))*RSTRIDE + ((lane >> 3) & 1)*16;
    uint32_t bsts = (tid >> 2)*RSTRIDE + kq*16;

    uint32_t hw[4];
    #define C1_LDGB(s) do { int kb = (s)*32 + kq*8; \
        float bv[8]; \
        _Pragma("unroll") for (int j = 0; j < 8; j++) { \
            int k = kb + j; \
            int iy = iy0 + t_ky[k], ix = ix0 + t_kx[k]; \
            bool v = (t_c[k] >= 0) && ((unsigned)iy < 224u) && ((unsigned)ix < 224u); \
            bv[j] = v ? __ldg(ibase + t_c[k] + iy*224 + ix) : 0.f; } \
        _Pragma("unroll") for (int j = 0; j < 4; j++) { \
            __half2 h2 = __floats2half2_rn(bv[2*j], bv[2*j+1]); \
            hw[j] = *(uint32_t*)&h2; } } while (0)
    #define C1_STSB(buf) do { \
        *(uint4*)(dsm + (buf)*STAGE1 + BOFF + bsts) = make_uint4(hw[0], hw[1], hw[2], hw[3]); } while (0)

    float acc[2][4][4];
    #pragma unroll
    for (int a = 0; a < 2; a++)
        #pragma unroll
        for (int b = 0; b < 4; b++)
            #pragma unroll
            for (int c = 0; c < 4; c++) acc[a][b][c] = 0.f;

    CPA(g_w1h, g_w1l, 160, 0, 0, STAGE1);
    CPA(g_w1h, g_w1l, 160, 1, 1, STAGE1);
    C1_LDGB(0);
    CPWAIT(1);
    C1_STSB(0);
    __syncthreads();

    for (int s = 0; s < 5; s++) {
        int buf = s & 1;
        if (s < 4) C1_LDGB(s + 1);
        {
            uint32_t Ab = sb + buf*STAGE1 + warp_m*(32*RSTRIDE);
            uint32_t Bb = sb + buf*STAGE1 + BOFF + warp_n*(32*RSTRIDE);
            #pragma unroll
            for (int h = 0; h < 2; h++) {
                uint32_t ab = Ab + h*32 + Aln;
                uint32_t bb = Bb + h*32 + Bln;
                uint32_t am[2][4], bq[4][2], t[4];
                ldsm4(bb, t); bq[0][0]=t[0]; bq[0][1]=t[1]; bq[1][0]=t[2]; bq[1][1]=t[3];
                ldsm4(bb + 16*RSTRIDE, t); bq[2][0]=t[0]; bq[2][1]=t[1]; bq[3][0]=t[2]; bq[3][1]=t[3];
                ldsm4(ab, am[0]); ldsm4(ab + 16*RSTRIDE, am[1]);
                #pragma unroll
                for (int mt = 0; mt < 2; mt++)
                    #pragma unroll
                    for (int nt = 0; nt < 4; nt++) mma16816(acc[mt][nt], am[mt], bq[nt]);
                ldsm4(ab + ATERM, am[0]); ldsm4(ab + ATERM + 16*RSTRIDE, am[1]);
                #pragma unroll
                for (int mt = 0; mt < 2; mt++)
                    #pragma unroll
                    for (int nt = 0; nt < 4; nt++) mma16816(acc[mt][nt], am[mt], bq[nt]);
            }
        }
        if (s < 4) {
            CPWAIT(0);
            C1_STSB(buf ^ 1);
            __syncthreads();
            if (s + 2 < 5) CPA(g_w1h, g_w1l, 160, s + 2, buf, STAGE1);
        }
    }

    int g = lane >> 2, cp = (lane & 3) * 2;
    #pragma unroll
    for (int mt = 0; mt < 2; mt++) {
        #pragma unroll
        for (int hh = 0; hh < 2; hh++) {
            int oc = warp_m*32 + mt*16 + hh*8 + g;
            float sv = 0.f, qv = 0.f;
            __half* obase = g_fpk + (size_t)(img*128 + oc)*NPMAX + pixbase;
            #pragma unroll
            for (int nt = 0; nt < 4; nt++) {
                float c0 = acc[mt][nt][hh*2], c1 = acc[mt][nt][hh*2 + 1];
                int pxl = warp_n*32 + nt*8 + cp;
                *(__half2*)(obase + pxl) = __floats2half2_rn(c0, c1);
                float w0 = s_wgt[pxl], w1 = s_wgt[pxl + 1];
                sv += w0*c0 + w1*c1; qv += w0*c0*c0 + w1*c1*c1;
            }
            atomicAdd(&s_red[oc], sv);
            atomicAdd(&s_red[128 + oc], qv);
        }
    }
    __syncthreads();
    if (tid < 128) {
        atomicAdd(&g_sum1[tid], s_red[tid]);
        atomicAdd(&g_sq1[tid],  s_red[128 + tid]);
    }
}

// ---------------- BN1 + ReLU + maxpool (fp16 max, shfl map, interior-only) ----------------
__global__ void __launch_bounds__(256) k_pool(const float* __restrict__ gamma,
                                              const float* __restrict__ beta) {
    int t = blockIdx.x * 256 + threadIdx.x;
    int xsl = t & 63;
    int rest = t >> 6;                // nc*56 + y
    int y = rest % 56, nc = rest / 56;
    int lane = threadIdx.x & 31;
    bool act = xsl < 56;
    int x = xsl;

    int c = nc & 127;
    float mean = g_sum1[c] * (1.f / N1F);
    float var  = g_sq1[c]  * (1.f / N1F) - mean * mean;
    float a = __ldg(gamma + c) * rsqrtf(var + 1e-5f);
    float b = __ldg(beta + c) - a * mean;

    const __half* fb = g_fpk + (size_t)nc * NPMAX;
    __half hm = __ushort_as_half((unsigned short)0xFC00);   // -inf
    __half hn = __ushort_as_half((unsigned short)0x7C00);   // +inf

    #pragma unroll
    for (int r = 0; r < 3; r++) {
        int yy = 2*y - 1 + r;
        bool rv = (yy >= 0);
        int yyc = rv ? yy : 0;
        const unsigned short* mrow = g_map16 + yyc*112;
        int xc = min(2*x, 110);
        unsigned u = *(const unsigned*)(mrow + xc);
        unsigned up = __shfl_up_sync(0xFFFFFFFFu, u, 1);
        unsigned short idm1;
        if (lane == 0) {
            int xc2 = min(max(2*x - 2, 0), 110);
            idm1 = mrow[xc2 + 1];
        } else idm1 = (unsigned short)(up >> 16);
        if (rv & act) {
            __half v0 = fb[(unsigned short)u];
            __half v1 = fb[(unsigned short)(u >> 16)];
            hm = __hmax(hm, v0); hn = __hmin(hn, v0);
            hm = __hmax(hm, v1); hn = __hmin(hn, v1);
            if (x > 0) {
                __half vm = fb[idm1];
                hm = __hmax(hm, vm); hn = __hmin(hn, vm);
            }
        }
    }
    if (act) {
        float mx = __half2float(hm), mn = __half2float(hn);
        float m = (a >= 0.f) ? fmaf(a, mx, b) : fmaf(a, mn, b);
        __half h = __float2half_rn(fmaxf(m, 0.f));
        size_t pos = (size_t)nc * PPLANE + (size_t)(y + 1) * 64 + x;
        g_hp[GUARD + pos] = h;
        g_hs[GUARD + pos - 1] = h;
    }
}

// ---------------- conv2: pure-async fp16x2 implicit GEMM ----------------
__global__ void __launch_bounds__(256, 3) k_conv2m(float* __restrict__ out) {
    extern __shared__ __align__(128) char dsm[];
    __shared__ int t_bo[1152];
    __shared__ float s_red[256];

    int tid = threadIdx.x, lane = tid & 31, wid = tid >> 5;
    int warp_m = wid & 3, warp_n = wid >> 2;

    for (int k = tid; k < 1152; k += 256) {
        int ic = k / 9, r = k - ic*9;
        int dy = r/3 - 1, dx = r - (r/3)*3 - 1;
        int off = dy*PSTRIDE + dx;
        int sel = off & 1;
        t_bo[k] = ((ic*PPLANE + (off - sel)) << 1) | sel;
    }
    s_red[tid] = 0.f;
    __syncthreads();

    int img = blockIdx.x / 56;
    int yp  = (blockIdx.x - img*56) + 1;
    int pp0 = yp * PSTRIDE;
    size_t ibase = (size_t)img * 128 * PPLANE;
    const __half* HP = g_hp + GUARD;
    const __half* HS = g_hs + GUARD;

    uint32_t sb = smem_u32(dsm);

    #define C2_CPA(s, buf) do { \
        _Pragma("unroll") for (int i = 0; i < 4; i++) { \
            int id = tid + i*256, term = id >> 9, rem = id & 511, row = rem >> 2, c = rem & 3; \
            const __half* src = (term ? g_w2l : g_w2h) + row*1152 + (s)*32 + c*8; \
            uint32_t dst = sb + (buf)*C2_STAGE + term*8192 + row*64 + (((c ^ ((row>>1)&3)) << 4)); \
            CP16(dst, src); } } while (0)
    #define C2_CPB(s, buf) do { \
        _Pragma("unroll") for (int i = 0; i < 4; i++) { \
            int id = tid + i*256, krow = id >> 5, ch = id & 31; \
            int bo = t_bo[(s)*32 + krow]; \
            const __half* base = (bo & 1) ? HS : HP; \
            const __half* src = base + ibase + (bo >> 1) + pp0 + ch*2; \
            uint32_t dst = sb + (buf)*C2_STAGE + C2_BOFF + krow*128 \
                         + (((ch >> 2) ^ (krow & 7)) << 4) + ((ch & 3) << 2); \
            CP4(dst, src); } } while (0)

    uint32_t arow = warp_m*32 + (lane & 15);
    uint32_t aswz = (arow >> 1) & 3;
    uint32_t arb  = arow * 64;
    uint32_t acol = lane >> 4;
    uint32_t brow = ((lane >> 3) & 1)*8 + (lane & 7);
    uint32_t bswz = lane & 7;
    uint32_t bg0  = warp_n*4 + (lane >> 4);

    float acc[2][4][4];
    #pragma unroll
    for (int a = 0; a < 2; a++)
        #pragma unroll
        for (int b = 0; b < 4; b++)
            #pragma unroll
            for (int c = 0; c < 4; c++) acc[a][b][c] = 0.f;

    C2_CPA(0, 0); C2_CPB(0, 0); CPCOMMIT();
    C2_CPA(1, 1); C2_CPB(1, 1); CPCOMMIT();

    for (int s = 0; s < 36; s++) {
        CPWAIT(1);
        __syncthreads();
        int nb = (s + 2) % 3;
        if (s + 2 < 36) { C2_CPA(s + 2, nb); C2_CPB(s + 2, nb); }
        CPCOMMIT();

        uint32_t bufb = sb + (s % 3) * C2_STAGE;
        #pragma unroll
        for (int h = 0; h < 2; h++) {
            uint32_t t[4];
            uint32_t bq[4][2];
            uint32_t bbase = bufb + C2_BOFF + (h*16 + brow)*128;
            ldsm4t(bbase + ((bg0 ^ bswz) << 4), t);
            bq[0][0]=t[0]; bq[0][1]=t[1]; bq[1][0]=t[2]; bq[1][1]=t[3];
            ldsm4t(bbase + (((bg0 + 2) ^ bswz) << 4), t);
            bq[2][0]=t[0]; bq[2][1]=t[1]; bq[3][0]=t[2]; bq[3][1]=t[3];

            uint32_t ac = (((h*2) + acol) ^ aswz) << 4;
            uint32_t am[2][4];
            ldsm4(bufb + arb + ac, am[0]);
            ldsm4(bufb + arb + 1024 + ac, am[1]);
            #pragma unroll
            for (int mt = 0; mt < 2; mt++)
                #pragma unroll
                for (int nt = 0; nt < 4; nt++) mma16816(acc[mt][nt], am[mt], bq[nt]);
            ldsm4(bufb + 8192 + arb + ac, am[0]);
            ldsm4(bufb + 8192 + arb + 1024 + ac, am[1]);
            #pragma unroll
            for (int mt = 0; mt < 2; mt++)
                #pragma unroll
                for (int nt = 0; nt < 4; nt++) mma16816(acc[mt][nt], am[mt], bq[nt]);
        }
    }

    // epilogue: B column c == output x (interior stored at column x)
    int g = lane >> 2, cp = (lane & 3) * 2;
    #pragma unroll
    for (int mt = 0; mt < 2; mt++) {
        #pragma unroll
        for (int hh = 0; hh < 2; hh++) {
            int oc = warp_m*32 + mt*16 + hh*8 + g;
            float sv = 0.f, qv = 0.f;
            float* obase = out + (size_t)(img*128 + oc)*NPIX2 + (yp - 1)*56;
            #pragma unroll
            for (int nt = 0; nt < 4; nt++) {
                float c0 = acc[mt][nt][hh*2], c1 = acc[mt][nt][hh*2 + 1];
                int xp = warp_n*32 + nt*8 + cp;
                if (xp <= 55) { obase[xp] = c0; sv += c0; qv += c0*c0; }
                if (xp + 1 <= 55) { obase[xp + 1] = c1; sv += c1; qv += c1*c1; }
            }
            atomicAdd(&s_red[oc], sv);
            atomicAdd(&s_red[128 + oc], qv);
        }
    }
    __syncthreads();
    if (tid < 128) {
        atomicAdd(&g_sum2[tid], s_red[tid]);
        atomicAdd(&g_sq2[tid],  s_red[128 + tid]);
    }
}

// ---------------- BN2 + ReLU in place (float4) ----------------
__global__ void k_bn2(float4* __restrict__ out,
                      const float* __restrict__ gamma, const float* __restrict__ beta) {
    int i = blockIdx.x * 256 + threadIdx.x;
    if (i >= BATCH * 128 * (NPIX2/4)) return;
    int c = (i / (NPIX2/4)) & 127;
    float mean = g_sum2[c] * (1.f / N2F);
    float var  = g_sq2[c]  * (1.f / N2F) - mean * mean;
    float a = __ldg(gamma + c) * rsqrtf(var + 1e-5f);
    float b = __ldg(beta + c) - a * mean;
    float4 v = out[i];
    v.x = fmaxf(fmaf(a, v.x, b), 0.f);
    v.y = fmaxf(fmaf(a, v.y, b), 0.f);
    v.z = fmaxf(fmaf(a, v.z, b), 0.f);
    v.w = fmaxf(fmaf(a, v.w, b), 0.f);
    out[i] = v;
}

// ---------------- launch ----------------
extern "C" void kernel_launch(void* const* d_in, const int* in_sizes, int n_in,
                              void* d_out, int out_size) {
    const float* inp = (const float*)d_in[0];
    const float* w1  = (const float*)d_in[1];
    const float* g1  = (const float*)d_in[2];
    const float* b1  = (const float*)d_in[3];
    const float* w2  = (const float*)d_in[4];
    const float* g2  = (const float*)d_in[5];
    const float* b2  = (const float*)d_in[6];
    float* out = (float*)d_out;

    WinTab tab;
    int np = 0;
    for (int s = 0; s < 7; s++) {
        int a = 16*s, b = a + 16, c = 224 - b, d = 224 - a;
        float scale = (float)(2.0 - (double)s / 6.0);
        for (int w = 0; w < 4; w++) {
            int t, l, bt, r;
            if      (w == 0) { t = a; l = a; bt = b; r = c; }
            else if (w == 1) { t = b; l = a; bt = d; r = b; }
            else if (w == 2) { t = c; l = b; bt = d; r = d; }
            else             { t = a; l = c; bt = c; r = d; }
            Win& W = tab.w[s*4 + w];
            W.ti = (int)((float)(t  + 6) / scale) - 3;
            W.li = (int)((float)(l  + 6) / scale) - 3;
            int bi = (int)((float)(bt + 6) / scale) + 3;
            int ri = (int)((float)(r  + 6) / scale) + 3;
            W.to = t >> 1; W.lo = l >> 1;
            W.oh = (bt >> 1) - W.to; W.ow = (r >> 1) - W.lo;
            W.fh = (bi - W.ti - 7) / 2 + 1;
            W.fw = (ri - W.li - 7) / 2 + 1;
            W.base = np;
            np += W.fh * W.fw;
        }
    }
    int tpi = (np + 63) / 64;

    cudaFuncSetAttribute(k_conv1m, cudaFuncAttributeMaxDynamicSharedMemorySize, DYN1);
    cudaFuncSetAttribute(k_conv2m, cudaFuncAttributeMaxDynamicSharedMemorySize, C2_DYN);

    k_init<<<576, 256>>>(w1, w2);
    k_map<<<(NPIX1 + 255) / 256, 256>>>(tab);
    k_conv1m<<<dim3(tpi, BATCH), 256, DYN1>>>(inp);
    k_pool<<<BATCH*128*56*64/256, 256>>>(g1, b1);
    k_conv2m<<<BATCH*56, 256, C2_DYN>>>(out);
    k_bn2<<<(BATCH*128*(NPIX2/4) + 255) / 256, 256>>>((float4*)out, g2, b2);
}

// round 10
// speedup vs baseline: 1.5594x; 1.1411x over previous
#include <cuda_runtime.h>
#include <cuda_fp16.h>
#include <cstdint>

// ---------------- constants ----------------
#define IMG   224
#define BATCH 32
#define NPIX1 12544
#define NPIX2 3136
#define N1F   401408.0f
#define N2F   100352.0f

// conv1 smem geometry (fp16x2: Ah, Al, B)
#define RSTRIDE 80
#define ATERM   10240
#define BOFF    20480
#define STAGE1  25600
#define DYN1    51200

// conv2 geometry: two-row CTA (128 px), A 16KB + B 8KB per stage
#define C2_BOFF  16384
#define C2_STAGE 24576
#define C2_DYN   (3*C2_STAGE)   // 73728

// padded activation plane
#define PSTRIDE 64
#define PPLANE  3712
#define GUARD   128

// packed conv1 output
#define NPMAX 5376

struct Win { int ti, li, to, lo, oh, ow, fh, fw, base; };
struct WinTab { Win w[28]; };

// ---------------- scratch ----------------
__device__ __half g_fpk[BATCH*128*NPMAX];
__device__ __half g_hp[GUARD + BATCH*128*PPLANE + GUARD];
__device__ __half g_hs[GUARD + BATCH*128*PPLANE + GUARD];
__device__ __half g_w1h[128*160], g_w1l[128*160];
__device__ __half g_w2h[128*1152], g_w2l[128*1152];
__device__ unsigned short g_map16[NPIX1];
__device__ uint4 g_ptab4[NPIX2*2];           // 16 ushorts per output (9 used)
__device__ int   g_wgt[NPMAX];
__device__ int2  g_pc[NPMAX];
__device__ float g_sum1[128], g_sq1[128], g_sum2[128], g_sq2[128];

// ---------------- helpers ----------------
__device__ __forceinline__ uint32_t smem_u32(const void* p) {
    uint32_t a;
    asm("{ .reg .u64 t; cvta.to.shared.u64 t, %1; cvt.u32.u64 %0, t; }" : "=r"(a) : "l"(p));
    return a;
}
__device__ __forceinline__ void ldsm4(uint32_t addr, uint32_t* r) {
    asm volatile("ldmatrix.sync.aligned.m8n8.x4.shared.b16 {%0,%1,%2,%3}, [%4];"
        : "=r"(r[0]), "=r"(r[1]), "=r"(r[2]), "=r"(r[3]) : "r"(addr));
}
__device__ __forceinline__ void ldsm4t(uint32_t addr, uint32_t* r) {
    asm volatile("ldmatrix.sync.aligned.m8n8.x4.trans.shared.b16 {%0,%1,%2,%3}, [%4];"
        : "=r"(r[0]), "=r"(r[1]), "=r"(r[2]), "=r"(r[3]) : "r"(addr));
}
__device__ __forceinline__ void mma16816(float* c, const uint32_t* a, const uint32_t* b) {
    asm volatile("mma.sync.aligned.m16n8k16.row.col.f32.f16.f16.f32 "
        "{%0,%1,%2,%3}, {%4,%5,%6,%7}, {%8,%9}, {%0,%1,%2,%3};"
        : "+f"(c[0]), "+f"(c[1]), "+f"(c[2]), "+f"(c[3])
        : "r"(a[0]), "r"(a[1]), "r"(a[2]), "r"(a[3]), "r"(b[0]), "r"(b[1]));
}
#define CP16(dst, src) \
    asm volatile("cp.async.cg.shared.global [%0], [%1], 16;" :: "r"(dst), "l"(src) : "memory")
#define CP4(dst, src) \
    asm volatile("cp.async.ca.shared.global [%0], [%1], 4;" :: "r"(dst), "l"(src) : "memory")
#define CPCOMMIT() asm volatile("cp.async.commit_group;" ::: "memory")
#define CPWAIT(n)  asm volatile("cp.async.wait_group %0;" :: "n"(n) : "memory")

#define CPA(WH, WL, KDIM, s, buf, STAGE) do { \
    _Pragma("unroll") for (int i = 0; i < 4; i++) { \
        int id = tid + i*256, term = id >> 9, rem = id & 511, row = rem >> 2, c = rem & 3; \
        const __half* src = (term ? (WL) : (WH)) + row*(KDIM) + (s)*32 + c*8; \
        uint32_t dst = sb + (buf)*(STAGE) + term*ATERM + row*RSTRIDE + c*16; \
        CP16(dst, src); } \
    CPCOMMIT(); } while (0)

// ---------------- init ----------------
__global__ void k_init(const float* __restrict__ w1, const float* __restrict__ w2) {
    int tid = blockIdx.x * blockDim.x + threadIdx.x;
    if (tid < 128) { g_sum1[tid] = 0.f; g_sq1[tid] = 0.f; g_sum2[tid] = 0.f; g_sq2[tid] = 0.f; }
    if (tid < NPMAX) { g_wgt[tid] = 0; g_pc[tid] = make_int2(0, 0); }
    if (tid < 128*160) {
        int oc = tid / 160, k = tid - oc*160;
        float v = (k < 147) ? w1[oc*147 + k] : 0.f;
        __half h = __float2half_rn(v);
        g_w1h[tid] = h;
        g_w1l[tid] = __float2half_rn(v - __half2float(h));
    }
    if (tid < 128*1152) {
        float v = w2[tid];
        __half h = __float2half_rn(v);
        g_w2h[tid] = h;
        g_w2l[tid] = __float2half_rn(v - __half2float(h));
    }
}

// ---------------- map builder ----------------
__global__ void k_map(WinTab tab) {
    int pix = blockIdx.x * 256 + threadIdx.x;
    if (pix >= NPIX1) return;
    int y = pix / 112, x = pix - y*112;
    int bi = y >> 3, bj = x >> 3;
    int sS = min(min(bi, bj), min(13 - bi, 13 - bj));
    int b2 = 8 * (sS + 1), c2v = 112 - b2;
    int w = (y < b2 && x < c2v) ? 0 : (x < b2 ? 1 : (y >= c2v ? 2 : 3));
    Win W = tab.w[sS*4 + w];
    int fy = ((y - W.to) * W.fh) / W.oh;
    int fx = ((x - W.lo) * W.fw) / W.ow;
    int id = W.base + fy * W.fw + fx;
    g_map16[pix] = (unsigned short)id;
    atomicAdd(&g_wgt[id], 1);
    g_pc[id] = make_int2(W.ti + 2*fy - 3, W.li + 2*fx - 3);
}

// ---------------- pool tap table: 9 packed ids per output (clamped taps) ----------------
__global__ void k_ptab() {
    int pix = blockIdx.x * 256 + threadIdx.x;
    if (pix >= NPIX2) return;
    int y = pix / 56, x = pix - y*56;
    unsigned short ids[16];
    #pragma unroll
    for (int r = 0; r < 3; r++)
        #pragma unroll
        for (int s = 0; s < 3; s++) {
            int yy = max(2*y - 1 + r, 0);
            int xx = max(2*x - 1 + s, 0);
            ids[r*3 + s] = g_map16[yy*112 + xx];
        }
    #pragma unroll
    for (int j = 9; j < 16; j++) ids[j] = ids[0];
    uint32_t u[8];
    #pragma unroll
    for (int j = 0; j < 8; j++)
        u[j] = (uint32_t)ids[2*j] | ((uint32_t)ids[2*j+1] << 16);
    g_ptab4[pix*2]     = make_uint4(u[0], u[1], u[2], u[3]);
    g_ptab4[pix*2 + 1] = make_uint4(u[4], u[5], u[6], u[7]);
}

// ---------------- conv1: fp16x2 over packed pixels ----------------
__global__ void __launch_bounds__(256, 2) k_conv1m(const float* __restrict__ inp) {
    extern __shared__ __align__(128) char dsm[];
    __shared__ int t_c[160];
    __shared__ signed char t_ky[160], t_kx[160];
    __shared__ float s_red[256];
    __shared__ float s_wgt[64];

    int tid = threadIdx.x, lane = tid & 31, wid = tid >> 5;
    int warp_m = wid & 3, warp_n = wid >> 2;

    if (tid < 160) {
        int k = tid;
        if (k < 147) {
            int c = k / 49, r = k - c*49, ky = r / 7, kx = r - ky*7;
            t_c[k] = c * 50176; t_ky[k] = (signed char)ky; t_kx[k] = (signed char)kx;
        } else { t_c[k] = -1; t_ky[k] = 0; t_kx[k] = 0; }
    }
    s_red[tid] = 0.f;

    int img = blockIdx.y;
    int pixbase = blockIdx.x * 64;
    if (tid < 64) s_wgt[tid] = (float)g_wgt[pixbase + tid];
    __syncthreads();

    int pix = pixbase + (tid >> 2);
    int kq = tid & 3;
    int2 pcv = g_pc[pix];
    int iy0 = pcv.x, ix0 = pcv.y;
    const float* ibase = inp + img * 150528;

    uint32_t sb = smem_u32(dsm);
    uint32_t Aln = (lane & 15)*RSTRIDE + (lane >> 4)*16;
    uint32_t Bln = ((lane >> 4)*8 + (lane & 7))*RSTRIDE + ((lane >> 3) & 1)*16;
    uint32_t bsts = (tid >> 2)*RSTRIDE + kq*16;

    uint32_t hw[4];
    #define C1_LDGB(s) do { int kb = (s)*32 + kq*8; \
        float bv[8]; \
        _Pragma("unroll") for (int j = 0; j < 8; j++) { \
            int k = kb + j; \
            int iy = iy0 + t_ky[k], ix = ix0 + t_kx[k]; \
            bool v = (t_c[k] >= 0) && ((unsigned)iy < 224u) && ((unsigned)ix < 224u); \
            bv[j] = v ? __ldg(ibase + t_c[k] + iy*224 + ix) : 0.f; } \
        _Pragma("unroll") for (int j = 0; j < 4; j++) { \
            __half2 h2 = __floats2half2_rn(bv[2*j], bv[2*j+1]); \
            hw[j] = *(uint32_t*)&h2; } } while (0)
    #define C1_STSB(buf) do { \
        *(uint4*)(dsm + (buf)*STAGE1 + BOFF + bsts) = make_uint4(hw[0], hw[1], hw[2], hw[3]); } while (0)

    float acc[2][4][4];
    #pragma unroll
    for (int a = 0; a < 2; a++)
        #pragma unroll
        for (int b = 0; b < 4; b++)
            #pragma unroll
            for (int c = 0; c < 4; c++) acc[a][b][c] = 0.f;

    CPA(g_w1h, g_w1l, 160, 0, 0, STAGE1);
    CPA(g_w1h, g_w1l, 160, 1, 1, STAGE1);
    C1_LDGB(0);
    CPWAIT(1);
    C1_STSB(0);
    __syncthreads();

    for (int s = 0; s < 5; s++) {
        int buf = s & 1;
        if (s < 4) C1_LDGB(s + 1);
        {
            uint32_t Ab = sb + buf*STAGE1 + warp_m*(32*RSTRIDE);
            uint32_t Bb = sb + buf*STAGE1 + BOFF + warp_n*(32*RSTRIDE);
            #pragma unroll
            for (int h = 0; h < 2; h++) {
                uint32_t ab = Ab + h*32 + Aln;
                uint32_t bb = Bb + h*32 + Bln;
                uint32_t am[2][4], bq[4][2], t[4];
                ldsm4(bb, t); bq[0][0]=t[0]; bq[0][1]=t[1]; bq[1][0]=t[2]; bq[1][1]=t[3];
                ldsm4(bb + 16*RSTRIDE, t); bq[2][0]=t[0]; bq[2][1]=t[1]; bq[3][0]=t[2]; bq[3][1]=t[3];
                ldsm4(ab, am[0]); ldsm4(ab + 16*RSTRIDE, am[1]);
                #pragma unroll
                for (int mt = 0; mt < 2; mt++)
                    #pragma unroll
                    for (int nt = 0; nt < 4; nt++) mma16816(acc[mt][nt], am[mt], bq[nt]);
                ldsm4(ab + ATERM, am[0]); ldsm4(ab + ATERM + 16*RSTRIDE, am[1]);
                #pragma unroll
                for (int mt = 0; mt < 2; mt++)
                    #pragma unroll
                    for (int nt = 0; nt < 4; nt++) mma16816(acc[mt][nt], am[mt], bq[nt]);
            }
        }
        if (s < 4) {
            CPWAIT(0);
            C1_STSB(buf ^ 1);
            __syncthreads();
            if (s + 2 < 5) CPA(g_w1h, g_w1l, 160, s + 2, buf, STAGE1);
        }
    }

    int g = lane >> 2, cp = (lane & 3) * 2;
    #pragma unroll
    for (int mt = 0; mt < 2; mt++) {
        #pragma unroll
        for (int hh = 0; hh < 2; hh++) {
            int oc = warp_m*32 + mt*16 + hh*8 + g;
            float sv = 0.f, qv = 0.f;
            __half* obase = g_fpk + (size_t)(img*128 + oc)*NPMAX + pixbase;
            #pragma unroll
            for (int nt = 0; nt < 4; nt++) {
                float c0 = acc[mt][nt][hh*2], c1 = acc[mt][nt][hh*2 + 1];
                int pxl = warp_n*32 + nt*8 + cp;
                *(__half2*)(obase + pxl) = __floats2half2_rn(c0, c1);
                float w0 = s_wgt[pxl], w1 = s_wgt[pxl + 1];
                sv += w0*c0 + w1*c1; qv += w0*c0*c0 + w1*c1*c1;
            }
            atomicAdd(&s_red[oc], sv);
            atomicAdd(&s_red[128 + oc], qv);
        }
    }
    __syncthreads();
    if (tid < 128) {
        atomicAdd(&g_sum1[tid], s_red[tid]);
        atomicAdd(&g_sq1[tid],  s_red[128 + tid]);
    }
}

// ---------------- BN1 + ReLU + maxpool: table-driven, 2 channels/thread ----------------
__global__ void __launch_bounds__(256) k_pool(const float* __restrict__ gamma,
                                              const float* __restrict__ beta) {
    int idx = blockIdx.x * 256 + threadIdx.x;     // 32*64*3136 total (exact)
    int pix = idx % NPIX2;
    int pr  = idx / NPIX2;
    int img = pr >> 6, cpr = pr & 63;
    int c0 = cpr*2;
    int nc0 = img*128 + c0;

    float mean0 = g_sum1[c0] * (1.f / N1F);
    float var0  = g_sq1[c0]  * (1.f / N1F) - mean0*mean0;
    float a0 = __ldg(gamma + c0) * rsqrtf(var0 + 1e-5f);
    float b0 = __ldg(beta + c0) - a0 * mean0;
    float mean1 = g_sum1[c0+1] * (1.f / N1F);
    float var1  = g_sq1[c0+1]  * (1.f / N1F) - mean1*mean1;
    float a1 = __ldg(gamma + c0+1) * rsqrtf(var1 + 1e-5f);
    float b1 = __ldg(beta + c0+1) - a1 * mean1;

    const __half* f0 = g_fpk + (size_t)nc0 * NPMAX;
    const __half* f1 = f0 + NPMAX;

    uint4 q0 = g_ptab4[pix*2];
    uint4 q1 = g_ptab4[pix*2 + 1];
    unsigned short id[9] = {
        (unsigned short)(q0.x), (unsigned short)(q0.x >> 16),
        (unsigned short)(q0.y), (unsigned short)(q0.y >> 16),
        (unsigned short)(q0.z), (unsigned short)(q0.z >> 16),
        (unsigned short)(q0.w), (unsigned short)(q0.w >> 16),
        (unsigned short)(q1.x)
    };

    __half2 mx = __halves2half2(__ushort_as_half(0xFC00), __ushort_as_half(0xFC00));
    __half2 mn = __halves2half2(__ushort_as_half(0x7C00), __ushort_as_half(0x7C00));
    #pragma unroll
    for (int j = 0; j < 9; j++) {
        __half2 v = __halves2half2(f0[id[j]], f1[id[j]]);
        mx = __hmax2(mx, v);
        mn = __hmin2(mn, v);
    }
    float mx0 = __half2float(__low2half(mx)),  mx1 = __half2float(__high2half(mx));
    float mn0 = __half2float(__low2half(mn)),  mn1 = __half2float(__high2half(mn));
    float m0 = fmaf(a0, (a0 >= 0.f) ? mx0 : mn0, b0);
    float m1 = fmaf(a1, (a1 >= 0.f) ? mx1 : mn1, b1);
    __half h0 = __float2half_rn(fmaxf(m0, 0.f));
    __half h1 = __float2half_rn(fmaxf(m1, 0.f));

    int y = pix / 56, x = pix - y*56;
    size_t pos = (size_t)nc0 * PPLANE + (size_t)(y + 1) * 64 + x;
    g_hp[GUARD + pos] = h0;
    g_hs[GUARD + pos - 1] = h0;
    g_hp[GUARD + pos + PPLANE] = h1;
    g_hs[GUARD + pos + PPLANE - 1] = h1;
}

// ---------------- conv2: two-row CTA (128 oc x 128 px), fp16x2, pure-async ----------------
__global__ void __launch_bounds__(256, 2) k_conv2m(float* __restrict__ out) {
    extern __shared__ __align__(128) char dsm[];
    __shared__ int t_bo[1152];
    __shared__ float s_red[256];

    int tid = threadIdx.x, lane = tid & 31, wid = tid >> 5;
    int warp_m = wid & 3, warp_n = wid >> 2;   // 4 M-warps x 2 N-warps

    for (int k = tid; k < 1152; k += 256) {
        int ic = k / 9, r = k - ic*9;
        int dy = r/3 - 1, dx = r - (r/3)*3 - 1;
        int off = dy*PSTRIDE + dx;
        int sel = off & 1;
        t_bo[k] = ((ic*PPLANE + (off - sel)) << 1) | sel;
    }
    s_red[tid] = 0.f;
    __syncthreads();

    int img = blockIdx.x / 28;
    int t2  = blockIdx.x - img*28;
    int yp0 = 2*t2 + 1;                      // padded rows yp0, yp0+1
    size_t ibase = (size_t)img * 128 * PPLANE;
    const __half* HP = g_hp + GUARD;
    const __half* HS = g_hs + GUARD;

    uint32_t sb = smem_u32(dsm);

    #define C2_CPA(s, buf) do { \
        _Pragma("unroll") for (int i = 0; i < 4; i++) { \
            int id = tid + i*256, term = id >> 9, rem = id & 511, row = rem >> 2, c = rem & 3; \
            const __half* src = (term ? g_w2l : g_w2h) + row*1152 + (s)*32 + c*8; \
            uint32_t dst = sb + (buf)*C2_STAGE + term*8192 + row*64 + (((c ^ ((row>>1)&3)) << 4)); \
            CP16(dst, src); } } while (0)
    // B: 32 krows x 128 px (2 rows of 64), 256B rows, 16-granule XOR swizzle
    #define C2_CPB(s, buf) do { \
        _Pragma("unroll") for (int i = 0; i < 8; i++) { \
            int id = tid + i*256, krow = id >> 6, ch = id & 63; \
            int bo = t_bo[(s)*32 + krow]; \
            const __half* base = (bo & 1) ? HS : HP; \
            int r = ch >> 5, xh = ch & 31; \
            const __half* src = base + ibase + (bo >> 1) + (yp0 + r)*64 + xh*2; \
            int gq = r*8 + (xh >> 2); \
            uint32_t dst = sb + (buf)*C2_STAGE + C2_BOFF + krow*256 \
                         + (((gq ^ (krow & 7)) << 4)) + ((xh & 3) << 2); \
            CP4(dst, src); } } while (0)

    uint32_t arow = warp_m*32 + (lane & 15);
    uint32_t aswz = (arow >> 1) & 3;
    uint32_t arb  = arow * 64;
    uint32_t acol = lane >> 4;
    uint32_t brow = ((lane >> 3) & 1)*8 + (lane & 7);
    uint32_t bswz = lane & 7;
    uint32_t bg0  = warp_n*8 + (lane >> 4);

    float acc[2][8][4];
    #pragma unroll
    for (int a = 0; a < 2; a++)
        #pragma unroll
        for (int b = 0; b < 8; b++)
            #pragma unroll
            for (int c = 0; c < 4; c++) acc[a][b][c] = 0.f;

    C2_CPA(0, 0); C2_CPB(0, 0); CPCOMMIT();
    C2_CPA(1, 1); C2_CPB(1, 1); CPCOMMIT();

    for (int s = 0; s < 36; s++) {
        CPWAIT(1);
        __syncthreads();
        int nb = (s + 2) % 3;
        if (s + 2 < 36) { C2_CPA(s + 2, nb); C2_CPB(s + 2, nb); }
        CPCOMMIT();

        uint32_t bufb = sb + (s % 3) * C2_STAGE;
        #pragma unroll
        for (int h = 0; h < 2; h++) {
            uint32_t t[4];
            uint32_t bq[8][2];
            uint32_t bbase = bufb + C2_BOFF + (h*16 + brow)*256;
            #pragma unroll
            for (int j = 0; j < 4; j++) {
                ldsm4t(bbase + (((bg0 + 2*j) ^ bswz) << 4), t);
                bq[2*j][0]   = t[0]; bq[2*j][1]   = t[1];
                bq[2*j+1][0] = t[2]; bq[2*j+1][1] = t[3];
            }
            uint32_t ac = (((h*2) + acol) ^ aswz) << 4;
            uint32_t am[2][4];
            ldsm4(bufb + arb + ac, am[0]);
            ldsm4(bufb + arb + 1024 + ac, am[1]);
            #pragma unroll
            for (int mt = 0; mt < 2; mt++)
                #pragma unroll
                for (int nt = 0; nt < 8; nt++) mma16816(acc[mt][nt], am[mt], bq[nt]);
            ldsm4(bufb + 8192 + arb + ac, am[0]);
            ldsm4(bufb + 8192 + arb + 1024 + ac, am[1]);
            #pragma unroll
            for (int mt = 0; mt < 2; mt++)
                #pragma unroll
                for (int nt = 0; nt < 8; nt++) mma16816(acc[mt][nt], am[mt], bq[nt]);
        }
    }

    // epilogue: warp_n selects output row; x = nt*8 + cp
    int g = lane >> 2, cp = (lane & 3) * 2;
    int yo = 2*t2 + warp_n;
    #pragma unroll
    for (int mt = 0; mt < 2; mt++) {
        #pragma unroll
        for (int hh = 0; hh < 2; hh++) {
            int oc = warp_m*32 + mt*16 + hh*8 + g;
            float sv = 0.f, qv = 0.f;
            float* obase = out + (size_t)(img*128 + oc)*NPIX2 + yo*56;
            #pragma unroll
            for (int nt = 0; nt < 8; nt++) {
                float c0 = acc[mt][nt][hh*2], c1 = acc[mt][nt][hh*2 + 1];
                int x = nt*8 + cp;
                if (x <= 55) { obase[x] = c0; sv += c0; qv += c0*c0; }
                if (x + 1 <= 55) { obase[x + 1] = c1; sv += c1; qv += c1*c1; }
            }
            atomicAdd(&s_red[oc], sv);
            atomicAdd(&s_red[128 + oc], qv);
        }
    }
    __syncthreads();
    if (tid < 128) {
        atomicAdd(&g_sum2[tid], s_red[tid]);
        atomicAdd(&g_sq2[tid],  s_red[128 + tid]);
    }
}

// ---------------- BN2 + ReLU in place (float4) ----------------
__global__ void k_bn2(float4* __restrict__ out,
                      const float* __restrict__ gamma, const float* __restrict__ beta) {
    int i = blockIdx.x * 256 + threadIdx.x;
    if (i >= BATCH * 128 * (NPIX2/4)) return;
    int c = (i / (NPIX2/4)) & 127;
    float mean = g_sum2[c] * (1.f / N2F);
    float var  = g_sq2[c]  * (1.f / N2F) - mean * mean;
    float a = __ldg(gamma + c) * rsqrtf(var + 1e-5f);
    float b = __ldg(beta + c) - a * mean;
    float4 v = out[i];
    v.x = fmaxf(fmaf(a, v.x, b), 0.f);
    v.y = fmaxf(fmaf(a, v.y, b), 0.f);
    v.z = fmaxf(fmaf(a, v.z, b), 0.f);
    v.w = fmaxf(fmaf(a, v.w, b), 0.f);
    out[i] = v;
}

// ---------------- launch ----------------
extern "C" void kernel_launch(void* const* d_in, const int* in_sizes, int n_in,
                              void* d_out, int out_size) {
    const float* inp = (const float*)d_in[0];
    const float* w1  = (const float*)d_in[1];
    const float* g1  = (const float*)d_in[2];
    const float* b1  = (const float*)d_in[3];
    const float* w2  = (const float*)d_in[4];
    const float* g2  = (const float*)d_in[5];
    const float* b2  = (const float*)d_in[6];
    float* out = (float*)d_out;

    WinTab tab;
    int np = 0;
    for (int s = 0; s < 7; s++) {
        int a = 16*s, b = a + 16, c = 224 - b, d = 224 - a;
        float scale = (float)(2.0 - (double)s / 6.0);
        for (int w = 0; w < 4; w++) {
            int t, l, bt, r;
            if      (w == 0) { t = a; l = a; bt = b; r = c; }
            else if (w == 1) { t = b; l = a; bt = d; r = b; }
            else if (w == 2) { t = c; l = b; bt = d; r = d; }
            else             { t = a; l = c; bt = c; r = d; }
            Win& W = tab.w[s*4 + w];
            W.ti = (int)((float)(t  + 6) / scale) - 3;
            W.li = (int)((float)(l  + 6) / scale) - 3;
            int bi = (int)((float)(bt + 6) / scale) + 3;
            int ri = (int)((float)(r  + 6) / scale) + 3;
            W.to = t >> 1; W.lo = l >> 1;
            W.oh = (bt >> 1) - W.to; W.ow = (r >> 1) - W.lo;
            W.fh = (bi - W.ti - 7) / 2 + 1;
            W.fw = (ri - W.li - 7) / 2 + 1;
            W.base = np;
            np += W.fh * W.fw;
        }
    }
    int tpi = (np + 63) / 64;

    cudaFuncSetAttribute(k_conv1m, cudaFuncAttributeMaxDynamicSharedMemorySize, DYN1);
    cudaFuncSetAttribute(k_conv2m, cudaFuncAttributeMaxDynamicSharedMemorySize, C2_DYN);

    k_init<<<576, 256>>>(w1, w2);
    k_map<<<(NPIX1 + 255) / 256, 256>>>(tab);
    k_ptab<<<(NPIX2 + 255) / 256, 256>>>();
    k_conv1m<<<dim3(tpi, BATCH), 256, DYN1>>>(inp);
    k_pool<<<BATCH*64*NPIX2/256, 256>>>(g1, b1);
    k_conv2m<<<BATCH*28, 256, C2_DYN>>>(out);
    k_bn2<<<(BATCH*128*(NPIX2/4) + 255) / 256, 256>>>((float4*)out, g2, b2);
}

// round 11
// speedup vs baseline: 1.8587x; 1.1919x over previous
#include <cuda_runtime.h>
#include <cuda_fp16.h>
#include <cstdint>

// ---------------- constants ----------------
#define IMG   224
#define BATCH 32
#define NPIX1 12544
#define NPIX2 3136
#define N1F   401408.0f
#define N2F   100352.0f

// conv1 smem geometry (fp16x2: Ah, Al, B)
#define RSTRIDE 80
#define ATERM   10240
#define BOFF    20480
#define STAGE1  25600
#define DYN1    51200

// conv2 geometry: two-row CTA, single-term A (8KB) + B (8KB)
#define C2_BOFF  8192
#define C2_STAGE 16384
#define C2_DYN   (3*C2_STAGE)   // 49152

// padded activation plane
#define PSTRIDE 64
#define PPLANE  3712
#define GUARD   128

// packed conv1 output
#define NPMAX 5376

struct Win { int ti, li, to, lo, oh, ow, fh, fw, base; };
struct WinTab { Win w[28]; };

// ---------------- scratch ----------------
__device__ __half g_in16[BATCH*3*IMG*IMG];   // fp16 input (9.6 MB)
__device__ __half g_fpk[BATCH*128*NPMAX];
__device__ __half g_hp[GUARD + BATCH*128*PPLANE + GUARD];
__device__ __half g_hs[GUARD + BATCH*128*PPLANE + GUARD];
__device__ __half g_w1h[128*160], g_w1l[128*160];
__device__ __half g_w2h[128*1152], g_w2l[128*1152];
__device__ unsigned short g_map16[NPIX1];
__device__ uint4 g_ptab4[NPIX2*2];
__device__ int   g_wgt[NPMAX];
__device__ int2  g_pc[NPMAX];
__device__ float g_sum1[128], g_sq1[128], g_sum2[128], g_sq2[128];

// ---------------- helpers ----------------
__device__ __forceinline__ uint32_t smem_u32(const void* p) {
    uint32_t a;
    asm("{ .reg .u64 t; cvta.to.shared.u64 t, %1; cvt.u32.u64 %0, t; }" : "=r"(a) : "l"(p));
    return a;
}
__device__ __forceinline__ void ldsm4(uint32_t addr, uint32_t* r) {
    asm volatile("ldmatrix.sync.aligned.m8n8.x4.shared.b16 {%0,%1,%2,%3}, [%4];"
        : "=r"(r[0]), "=r"(r[1]), "=r"(r[2]), "=r"(r[3]) : "r"(addr));
}
__device__ __forceinline__ void ldsm4t(uint32_t addr, uint32_t* r) {
    asm volatile("ldmatrix.sync.aligned.m8n8.x4.trans.shared.b16 {%0,%1,%2,%3}, [%4];"
        : "=r"(r[0]), "=r"(r[1]), "=r"(r[2]), "=r"(r[3]) : "r"(addr));
}
__device__ __forceinline__ void mma16816(float* c, const uint32_t* a, const uint32_t* b) {
    asm volatile("mma.sync.aligned.m16n8k16.row.col.f32.f16.f16.f32 "
        "{%0,%1,%2,%3}, {%4,%5,%6,%7}, {%8,%9}, {%0,%1,%2,%3};"
        : "+f"(c[0]), "+f"(c[1]), "+f"(c[2]), "+f"(c[3])
        : "r"(a[0]), "r"(a[1]), "r"(a[2]), "r"(a[3]), "r"(b[0]), "r"(b[1]));
}
#define CP16(dst, src) \
    asm volatile("cp.async.cg.shared.global [%0], [%1], 16;" :: "r"(dst), "l"(src) : "memory")
#define CP4(dst, src) \
    asm volatile("cp.async.ca.shared.global [%0], [%1], 4;" :: "r"(dst), "l"(src) : "memory")
#define CPCOMMIT() asm volatile("cp.async.commit_group;" ::: "memory")
#define CPWAIT(n)  asm volatile("cp.async.wait_group %0;" :: "n"(n) : "memory")

#define CPA(WH, WL, KDIM, s, buf, STAGE) do { \
    _Pragma("unroll") for (int i = 0; i < 4; i++) { \
        int id = tid + i*256, term = id >> 9, rem = id & 511, row = rem >> 2, c = rem & 3; \
        const __half* src = (term ? (WL) : (WH)) + row*(KDIM) + (s)*32 + c*8; \
        uint32_t dst = sb + (buf)*(STAGE) + term*ATERM + row*RSTRIDE + c*16; \
        CP16(dst, src); } \
    CPCOMMIT(); } while (0)

// ---------------- init ----------------
__global__ void k_init(const float* __restrict__ w1, const float* __restrict__ w2) {
    int tid = blockIdx.x * blockDim.x + threadIdx.x;
    if (tid < 128) { g_sum1[tid] = 0.f; g_sq1[tid] = 0.f; g_sum2[tid] = 0.f; g_sq2[tid] = 0.f; }
    if (tid < NPMAX) { g_wgt[tid] = 0; g_pc[tid] = make_int2(0, 0); }
    if (tid < 128*160) {
        int oc = tid / 160, k = tid - oc*160;
        float v = (k < 147) ? w1[oc*147 + k] : 0.f;
        __half h = __float2half_rn(v);
        g_w1h[tid] = h;
        g_w1l[tid] = __float2half_rn(v - __half2float(h));
    }
    if (tid < 128*1152) {
        float v = w2[tid];
        g_w2h[tid] = __float2half_rn(v);
    }
}

// ---------------- input -> fp16 (bit-identical to pack-time rounding) ----------------
__global__ void k_prep(const float4* __restrict__ inp) {
    int i = blockIdx.x * 256 + threadIdx.x;
    if (i >= BATCH*3*IMG*IMG/4) return;
    float4 v = inp[i];
    __half2 a = __floats2half2_rn(v.x, v.y);
    __half2 b = __floats2half2_rn(v.z, v.w);
    *(uint2*)(g_in16 + i*4) = make_uint2(*(uint32_t*)&a, *(uint32_t*)&b);
}

// ---------------- map builder ----------------
__global__ void k_map(WinTab tab) {
    int pix = blockIdx.x * 256 + threadIdx.x;
    if (pix >= NPIX1) return;
    int y = pix / 112, x = pix - y*112;
    int bi = y >> 3, bj = x >> 3;
    int sS = min(min(bi, bj), min(13 - bi, 13 - bj));
    int b2 = 8 * (sS + 1), c2v = 112 - b2;
    int w = (y < b2 && x < c2v) ? 0 : (x < b2 ? 1 : (y >= c2v ? 2 : 3));
    Win W = tab.w[sS*4 + w];
    int fy = ((y - W.to) * W.fh) / W.oh;
    int fx = ((x - W.lo) * W.fw) / W.ow;
    int id = W.base + fy * W.fw + fx;
    g_map16[pix] = (unsigned short)id;
    atomicAdd(&g_wgt[id], 1);
    g_pc[id] = make_int2(W.ti + 2*fy - 3, W.li + 2*fx - 3);
}

// ---------------- pool tap table ----------------
__global__ void k_ptab() {
    int pix = blockIdx.x * 256 + threadIdx.x;
    if (pix >= NPIX2) return;
    int y = pix / 56, x = pix - y*56;
    unsigned short ids[16];
    #pragma unroll
    for (int r = 0; r < 3; r++)
        #pragma unroll
        for (int s = 0; s < 3; s++) {
            int yy = max(2*y - 1 + r, 0);
            int xx = max(2*x - 1 + s, 0);
            ids[r*3 + s] = g_map16[yy*112 + xx];
        }
    #pragma unroll
    for (int j = 9; j < 16; j++) ids[j] = ids[0];
    uint32_t u[8];
    #pragma unroll
    for (int j = 0; j < 8; j++)
        u[j] = (uint32_t)ids[2*j] | ((uint32_t)ids[2*j+1] << 16);
    g_ptab4[pix*2]     = make_uint4(u[0], u[1], u[2], u[3]);
    g_ptab4[pix*2 + 1] = make_uint4(u[4], u[5], u[6], u[7]);
}

// ---------------- conv1: fp16x2 over packed pixels, fp16 gather ----------------
__global__ void __launch_bounds__(256, 3) k_conv1m() {
    extern __shared__ __align__(128) char dsm[];
    __shared__ int t_c[160];
    __shared__ signed char t_ky[160], t_kx[160];
    __shared__ float s_red[256];
    __shared__ float s_wgt[64];

    int tid = threadIdx.x, lane = tid & 31, wid = tid >> 5;
    int warp_m = wid & 3, warp_n = wid >> 2;

    if (tid < 160) {
        int k = tid;
        if (k < 147) {
            int c = k / 49, r = k - c*49, ky = r / 7, kx = r - ky*7;
            t_c[k] = c * 50176; t_ky[k] = (signed char)ky; t_kx[k] = (signed char)kx;
        } else { t_c[k] = -1; t_ky[k] = 0; t_kx[k] = 0; }
    }
    s_red[tid] = 0.f;

    int img = blockIdx.y;
    int pixbase = blockIdx.x * 64;
    if (tid < 64) s_wgt[tid] = (float)g_wgt[pixbase + tid];
    __syncthreads();

    int pix = pixbase + (tid >> 2);
    int kq = tid & 3;
    int2 pcv = g_pc[pix];
    int iy0 = pcv.x, ix0 = pcv.y;
    const __half* ibase = g_in16 + img * 150528;

    uint32_t sb = smem_u32(dsm);
    uint32_t Aln = (lane & 15)*RSTRIDE + (lane >> 4)*16;
    uint32_t Bln = ((lane >> 4)*8 + (lane & 7))*RSTRIDE + ((lane >> 3) & 1)*16;
    uint32_t bsts = (tid >> 2)*RSTRIDE + kq*16;

    uint32_t hw[4];
    #define C1_LDGB(s) do { int kb = (s)*32 + kq*8; \
        unsigned short bu[8]; \
        _Pragma("unroll") for (int j = 0; j < 8; j++) { \
            int k = kb + j; \
            int iy = iy0 + t_ky[k], ix = ix0 + t_kx[k]; \
            bool v = (t_c[k] >= 0) && ((unsigned)iy < 224u) && ((unsigned)ix < 224u); \
            bu[j] = v ? __half_as_ushort(__ldg(ibase + t_c[k] + iy*224 + ix)) : (unsigned short)0; } \
        _Pragma("unroll") for (int j = 0; j < 4; j++) \
            hw[j] = (uint32_t)bu[2*j] | ((uint32_t)bu[2*j+1] << 16); } while (0)
    #define C1_STSB(buf) do { \
        *(uint4*)(dsm + (buf)*STAGE1 + BOFF + bsts) = make_uint4(hw[0], hw[1], hw[2], hw[3]); } while (0)

    float acc[2][4][4];
    #pragma unroll
    for (int a = 0; a < 2; a++)
        #pragma unroll
        for (int b = 0; b < 4; b++)
            #pragma unroll
            for (int c = 0; c < 4; c++) acc[a][b][c] = 0.f;

    CPA(g_w1h, g_w1l, 160, 0, 0, STAGE1);
    CPA(g_w1h, g_w1l, 160, 1, 1, STAGE1);
    C1_LDGB(0);
    CPWAIT(1);
    C1_STSB(0);
    __syncthreads();

    for (int s = 0; s < 5; s++) {
        int buf = s & 1;
        if (s < 4) C1_LDGB(s + 1);
        {
            uint32_t Ab = sb + buf*STAGE1 + warp_m*(32*RSTRIDE);
            uint32_t Bb = sb + buf*STAGE1 + BOFF + warp_n*(32*RSTRIDE);
            #pragma unroll
            for (int h = 0; h < 2; h++) {
                uint32_t ab = Ab + h*32 + Aln;
                uint32_t bb = Bb + h*32 + Bln;
                uint32_t am[2][4], bq[4][2], t[4];
                ldsm4(bb, t); bq[0][0]=t[0]; bq[0][1]=t[1]; bq[1][0]=t[2]; bq[1][1]=t[3];
                ldsm4(bb + 16*RSTRIDE, t); bq[2][0]=t[0]; bq[2][1]=t[1]; bq[3][0]=t[2]; bq[3][1]=t[3];
                ldsm4(ab, am[0]); ldsm4(ab + 16*RSTRIDE, am[1]);
                #pragma unroll
                for (int mt = 0; mt < 2; mt++)
                    #pragma unroll
                    for (int nt = 0; nt < 4; nt++) mma16816(acc[mt][nt], am[mt], bq[nt]);
                ldsm4(ab + ATERM, am[0]); ldsm4(ab + ATERM + 16*RSTRIDE, am[1]);
                #pragma unroll
                for (int mt = 0; mt < 2; mt++)
                    #pragma unroll
                    for (int nt = 0; nt < 4; nt++) mma16816(acc[mt][nt], am[mt], bq[nt]);
            }
        }
        if (s < 4) {
            CPWAIT(0);
            C1_STSB(buf ^ 1);
            __syncthreads();
            if (s + 2 < 5) CPA(g_w1h, g_w1l, 160, s + 2, buf, STAGE1);
        }
    }

    int g = lane >> 2, cp = (lane & 3) * 2;
    #pragma unroll
    for (int mt = 0; mt < 2; mt++) {
        #pragma unroll
        for (int hh = 0; hh < 2; hh++) {
            int oc = warp_m*32 + mt*16 + hh*8 + g;
            float sv = 0.f, qv = 0.f;
            __half* obase = g_fpk + (size_t)(img*128 + oc)*NPMAX + pixbase;
            #pragma unroll
            for (int nt = 0; nt < 4; nt++) {
                float c0 = acc[mt][nt][hh*2], c1 = acc[mt][nt][hh*2 + 1];
                int pxl = warp_n*32 + nt*8 + cp;
                *(__half2*)(obase + pxl) = __floats2half2_rn(c0, c1);
                float w0 = s_wgt[pxl], w1 = s_wgt[pxl + 1];
                sv += w0*c0 + w1*c1; qv += w0*c0*c0 + w1*c1*c1;
            }
            atomicAdd(&s_red[oc], sv);
            atomicAdd(&s_red[128 + oc], qv);
        }
    }
    __syncthreads();
    if (tid < 128) {
        atomicAdd(&g_sum1[tid], s_red[tid]);
        atomicAdd(&g_sq1[tid],  s_red[128 + tid]);
    }
}

// ---------------- BN1 + ReLU + maxpool: table-driven, 2 channels/thread ----------------
__global__ void __launch_bounds__(256) k_pool(const float* __restrict__ gamma,
                                              const float* __restrict__ beta) {
    int idx = blockIdx.x * 256 + threadIdx.x;
    int pix = idx % NPIX2;
    int pr  = idx / NPIX2;
    int img = pr >> 6, cpr = pr & 63;
    int c0 = cpr*2;
    int nc0 = img*128 + c0;

    float mean0 = g_sum1[c0] * (1.f / N1F);
    float var0  = g_sq1[c0]  * (1.f / N1F) - mean0*mean0;
    float a0 = __ldg(gamma + c0) * rsqrtf(var0 + 1e-5f);
    float b0 = __ldg(beta + c0) - a0 * mean0;
    float mean1 = g_sum1[c0+1] * (1.f / N1F);
    float var1  = g_sq1[c0+1]  * (1.f / N1F) - mean1*mean1;
    float a1 = __ldg(gamma + c0+1) * rsqrtf(var1 + 1e-5f);
    float b1 = __ldg(beta + c0+1) - a1 * mean1;

    const __half* f0 = g_fpk + (size_t)nc0 * NPMAX;
    const __half* f1 = f0 + NPMAX;

    uint4 q0 = g_ptab4[pix*2];
    uint4 q1 = g_ptab4[pix*2 + 1];
    unsigned short id[9] = {
        (unsigned short)(q0.x), (unsigned short)(q0.x >> 16),
        (unsigned short)(q0.y), (unsigned short)(q0.y >> 16),
        (unsigned short)(q0.z), (unsigned short)(q0.z >> 16),
        (unsigned short)(q0.w), (unsigned short)(q0.w >> 16),
        (unsigned short)(q1.x)
    };

    __half2 mx = __halves2half2(__ushort_as_half(0xFC00), __ushort_as_half(0xFC00));
    __half2 mn = __halves2half2(__ushort_as_half(0x7C00), __ushort_as_half(0x7C00));
    #pragma unroll
    for (int j = 0; j < 9; j++) {
        __half2 v = __halves2half2(f0[id[j]], f1[id[j]]);
        mx = __hmax2(mx, v);
        mn = __hmin2(mn, v);
    }
    float mx0 = __half2float(__low2half(mx)),  mx1 = __half2float(__high2half(mx));
    float mn0 = __half2float(__low2half(mn)),  mn1 = __half2float(__high2half(mn));
    float m0 = fmaf(a0, (a0 >= 0.f) ? mx0 : mn0, b0);
    float m1 = fmaf(a1, (a1 >= 0.f) ? mx1 : mn1, b1);
    __half h0 = __float2half_rn(fmaxf(m0, 0.f));
    __half h1 = __float2half_rn(fmaxf(m1, 0.f));

    int y = pix / 56, x = pix - y*56;
    size_t pos = (size_t)nc0 * PPLANE + (size_t)(y + 1) * 64 + x;
    g_hp[GUARD + pos] = h0;
    g_hs[GUARD + pos - 1] = h0;
    g_hp[GUARD + pos + PPLANE] = h1;
    g_hs[GUARD + pos + PPLANE - 1] = h1;
}

// ---------------- conv2: two-row CTA, single-term A, pure-async ----------------
__global__ void __launch_bounds__(256, 2) k_conv2m(float* __restrict__ out) {
    extern __shared__ __align__(128) char dsm[];
    __shared__ int t_bo[1152];
    __shared__ float s_red[256];

    int tid = threadIdx.x, lane = tid & 31, wid = tid >> 5;
    int warp_m = wid & 3, warp_n = wid >> 2;

    for (int k = tid; k < 1152; k += 256) {
        int ic = k / 9, r = k - ic*9;
        int dy = r/3 - 1, dx = r - (r/3)*3 - 1;
        int off = dy*PSTRIDE + dx;
        int sel = off & 1;
        t_bo[k] = ((ic*PPLANE + (off - sel)) << 1) | sel;
    }
    s_red[tid] = 0.f;
    __syncthreads();

    int img = blockIdx.x / 28;
    int t2  = blockIdx.x - img*28;
    int yp0 = 2*t2 + 1;
    size_t ibase = (size_t)img * 128 * PPLANE;
    const __half* HP = g_hp + GUARD;
    const __half* HS = g_hs + GUARD;

    uint32_t sb = smem_u32(dsm);

    #define C2_CPA(s, buf) do { \
        _Pragma("unroll") for (int i = 0; i < 2; i++) { \
            int id = tid + i*256, row = id >> 2, c = id & 3; \
            const __half* src = g_w2h + row*1152 + (s)*32 + c*8; \
            uint32_t dst = sb + (buf)*C2_STAGE + row*64 + (((c ^ ((row>>1)&3)) << 4)); \
            CP16(dst, src); } } while (0)
    #define C2_CPB(s, buf) do { \
        _Pragma("unroll") for (int i = 0; i < 8; i++) { \
            int id = tid + i*256, krow = id >> 6, ch = id & 63; \
            int bo = t_bo[(s)*32 + krow]; \
            const __half* base = (bo & 1) ? HS : HP; \
            int r = ch >> 5, xh = ch & 31; \
            const __half* src = base + ibase + (bo >> 1) + (yp0 + r)*64 + xh*2; \
            int gq = r*8 + (xh >> 2); \
            uint32_t dst = sb + (buf)*C2_STAGE + C2_BOFF + krow*256 \
                         + (((gq ^ (krow & 7)) << 4)) + ((xh & 3) << 2); \
            CP4(dst, src); } } while (0)

    uint32_t arow = warp_m*32 + (lane & 15);
    uint32_t aswz = (arow >> 1) & 3;
    uint32_t arb  = arow * 64;
    uint32_t acol = lane >> 4;
    uint32_t brow = ((lane >> 3) & 1)*8 + (lane & 7);
    uint32_t bswz = lane & 7;
    uint32_t bg0  = warp_n*8 + (lane >> 4);

    float acc[2][8][4];
    #pragma unroll
    for (int a = 0; a < 2; a++)
        #pragma unroll
        for (int b = 0; b < 8; b++)
            #pragma unroll
            for (int c = 0; c < 4; c++) acc[a][b][c] = 0.f;

    C2_CPA(0, 0); C2_CPB(0, 0); CPCOMMIT();
    C2_CPA(1, 1); C2_CPB(1, 1); CPCOMMIT();

    for (int s = 0; s < 36; s++) {
        CPWAIT(1);
        __syncthreads();
        int nb = (s + 2) % 3;
        if (s + 2 < 36) { C2_CPA(s + 2, nb); C2_CPB(s + 2, nb); }
        CPCOMMIT();

        uint32_t bufb = sb + (s % 3) * C2_STAGE;
        #pragma unroll
        for (int h = 0; h < 2; h++) {
            uint32_t t[4];
            uint32_t bq[8][2];
            uint32_t bbase = bufb + C2_BOFF + (h*16 + brow)*256;
            #pragma unroll
            for (int j = 0; j < 4; j++) {
                ldsm4t(bbase + (((bg0 + 2*j) ^ bswz) << 4), t);
                bq[2*j][0]   = t[0]; bq[2*j][1]   = t[1];
                bq[2*j+1][0] = t[2]; bq[2*j+1][1] = t[3];
            }
            uint32_t ac = (((h*2) + acol) ^ aswz) << 4;
            uint32_t am[2][4];
            ldsm4(bufb + arb + ac, am[0]);
            ldsm4(bufb + arb + 1024 + ac, am[1]);
            #pragma unroll
            for (int mt = 0; mt < 2; mt++)
                #pragma unroll
                for (int nt = 0; nt < 8; nt++) mma16816(acc[mt][nt], am[mt], bq[nt]);
        }
    }

    int g = lane >> 2, cp = (lane & 3) * 2;
    int yo = 2*t2 + warp_n;
    #pragma unroll
    for (int mt = 0; mt < 2; mt++) {
        #pragma unroll
        for (int hh = 0; hh < 2; hh++) {
            int oc = warp_m*32 + mt*16 + hh*8 + g;
            float sv = 0.f, qv = 0.f;
            float* obase = out + (size_t)(img*128 + oc)*NPIX2 + yo*56;
            #pragma unroll
            for (int nt = 0; nt < 8; nt++) {
                float c0 = acc[mt][nt][hh*2], c1 = acc[mt][nt][hh*2 + 1];
                int x = nt*8 + cp;
                if (x <= 55) { obase[x] = c0; sv += c0; qv += c0*c0; }
                if (x + 1 <= 55) { obase[x + 1] = c1; sv += c1; qv += c1*c1; }
            }
            atomicAdd(&s_red[oc], sv);
            atomicAdd(&s_red[128 + oc], qv);
        }
    }
    __syncthreads();
    if (tid < 128) {
        atomicAdd(&g_sum2[tid], s_red[tid]);
        atomicAdd(&g_sq2[tid],  s_red[128 + tid]);
    }
}

// ---------------- BN2 + ReLU in place (float4) ----------------
__global__ void k_bn2(float4* __restrict__ out,
                      const float* __restrict__ gamma, const float* __restrict__ beta) {
    int i = blockIdx.x * 256 + threadIdx.x;
    if (i >= BATCH * 128 * (NPIX2/4)) return;
    int c = (i / (NPIX2/4)) & 127;
    float mean = g_sum2[c] * (1.f / N2F);
    float var  = g_sq2[c]  * (1.f / N2F) - mean * mean;
    float a = __ldg(gamma + c) * rsqrtf(var + 1e-5f);
    float b = __ldg(beta + c) - a * mean;
    float4 v = out[i];
    v.x = fmaxf(fmaf(a, v.x, b), 0.f);
    v.y = fmaxf(fmaf(a, v.y, b), 0.f);
    v.z = fmaxf(fmaf(a, v.z, b), 0.f);
    v.w = fmaxf(fmaf(a, v.w, b), 0.f);
    out[i] = v;
}

// ---------------- launch ----------------
extern "C" void kernel_launch(void* const* d_in, const int* in_sizes, int n_in,
                              void* d_out, int out_size) {
    const float* inp = (const float*)d_in[0];
    const float* w1  = (const float*)d_in[1];
    const float* g1  = (const float*)d_in[2];
    const float* b1  = (const float*)d_in[3];
    const float* w2  = (const float*)d_in[4];
    const float* g2  = (const float*)d_in[5];
    const float* b2  = (const float*)d_in[6];
    float* out = (float*)d_out;

    WinTab tab;
    int np = 0;
    for (int s = 0; s < 7; s++) {
        int a = 16*s, b = a + 16, c = 224 - b, d = 224 - a;
        float scale = (float)(2.0 - (double)s / 6.0);
        for (int w = 0; w < 4; w++) {
            int t, l, bt, r;
            if      (w == 0) { t = a; l = a; bt = b; r = c; }
            else if (w == 1) { t = b; l = a; bt = d; r = b; }
            else if (w == 2) { t = c; l = b; bt = d; r = d; }
            else             { t = a; l = c; bt = c; r = d; }
            Win& W = tab.w[s*4 + w];
            W.ti = (int)((float)(t  + 6) / scale) - 3;
            W.li = (int)((float)(l  + 6) / scale) - 3;
            int bi = (int)((float)(bt + 6) / scale) + 3;
            int ri = (int)((float)(r  + 6) / scale) + 3;
            W.to = t >> 1; W.lo = l >> 1;
            W.oh = (bt >> 1) - W.to; W.ow = (r >> 1) - W.lo;
            W.fh = (bi - W.ti - 7) / 2 + 1;
            W.fw = (ri - W.li - 7) / 2 + 1;
            W.base = np;
            np += W.fh * W.fw;
        }
    }
    int tpi = (np + 63) / 64;

    cudaFuncSetAttribute(k_conv1m, cudaFuncAttributeMaxDynamicSharedMemorySize, DYN1);
    cudaFuncSetAttribute(k_conv2m, cudaFuncAttributeMaxDynamicSharedMemorySize, C2_DYN);

    k_init<<<576, 256>>>(w1, w2);
    k_prep<<<(BATCH*3*IMG*IMG/4 + 255) / 256, 256>>>((const float4*)inp);
    k_map<<<(NPIX1 + 255) / 256, 256>>>(tab);
    k_ptab<<<(NPIX2 + 255) / 256, 256>>>();
    k_conv1m<<<dim3(tpi, BATCH), 256, DYN1>>>();
    k_pool<<<BATCH*64*NPIX2/256, 256>>>(g1, b1);
    k_conv2m<<<BATCH*28, 256, C2_DYN>>>(out);
    k_bn2<<<(BATCH*128*(NPIX2/4) + 255) / 256, 256>>>((float4*)out, g2, b2);
}

// round 12
// speedup vs baseline: 2.0052x; 1.0788x over previous
#include <cuda_runtime.h>
#include <cuda_fp16.h>
#include <cstdint>

// ---------------- constants ----------------
#define IMG   224
#define BATCH 32
#define NPIX1 12544
#define NPIX2 3136
#define N1F   401408.0f
#define N2F   100352.0f

// conv1 smem geometry (fp16x2: Ah, Al, B)
#define RSTRIDE 80
#define ATERM   10240
#define BOFF    20480
#define STAGE1  25600
#define DYN1    51200

// conv2 geometry: two-row CTA, single-term A (8KB) + B (8KB), 4 stages
#define C2_BOFF  8192
#define C2_STAGE 16384
#define C2_DYN   (4*C2_STAGE)   // 65536

// padded activation plane
#define PSTRIDE 64
#define PPLANE  3712
#define GUARD   128

// packed conv1 output
#define NPMAX 5376

struct Win { int ti, li, to, lo, oh, ow, fh, fw, base; };
struct WinTab { Win w[28]; };

// ---------------- scratch ----------------
__device__ __half g_in16[BATCH*3*IMG*IMG];
__device__ __half g_fpk[BATCH*128*NPMAX];
__device__ __half g_hp[GUARD + BATCH*128*PPLANE + GUARD];   // shift 0
__device__ __half g_hs[GUARD + BATCH*128*PPLANE + GUARD];   // hs[j] = hp[j+1]
__device__ __half g_hm[GUARD + BATCH*128*PPLANE + GUARD];   // hm[j] = hp[j-1]
__device__ __half g_w1h[128*160], g_w1l[128*160];
__device__ __half g_w2h[128*1152];
__device__ uint4 g_ptab4[NPIX2*2];
__device__ int   g_wgt[NPMAX];
__device__ int2  g_pc[NPMAX];
__device__ float g_sum1[128], g_sq1[128], g_sum2[128], g_sq2[128];

// ---------------- helpers ----------------
__device__ __forceinline__ uint32_t smem_u32(const void* p) {
    uint32_t a;
    asm("{ .reg .u64 t; cvta.to.shared.u64 t, %1; cvt.u32.u64 %0, t; }" : "=r"(a) : "l"(p));
    return a;
}
__device__ __forceinline__ void ldsm4(uint32_t addr, uint32_t* r) {
    asm volatile("ldmatrix.sync.aligned.m8n8.x4.shared.b16 {%0,%1,%2,%3}, [%4];"
        : "=r"(r[0]), "=r"(r[1]), "=r"(r[2]), "=r"(r[3]) : "r"(addr));
}
__device__ __forceinline__ void ldsm4t(uint32_t addr, uint32_t* r) {
    asm volatile("ldmatrix.sync.aligned.m8n8.x4.trans.shared.b16 {%0,%1,%2,%3}, [%4];"
        : "=r"(r[0]), "=r"(r[1]), "=r"(r[2]), "=r"(r[3]) : "r"(addr));
}
__device__ __forceinline__ void mma16816(float* c, const uint32_t* a, const uint32_t* b) {
    asm volatile("mma.sync.aligned.m16n8k16.row.col.f32.f16.f16.f32 "
        "{%0,%1,%2,%3}, {%4,%5,%6,%7}, {%8,%9}, {%0,%1,%2,%3};"
        : "+f"(c[0]), "+f"(c[1]), "+f"(c[2]), "+f"(c[3])
        : "r"(a[0]), "r"(a[1]), "r"(a[2]), "r"(a[3]), "r"(b[0]), "r"(b[1]));
}
#define CP16(dst, src) \
    asm volatile("cp.async.cg.shared.global [%0], [%1], 16;" :: "r"(dst), "l"(src) : "memory")
#define CPCOMMIT() asm volatile("cp.async.commit_group;" ::: "memory")
#define CPWAIT(n)  asm volatile("cp.async.wait_group %0;" :: "n"(n) : "memory")

#define CPA(WH, WL, KDIM, s, buf, STAGE) do { \
    _Pragma("unroll") for (int i = 0; i < 4; i++) { \
        int id = tid + i*256, term = id >> 9, rem = id & 511, row = rem >> 2, c = rem & 3; \
        const __half* src = (term ? (WL) : (WH)) + row*(KDIM) + (s)*32 + c*8; \
        uint32_t dst = sb + (buf)*(STAGE) + term*ATERM + row*RSTRIDE + c*16; \
        CP16(dst, src); } \
    CPCOMMIT(); } while (0)

__device__ __forceinline__ int map_id(int y, int x, const WinTab& tab) {
    int bi = y >> 3, bj = x >> 3;
    int sS = min(min(bi, bj), min(13 - bi, 13 - bj));
    int b2 = 8 * (sS + 1), c2v = 112 - b2;
    int w = (y < b2 && x < c2v) ? 0 : (x < b2 ? 1 : (y >= c2v ? 2 : 3));
    Win W = tab.w[sS*4 + w];
    int fy = ((y - W.to) * W.fh) / W.oh;
    int fx = ((x - W.lo) * W.fw) / W.ow;
    return W.base + fy * W.fw + fx;
}

// ---------------- init: weights + zero stats/wgt ----------------
__global__ void k_init(const float* __restrict__ w1, const float* __restrict__ w2) {
    int tid = blockIdx.x * blockDim.x + threadIdx.x;
    if (tid < 128) { g_sum1[tid] = 0.f; g_sq1[tid] = 0.f; g_sum2[tid] = 0.f; g_sq2[tid] = 0.f; }
    if (tid < NPMAX) { g_wgt[tid] = 0; g_pc[tid] = make_int2(0, 0); }
    if (tid < 128*160) {
        int oc = tid / 160, k = tid - oc*160;
        float v = (k < 147) ? w1[oc*147 + k] : 0.f;
        __half h = __float2half_rn(v);
        g_w1h[tid] = h;
        g_w1l[tid] = __float2half_rn(v - __half2float(h));
    }
    if (tid < 128*1152) g_w2h[tid] = __float2half_rn(w2[tid]);
}

// ---------------- fused pre-pass: input->fp16 | map(wgt,pc) | pool tap table ----------------
#define PREP_BLKS 4704
#define MAP_BLKS  49
__global__ void k_pre(const float4* __restrict__ inp, WinTab tab) {
    int b = blockIdx.x, tid = threadIdx.x;
    if (b < PREP_BLKS) {
        int i = b*256 + tid;
        float4 v = inp[i];
        __half2 a = __floats2half2_rn(v.x, v.y);
        __half2 c = __floats2half2_rn(v.z, v.w);
        *(uint2*)(g_in16 + i*4) = make_uint2(*(uint32_t*)&a, *(uint32_t*)&c);
    } else if (b < PREP_BLKS + MAP_BLKS) {
        int pix = (b - PREP_BLKS)*256 + tid;
        int y = pix / 112, x = pix - y*112;
        int bi = y >> 3, bj = x >> 3;
        int sS = min(min(bi, bj), min(13 - bi, 13 - bj));
        int b2 = 8 * (sS + 1), c2v = 112 - b2;
        int w = (y < b2 && x < c2v) ? 0 : (x < b2 ? 1 : (y >= c2v ? 2 : 3));
        Win W = tab.w[sS*4 + w];
        int fy = ((y - W.to) * W.fh) / W.oh;
        int fx = ((x - W.lo) * W.fw) / W.ow;
        int id = W.base + fy * W.fw + fx;
        atomicAdd(&g_wgt[id], 1);
        g_pc[id] = make_int2(W.ti + 2*fy - 3, W.li + 2*fx - 3);
    } else {
        int pix = (b - PREP_BLKS - MAP_BLKS)*256 + tid;
        if (pix >= NPIX2) return;
        int y = pix / 56, x = pix - y*56;
        unsigned short ids[16];
        #pragma unroll
        for (int r = 0; r < 3; r++)
            #pragma unroll
            for (int s = 0; s < 3; s++) {
                int yy = max(2*y - 1 + r, 0);
                int xx = max(2*x - 1 + s, 0);
                ids[r*3 + s] = (unsigned short)map_id(yy, xx, tab);
            }
        #pragma unroll
        for (int j = 9; j < 16; j++) ids[j] = ids[0];
        uint32_t u[8];
        #pragma unroll
        for (int j = 0; j < 8; j++)
            u[j] = (uint32_t)ids[2*j] | ((uint32_t)ids[2*j+1] << 16);
        g_ptab4[pix*2]     = make_uint4(u[0], u[1], u[2], u[3]);
        g_ptab4[pix*2 + 1] = make_uint4(u[4], u[5], u[6], u[7]);
    }
}

// ---------------- conv1: fp16x2 over packed pixels, fp16 gather ----------------
__global__ void __launch_bounds__(256, 3) k_conv1m() {
    extern __shared__ __align__(128) char dsm[];
    __shared__ int t_c[160];
    __shared__ signed char t_ky[160], t_kx[160];
    __shared__ float s_red[256];
    __shared__ float s_wgt[64];

    int tid = threadIdx.x, lane = tid & 31, wid = tid >> 5;
    int warp_m = wid & 3, warp_n = wid >> 2;

    if (tid < 160) {
        int k = tid;
        if (k < 147) {
            int c = k / 49, r = k - c*49, ky = r / 7, kx = r - ky*7;
            t_c[k] = c * 50176; t_ky[k] = (signed char)ky; t_kx[k] = (signed char)kx;
        } else { t_c[k] = -1; t_ky[k] = 0; t_kx[k] = 0; }
    }
    s_red[tid] = 0.f;

    int img = blockIdx.y;
    int pixbase = blockIdx.x * 64;
    if (tid < 64) s_wgt[tid] = (float)g_wgt[pixbase + tid];
    __syncthreads();

    int pix = pixbase + (tid >> 2);
    int kq = tid & 3;
    int2 pcv = g_pc[pix];
    int iy0 = pcv.x, ix0 = pcv.y;
    const __half* ibase = g_in16 + img * 150528;

    uint32_t sb = smem_u32(dsm);
    uint32_t Aln = (lane & 15)*RSTRIDE + (lane >> 4)*16;
    uint32_t Bln = ((lane >> 4)*8 + (lane & 7))*RSTRIDE + ((lane >> 3) & 1)*16;
    uint32_t bsts = (tid >> 2)*RSTRIDE + kq*16;

    uint32_t hw[4];
    #define C1_LDGB(s) do { int kb = (s)*32 + kq*8; \
        unsigned short bu[8]; \
        _Pragma("unroll") for (int j = 0; j < 8; j++) { \
            int k = kb + j; \
            int iy = iy0 + t_ky[k], ix = ix0 + t_kx[k]; \
            bool v = (t_c[k] >= 0) && ((unsigned)iy < 224u) && ((unsigned)ix < 224u); \
            bu[j] = v ? __half_as_ushort(__ldg(ibase + t_c[k] + iy*224 + ix)) : (unsigned short)0; } \
        _Pragma("unroll") for (int j = 0; j < 4; j++) \
            hw[j] = (uint32_t)bu[2*j] | ((uint32_t)bu[2*j+1] << 16); } while (0)
    #define C1_STSB(buf) do { \
        *(uint4*)(dsm + (buf)*STAGE1 + BOFF + bsts) = make_uint4(hw[0], hw[1], hw[2], hw[3]); } while (0)

    float acc[2][4][4];
    #pragma unroll
    for (int a = 0; a < 2; a++)
        #pragma unroll
        for (int b = 0; b < 4; b++)
            #pragma unroll
            for (int c = 0; c < 4; c++) acc[a][b][c] = 0.f;

    CPA(g_w1h, g_w1l, 160, 0, 0, STAGE1);
    CPA(g_w1h, g_w1l, 160, 1, 1, STAGE1);
    C1_LDGB(0);
    CPWAIT(1);
    C1_STSB(0);
    __syncthreads();

    for (int s = 0; s < 5; s++) {
        int buf = s & 1;
        if (s < 4) C1_LDGB(s + 1);
        {
            uint32_t Ab = sb + buf*STAGE1 + warp_m*(32*RSTRIDE);
            uint32_t Bb = sb + buf*STAGE1 + BOFF + warp_n*(32*RSTRIDE);
            #pragma unroll
            for (int h = 0; h < 2; h++) {
                uint32_t ab = Ab + h*32 + Aln;
                uint32_t bb = Bb + h*32 + Bln;
                uint32_t am[2][4], bq[4][2], t[4];
                ldsm4(bb, t); bq[0][0]=t[0]; bq[0][1]=t[1]; bq[1][0]=t[2]; bq[1][1]=t[3];
                ldsm4(bb + 16*RSTRIDE, t); bq[2][0]=t[0]; bq[2][1]=t[1]; bq[3][0]=t[2]; bq[3][1]=t[3];
                ldsm4(ab, am[0]); ldsm4(ab + 16*RSTRIDE, am[1]);
                #pragma unroll
                for (int mt = 0; mt < 2; mt++)
                    #pragma unroll
                    for (int nt = 0; nt < 4; nt++) mma16816(acc[mt][nt], am[mt], bq[nt]);
                ldsm4(ab + ATERM, am[0]); ldsm4(ab + ATERM + 16*RSTRIDE, am[1]);
                #pragma unroll
                for (int mt = 0; mt < 2; mt++)
                    #pragma unroll
                    for (int nt = 0; nt < 4; nt++) mma16816(acc[mt][nt], am[mt], bq[nt]);
            }
        }
        if (s < 4) {
            CPWAIT(0);
            C1_STSB(buf ^ 1);
            __syncthreads();
            if (s + 2 < 5) CPA(g_w1h, g_w1l, 160, s + 2, buf, STAGE1);
        }
    }

    int g = lane >> 2, cp = (lane & 3) * 2;
    #pragma unroll
    for (int mt = 0; mt < 2; mt++) {
        #pragma unroll
        for (int hh = 0; hh < 2; hh++) {
            int oc = warp_m*32 + mt*16 + hh*8 + g;
            float sv = 0.f, qv = 0.f;
            __half* obase = g_fpk + (size_t)(img*128 + oc)*NPMAX + pixbase;
            #pragma unroll
            for (int nt = 0; nt < 4; nt++) {
                float c0 = acc[mt][nt][hh*2], c1 = acc[mt][nt][hh*2 + 1];
                int pxl = warp_n*32 + nt*8 + cp;
                *(__half2*)(obase + pxl) = __floats2half2_rn(c0, c1);
                float w0 = s_wgt[pxl], w1 = s_wgt[pxl + 1];
                sv += w0*c0 + w1*c1; qv += w0*c0*c0 + w1*c1*c1;
            }
            atomicAdd(&s_red[oc], sv);
            atomicAdd(&s_red[128 + oc], qv);
        }
    }
    __syncthreads();
    if (tid < 128) {
        atomicAdd(&g_sum1[tid], s_red[tid]);
        atomicAdd(&g_sq1[tid],  s_red[128 + tid]);
    }
}

// ---------------- BN1 + ReLU + maxpool: table-driven, 2 channels/thread, 3 copies ----------------
__global__ void __launch_bounds__(256) k_pool(const float* __restrict__ gamma,
                                              const float* __restrict__ beta) {
    int idx = blockIdx.x * 256 + threadIdx.x;
    int pix = idx % NPIX2;
    int pr  = idx / NPIX2;
    int img = pr >> 6, cpr = pr & 63;
    int c0 = cpr*2;
    int nc0 = img*128 + c0;

    float mean0 = g_sum1[c0] * (1.f / N1F);
    float var0  = g_sq1[c0]  * (1.f / N1F) - mean0*mean0;
    float a0 = __ldg(gamma + c0) * rsqrtf(var0 + 1e-5f);
    float b0 = __ldg(beta + c0) - a0 * mean0;
    float mean1 = g_sum1[c0+1] * (1.f / N1F);
    float var1  = g_sq1[c0+1]  * (1.f / N1F) - mean1*mean1;
    float a1 = __ldg(gamma + c0+1) * rsqrtf(var1 + 1e-5f);
    float b1 = __ldg(beta + c0+1) - a1 * mean1;

    const __half* f0 = g_fpk + (size_t)nc0 * NPMAX;
    const __half* f1 = f0 + NPMAX;

    uint4 q0 = g_ptab4[pix*2];
    uint4 q1 = g_ptab4[pix*2 + 1];
    unsigned short id[9] = {
        (unsigned short)(q0.x), (unsigned short)(q0.x >> 16),
        (unsigned short)(q0.y), (unsigned short)(q0.y >> 16),
        (unsigned short)(q0.z), (unsigned short)(q0.z >> 16),
        (unsigned short)(q0.w), (unsigned short)(q0.w >> 16),
        (unsigned short)(q1.x)
    };

    __half2 mx = __halves2half2(__ushort_as_half(0xFC00), __ushort_as_half(0xFC00));
    __half2 mn = __halves2half2(__ushort_as_half(0x7C00), __ushort_as_half(0x7C00));
    #pragma unroll
    for (int j = 0; j < 9; j++) {
        __half2 v = __halves2half2(f0[id[j]], f1[id[j]]);
        mx = __hmax2(mx, v);
        mn = __hmin2(mn, v);
    }
    float mx0 = __half2float(__low2half(mx)),  mx1 = __half2float(__high2half(mx));
    float mn0 = __half2float(__low2half(mn)),  mn1 = __half2float(__high2half(mn));
    float m0 = fmaf(a0, (a0 >= 0.f) ? mx0 : mn0, b0);
    float m1 = fmaf(a1, (a1 >= 0.f) ? mx1 : mn1, b1);
    __half h0 = __float2half_rn(fmaxf(m0, 0.f));
    __half h1 = __float2half_rn(fmaxf(m1, 0.f));

    int y = pix / 56, x = pix - y*56;
    size_t pos = (size_t)nc0 * PPLANE + (size_t)(y + 1) * 64 + x;
    g_hp[GUARD + pos] = h0;
    g_hs[GUARD + pos - 1] = h0;
    g_hm[GUARD + pos + 1] = h0;
    g_hp[GUARD + pos + PPLANE] = h1;
    g_hs[GUARD + pos + PPLANE - 1] = h1;
    g_hm[GUARD + pos + PPLANE + 1] = h1;
}

// ---------------- conv2: two-row CTA, single-term A, all-16B cp.async, 4 stages ----------------
__global__ void __launch_bounds__(256, 2) k_conv2m(float* __restrict__ out) {
    extern __shared__ __align__(128) char dsm[];
    __shared__ int t_bo[1152];       // ((ic*PPLANE + dy*64 + 64) << 2) | (dx+1)
    __shared__ float s_red[256];

    int tid = threadIdx.x, lane = tid & 31, wid = tid >> 5;
    int warp_m = wid & 3, warp_n = wid >> 2;

    for (int k = tid; k < 1152; k += 256) {
        int ic = k / 9, r = k - ic*9;
        int dy = r/3 - 1, dx = r - (r/3)*3 - 1;
        t_bo[k] = ((ic*PPLANE + dy*64 + 64) << 2) | (dx + 1);
    }
    s_red[tid] = 0.f;
    __syncthreads();

    int img = blockIdx.x / 28;
    int t2  = blockIdx.x - img*28;
    int yp0 = 2*t2 + 1;
    size_t ibase = (size_t)img * 128 * PPLANE;
    const __half* HP = g_hp + GUARD;
    const __half* HS = g_hs + GUARD;
    const __half* HM = g_hm + GUARD;

    uint32_t sb = smem_u32(dsm);

    #define C2_CPA(s, buf) do { \
        _Pragma("unroll") for (int i = 0; i < 2; i++) { \
            int id = tid + i*256, row = id >> 2, c = id & 3; \
            const __half* src = g_w2h + row*1152 + (s)*32 + c*8; \
            uint32_t dst = sb + (buf)*C2_STAGE + row*64 + (((c ^ ((row>>1)&3)) << 4)); \
            CP16(dst, src); } } while (0)
    // B: 512 x 16B granules per stage; all sources 16B-aligned via hm/hp/hs select
    #define C2_CPB(s, buf) do { \
        _Pragma("unroll") for (int i = 0; i < 2; i++) { \
            int id = tid + i*256, krow = id >> 4, G = id & 15; \
            int p = t_bo[(s)*32 + krow]; \
            int sel = p & 3; \
            const __half* base = (sel == 0) ? HM : ((sel == 1) ? HP : HS); \
            int r = G >> 3, gx = G & 7; \
            const __half* src = base + ibase + ((p >> 2) - 64) + (yp0 + r)*64 + gx*8; \
            uint32_t dst = sb + (buf)*C2_STAGE + C2_BOFF + krow*256 + (((G ^ (krow & 7)) << 4)); \
            CP16(dst, src); } } while (0)

    uint32_t arow = warp_m*32 + (lane & 15);
    uint32_t aswz = (arow >> 1) & 3;
    uint32_t arb  = arow * 64;
    uint32_t acol = lane >> 4;
    uint32_t brow = ((lane >> 3) & 1)*8 + (lane & 7);
    uint32_t bswz = lane & 7;
    uint32_t bg0  = warp_n*8 + (lane >> 4);

    float acc[2][8][4];
    #pragma unroll
    for (int a = 0; a < 2; a++)
        #pragma unroll
        for (int b = 0; b < 8; b++)
            #pragma unroll
            for (int c = 0; c < 4; c++) acc[a][b][c] = 0.f;

    C2_CPA(0, 0); C2_CPB(0, 0); CPCOMMIT();
    C2_CPA(1, 1); C2_CPB(1, 1); CPCOMMIT();
    C2_CPA(2, 2); C2_CPB(2, 2); CPCOMMIT();

    for (int s = 0; s < 36; s++) {
        CPWAIT(2);
        __syncthreads();
        int nb = (s + 3) & 3;
        if (s + 3 < 36) { C2_CPA(s + 3, nb); C2_CPB(s + 3, nb); }
        CPCOMMIT();

        uint32_t bufb = sb + (s & 3) * C2_STAGE;
        #pragma unroll
        for (int h = 0; h < 2; h++) {
            uint32_t t[4];
            uint32_t bq[8][2];
            uint32_t bbase = bufb + C2_BOFF + (h*16 + brow)*256;
            #pragma unroll
            for (int j = 0; j < 4; j++) {
                ldsm4t(bbase + (((bg0 + 2*j) ^ bswz) << 4), t);
                bq[2*j][0]   = t[0]; bq[2*j][1]   = t[1];
                bq[2*j+1][0] = t[2]; bq[2*j+1][1] = t[3];
            }
            uint32_t ac = (((h*2) + acol) ^ aswz) << 4;
            uint32_t am[2][4];
            ldsm4(bufb + arb + ac, am[0]);
            ldsm4(bufb + arb + 1024 + ac, am[1]);
            #pragma unroll
            for (int mt = 0; mt < 2; mt++)
                #pragma unroll
                for (int nt = 0; nt < 8; nt++) mma16816(acc[mt][nt], am[mt], bq[nt]);
        }
    }

    int g = lane >> 2, cp = (lane & 3) * 2;
    int yo = 2*t2 + warp_n;
    #pragma unroll
    for (int mt = 0; mt < 2; mt++) {
        #pragma unroll
        for (int hh = 0; hh < 2; hh++) {
            int oc = warp_m*32 + mt*16 + hh*8 + g;
            float sv = 0.f, qv = 0.f;
            float* obase = out + (size_t)(img*128 + oc)*NPIX2 + yo*56;
            #pragma unroll
            for (int nt = 0; nt < 8; nt++) {
                float c0 = acc[mt][nt][hh*2], c1 = acc[mt][nt][hh*2 + 1];
                int x = nt*8 + cp;
                if (x <= 55) { obase[x] = c0; sv += c0; qv += c0*c0; }
                if (x + 1 <= 55) { obase[x + 1] = c1; sv += c1; qv += c1*c1; }
            }
            atomicAdd(&s_red[oc], sv);
            atomicAdd(&s_red[128 + oc], qv);
        }
    }
    __syncthreads();
    if (tid < 128) {
        atomicAdd(&g_sum2[tid], s_red[tid]);
        atomicAdd(&g_sq2[tid],  s_red[128 + tid]);
    }
}

// ---------------- BN2 + ReLU in place (float4) ----------------
__global__ void k_bn2(float4* __restrict__ out,
                      const float* __restrict__ gamma, const float* __restrict__ beta) {
    int i = blockIdx.x * 256 + threadIdx.x;
    if (i >= BATCH * 128 * (NPIX2/4)) return;
    int c = (i / (NPIX2/4)) & 127;
    float mean = g_sum2[c] * (1.f / N2F);
    float var  = g_sq2[c]  * (1.f / N2F) - mean * mean;
    float a = __ldg(gamma + c) * rsqrtf(var + 1e-5f);
    float b = __ldg(beta + c) - a * mean;
    float4 v = out[i];
    v.x = fmaxf(fmaf(a, v.x, b), 0.f);
    v.y = fmaxf(fmaf(a, v.y, b), 0.f);
    v.z = fmaxf(fmaf(a, v.z, b), 0.f);
    v.w = fmaxf(fmaf(a, v.w, b), 0.f);
    out[i] = v;
}

// ---------------- launch ----------------
extern "C" void kernel_launch(void* const* d_in, const int* in_sizes, int n_in,
                              void* d_out, int out_size) {
    const float* inp = (const float*)d_in[0];
    const float* w1  = (const float*)d_in[1];
    const float* g1  = (const float*)d_in[2];
    const float* b1  = (const float*)d_in[3];
    const float* w2  = (const float*)d_in[4];
    const float* g2  = (const float*)d_in[5];
    const float* b2  = (const float*)d_in[6];
    float* out = (float*)d_out;

    WinTab tab;
    int np = 0;
    for (int s = 0; s < 7; s++) {
        int a = 16*s, b = a + 16, c = 224 - b, d = 224 - a;
        float scale = (float)(2.0 - (double)s / 6.0);
        for (int w = 0; w < 4; w++) {
            int t, l, bt, r;
            if      (w == 0) { t = a; l = a; bt = b; r = c; }
            else if (w == 1) { t = b; l = a; bt = d; r = b; }
            else if (w == 2) { t = c; l = b; bt = d; r = d; }
            else             { t = a; l = c; bt = c; r = d; }
            Win& W = tab.w[s*4 + w];
            W.ti = (int)((float)(t  + 6) / scale) - 3;
            W.li = (int)((float)(l  + 6) / scale) - 3;
            int bi = (int)((float)(bt + 6) / scale) + 3;
            int ri = (int)((float)(r  + 6) / scale) + 3;
            W.to = t >> 1; W.lo = l >> 1;
            W.oh = (bt >> 1) - W.to; W.ow = (r >> 1) - W.lo;
            W.fh = (bi - W.ti - 7) / 2 + 1;
            W.fw = (ri - W.li - 7) / 2 + 1;
            W.base = np;
            np += W.fh * W.fw;
        }
    }
    int tpi = (np + 63) / 64;
    int ptab_blks = (NPIX2 + 255) / 256;

    cudaFuncSetAttribute(k_conv1m, cudaFuncAttributeMaxDynamicSharedMemorySize, DYN1);
    cudaFuncSetAttribute(k_conv2m, cudaFuncAttributeMaxDynamicSharedMemorySize, C2_DYN);

    k_init<<<576, 256>>>(w1, w2);
    k_pre<<<PREP_BLKS + MAP_BLKS + ptab_blks, 256>>>((const float4*)inp, tab);
    k_conv1m<<<dim3(tpi, BATCH), 256, DYN1>>>();
    k_pool<<<BATCH*64*NPIX2/256, 256>>>(g1, b1);
    k_conv2m<<<BATCH*28, 256, C2_DYN>>>(out);
    k_bn2<<<(BATCH*128*(NPIX2/4) + 255) / 256, 256>>>((float4*)out, g2, b2);
}

// round 13
// speedup vs baseline: 2.0945x; 1.0446x over previous
#include <cuda_runtime.h>
#include <cuda_fp16.h>
#include <cstdint>

// ---------------- constants ----------------
#define IMG   224
#define BATCH 32
#define NPIX1 12544
#define NPIX2 3136
#define N1F   401408.0f
#define N2F   100352.0f

// conv1 smem geometry (fp16x2: Ah, Al, B)
#define RSTRIDE 80
#define ATERM   10240
#define BOFF    20480
#define STAGE1  25600
#define DYN1    51200

// conv2 geometry: two-row CTA, single-term A (8KB) + B (8KB), 4 stages
#define C2_BOFF  8192
#define C2_STAGE 16384
#define C2_DYN   (4*C2_STAGE)   // 65536

// padded activation plane
#define PSTRIDE 64
#define PPLANE  3712
#define GUARD   128

// packed conv1 output
#define NPMAX 5376

struct Win { int ti, li, to, lo, oh, ow, fh, fw, base; };
struct WinTab { Win w[28]; };

// ---------------- scratch ----------------
__device__ __half g_in16[BATCH*3*IMG*IMG];
__device__ __half g_fpk[BATCH*128*NPMAX];
__device__ __half g_hp[GUARD + BATCH*128*PPLANE + GUARD];   // shift 0
__device__ __half g_hs[GUARD + BATCH*128*PPLANE + GUARD];   // hs[j] = hp[j+1]
__device__ __half g_hm[GUARD + BATCH*128*PPLANE + GUARD];   // hm[j] = hp[j-1]
__device__ __half g_w1h[128*160], g_w1l[128*160];
__device__ __half g_w2h[128*1152];
__device__ unsigned short g_map16[NPIX1];
__device__ int   g_wgt[NPMAX];
__device__ int2  g_pc[NPMAX];
__device__ float g_sum1[128], g_sq1[128], g_sum2[128], g_sq2[128];

// ---------------- helpers ----------------
__device__ __forceinline__ uint32_t smem_u32(const void* p) {
    uint32_t a;
    asm("{ .reg .u64 t; cvta.to.shared.u64 t, %1; cvt.u32.u64 %0, t; }" : "=r"(a) : "l"(p));
    return a;
}
__device__ __forceinline__ void ldsm4(uint32_t addr, uint32_t* r) {
    asm volatile("ldmatrix.sync.aligned.m8n8.x4.shared.b16 {%0,%1,%2,%3}, [%4];"
        : "=r"(r[0]), "=r"(r[1]), "=r"(r[2]), "=r"(r[3]) : "r"(addr));
}
__device__ __forceinline__ void ldsm4t(uint32_t addr, uint32_t* r) {
    asm volatile("ldmatrix.sync.aligned.m8n8.x4.trans.shared.b16 {%0,%1,%2,%3}, [%4];"
        : "=r"(r[0]), "=r"(r[1]), "=r"(r[2]), "=r"(r[3]) : "r"(addr));
}
__device__ __forceinline__ void mma16816(float* c, const uint32_t* a, const uint32_t* b) {
    asm volatile("mma.sync.aligned.m16n8k16.row.col.f32.f16.f16.f32 "
        "{%0,%1,%2,%3}, {%4,%5,%6,%7}, {%8,%9}, {%0,%1,%2,%3};"
        : "+f"(c[0]), "+f"(c[1]), "+f"(c[2]), "+f"(c[3])
        : "r"(a[0]), "r"(a[1]), "r"(a[2]), "r"(a[3]), "r"(b[0]), "r"(b[1]));
}
#define CP16(dst, src) \
    asm volatile("cp.async.cg.shared.global [%0], [%1], 16;" :: "r"(dst), "l"(src) : "memory")
#define CPCOMMIT() asm volatile("cp.async.commit_group;" ::: "memory")
#define CPWAIT(n)  asm volatile("cp.async.wait_group %0;" :: "n"(n) : "memory")

#define CPA(WH, WL, KDIM, s, buf, STAGE) do { \
    _Pragma("unroll") for (int i = 0; i < 4; i++) { \
        int id = tid + i*256, term = id >> 9, rem = id & 511, row = rem >> 2, c = rem & 3; \
        const __half* src = (term ? (WL) : (WH)) + row*(KDIM) + (s)*32 + c*8; \
        uint32_t dst = sb + (buf)*(STAGE) + term*ATERM + row*RSTRIDE + c*16; \
        CP16(dst, src); } \
    CPCOMMIT(); } while (0)

// ---------------- init: weights + zero stats/wgt ----------------
__global__ void k_init(const float* __restrict__ w1, const float* __restrict__ w2) {
    int tid = blockIdx.x * blockDim.x + threadIdx.x;
    if (tid < 128) { g_sum1[tid] = 0.f; g_sq1[tid] = 0.f; g_sum2[tid] = 0.f; g_sq2[tid] = 0.f; }
    if (tid < NPMAX) { g_wgt[tid] = 0; g_pc[tid] = make_int2(0, 0); }
    if (tid < 128*160) {
        int oc = tid / 160, k = tid - oc*160;
        float v = (k < 147) ? w1[oc*147 + k] : 0.f;
        __half h = __float2half_rn(v);
        g_w1h[tid] = h;
        g_w1l[tid] = __float2half_rn(v - __half2float(h));
    }
    if (tid < 128*1152) g_w2h[tid] = __float2half_rn(w2[tid]);
}

// ---------------- fused pre-pass: input->fp16 | map(map16,wgt,pc) ----------------
#define PREP_BLKS 4704
#define MAP_BLKS  49
__global__ void k_pre(const float4* __restrict__ inp, WinTab tab) {
    int b = blockIdx.x, tid = threadIdx.x;
    if (b < PREP_BLKS) {
        int i = b*256 + tid;
        float4 v = inp[i];
        __half2 a = __floats2half2_rn(v.x, v.y);
        __half2 c = __floats2half2_rn(v.z, v.w);
        *(uint2*)(g_in16 + i*4) = make_uint2(*(uint32_t*)&a, *(uint32_t*)&c);
    } else {
        int pix = (b - PREP_BLKS)*256 + tid;
        int y = pix / 112, x = pix - y*112;
        int bi = y >> 3, bj = x >> 3;
        int sS = min(min(bi, bj), min(13 - bi, 13 - bj));
        int b2 = 8 * (sS + 1), c2v = 112 - b2;
        int w = (y < b2 && x < c2v) ? 0 : (x < b2 ? 1 : (y >= c2v ? 2 : 3));
        Win W = tab.w[sS*4 + w];
        int fy = ((y - W.to) * W.fh) / W.oh;
        int fx = ((x - W.lo) * W.fw) / W.ow;
        int id = W.base + fy * W.fw + fx;
        g_map16[pix] = (unsigned short)id;
        atomicAdd(&g_wgt[id], 1);
        g_pc[id] = make_int2(W.ti + 2*fy - 3, W.li + 2*fx - 3);
    }
}

// ---------------- conv1: fp16x2 over packed pixels, fp16 gather ----------------
__global__ void __launch_bounds__(256, 3) k_conv1m() {
    extern __shared__ __align__(128) char dsm[];
    __shared__ int t_c[160];
    __shared__ signed char t_ky[160], t_kx[160];
    __shared__ float s_red[256];
    __shared__ float s_wgt[64];

    int tid = threadIdx.x, lane = tid & 31, wid = tid >> 5;
    int warp_m = wid & 3, warp_n = wid >> 2;

    if (tid < 160) {
        int k = tid;
        if (k < 147) {
            int c = k / 49, r = k - c*49, ky = r / 7, kx = r - ky*7;
            t_c[k] = c * 50176; t_ky[k] = (signed char)ky; t_kx[k] = (signed char)kx;
        } else { t_c[k] = -1; t_ky[k] = 0; t_kx[k] = 0; }
    }
    s_red[tid] = 0.f;

    int img = blockIdx.y;
    int pixbase = blockIdx.x * 64;
    if (tid < 64) s_wgt[tid] = (float)g_wgt[pixbase + tid];
    __syncthreads();

    int pix = pixbase + (tid >> 2);
    int kq = tid & 3;
    int2 pcv = g_pc[pix];
    int iy0 = pcv.x, ix0 = pcv.y;
    const __half* ibase = g_in16 + img * 150528;

    uint32_t sb = smem_u32(dsm);
    uint32_t Aln = (lane & 15)*RSTRIDE + (lane >> 4)*16;
    uint32_t Bln = ((lane >> 4)*8 + (lane & 7))*RSTRIDE + ((lane >> 3) & 1)*16;
    uint32_t bsts = (tid >> 2)*RSTRIDE + kq*16;

    uint32_t hw[4];
    #define C1_LDGB(s) do { int kb = (s)*32 + kq*8; \
        unsigned short bu[8]; \
        _Pragma("unroll") for (int j = 0; j < 8; j++) { \
            int k = kb + j; \
            int iy = iy0 + t_ky[k], ix = ix0 + t_kx[k]; \
            bool v = (t_c[k] >= 0) && ((unsigned)iy < 224u) && ((unsigned)ix < 224u); \
            bu[j] = v ? __half_as_ushort(__ldg(ibase + t_c[k] + iy*224 + ix)) : (unsigned short)0; } \
        _Pragma("unroll") for (int j = 0; j < 4; j++) \
            hw[j] = (uint32_t)bu[2*j] | ((uint32_t)bu[2*j+1] << 16); } while (0)
    #define C1_STSB(buf) do { \
        *(uint4*)(dsm + (buf)*STAGE1 + BOFF + bsts) = make_uint4(hw[0], hw[1], hw[2], hw[3]); } while (0)

    float acc[2][4][4];
    #pragma unroll
    for (int a = 0; a < 2; a++)
        #pragma unroll
        for (int b = 0; b < 4; b++)
            #pragma unroll
            for (int c = 0; c < 4; c++) acc[a][b][c] = 0.f;

    CPA(g_w1h, g_w1l, 160, 0, 0, STAGE1);
    CPA(g_w1h, g_w1l, 160, 1, 1, STAGE1);
    C1_LDGB(0);
    CPWAIT(1);
    C1_STSB(0);
    __syncthreads();

    for (int s = 0; s < 5; s++) {
        int buf = s & 1;
        if (s < 4) C1_LDGB(s + 1);
        {
            uint32_t Ab = sb + buf*STAGE1 + warp_m*(32*RSTRIDE);
            uint32_t Bb = sb + buf*STAGE1 + BOFF + warp_n*(32*RSTRIDE);
            #pragma unroll
            for (int h = 0; h < 2; h++) {
                uint32_t ab = Ab + h*32 + Aln;
                uint32_t bb = Bb + h*32 + Bln;
                uint32_t am[2][4], bq[4][2], t[4];
                ldsm4(bb, t); bq[0][0]=t[0]; bq[0][1]=t[1]; bq[1][0]=t[2]; bq[1][1]=t[3];
                ldsm4(bb + 16*RSTRIDE, t); bq[2][0]=t[0]; bq[2][1]=t[1]; bq[3][0]=t[2]; bq[3][1]=t[3];
                ldsm4(ab, am[0]); ldsm4(ab + 16*RSTRIDE, am[1]);
                #pragma unroll
                for (int mt = 0; mt < 2; mt++)
                    #pragma unroll
                    for (int nt = 0; nt < 4; nt++) mma16816(acc[mt][nt], am[mt], bq[nt]);
                ldsm4(ab + ATERM, am[0]); ldsm4(ab + ATERM + 16*RSTRIDE, am[1]);
                #pragma unroll
                for (int mt = 0; mt < 2; mt++)
                    #pragma unroll
                    for (int nt = 0; nt < 4; nt++) mma16816(acc[mt][nt], am[mt], bq[nt]);
            }
        }
        if (s < 4) {
            CPWAIT(0);
            C1_STSB(buf ^ 1);
            __syncthreads();
            if (s + 2 < 5) CPA(g_w1h, g_w1l, 160, s + 2, buf, STAGE1);
        }
    }

    int g = lane >> 2, cp = (lane & 3) * 2;
    #pragma unroll
    for (int mt = 0; mt < 2; mt++) {
        #pragma unroll
        for (int hh = 0; hh < 2; hh++) {
            int oc = warp_m*32 + mt*16 + hh*8 + g;
            float sv = 0.f, qv = 0.f;
            __half* obase = g_fpk + (size_t)(img*128 + oc)*NPMAX + pixbase;
            #pragma unroll
            for (int nt = 0; nt < 4; nt++) {
                float c0 = acc[mt][nt][hh*2], c1 = acc[mt][nt][hh*2 + 1];
                int pxl = warp_n*32 + nt*8 + cp;
                *(__half2*)(obase + pxl) = __floats2half2_rn(c0, c1);
                float w0 = s_wgt[pxl], w1 = s_wgt[pxl + 1];
                sv += w0*c0 + w1*c1; qv += w0*c0*c0 + w1*c1*c1;
            }
            atomicAdd(&s_red[oc], sv);
            atomicAdd(&s_red[128 + oc], qv);
        }
    }
    __syncthreads();
    if (tid < 128) {
        atomicAdd(&g_sum1[tid], s_red[tid]);
        atomicAdd(&g_sq1[tid],  s_red[128 + tid]);
    }
}

// ---------------- BN1 + ReLU + maxpool: plane-in-smem separable version ----------------
// one block per (img, c) plane; 128 threads; thread x = input column
__global__ void __launch_bounds__(128) k_pool(const float* __restrict__ gamma,
                                              const float* __restrict__ beta) {
    __shared__ __half s_val[NPMAX];
    __shared__ __half s_vmx[112], s_vmn[112];

    int ncb = blockIdx.x;             // img*128 + c
    int c = ncb & 127;
    int tid = threadIdx.x;

    // load packed plane (10.75 KB) into smem
    {
        const uint4* src = (const uint4*)(g_fpk + (size_t)ncb * NPMAX);
        uint4* dst = (uint4*)s_val;
        #pragma unroll 6
        for (int i = tid; i < NPMAX/8; i += 128) dst[i] = src[i];
    }
    float mean = g_sum1[c] * (1.f / N1F);
    float var  = g_sq1[c]  * (1.f / N1F) - mean * mean;
    float a = __ldg(gamma + c) * rsqrtf(var + 1e-5f);
    float b = __ldg(beta + c) - a * mean;
    bool pos = (a >= 0.f);
    __syncthreads();

    int x = tid;
    bool act = x < 112;
    __half cmx = __ushort_as_half((unsigned short)0xFC00);
    __half cmn = __ushort_as_half((unsigned short)0x7C00);
    __half* hpO = g_hp + GUARD + (size_t)ncb * PPLANE;
    __half* hsO = g_hs + GUARD + (size_t)ncb * PPLANE;
    __half* hmO = g_hm + GUARD + (size_t)ncb * PPLANE;

    for (int y = 0; y < 56; y++) {
        if (act) {
            __half vb = s_val[__ldg(g_map16 + (2*y)*112 + x)];
            __half vc = s_val[__ldg(g_map16 + (2*y + 1)*112 + x)];
            s_vmx[x] = __hmax(__hmax(cmx, vb), vc);
            s_vmn[x] = __hmin(__hmin(cmn, vb), vc);
            cmx = vc; cmn = vc;
        }
        __syncthreads();
        if (x < 56) {
            int xl = max(2*x - 1, 0);
            float m;
            if (pos) {
                __half hx = __hmax(__hmax(s_vmx[xl], s_vmx[2*x]), s_vmx[2*x + 1]);
                m = fmaf(a, __half2float(hx), b);
            } else {
                __half hn = __hmin(__hmin(s_vmn[xl], s_vmn[2*x]), s_vmn[2*x + 1]);
                m = fmaf(a, __half2float(hn), b);
            }
            __half h = __float2half_rn(fmaxf(m, 0.f));
            int p = (y + 1)*64 + x;
            hpO[p] = h;
            hsO[p - 1] = h;
            hmO[p + 1] = h;
        }
        __syncthreads();
    }
}

// ---------------- conv2: two-row CTA, single-term A, all-16B cp.async, 4 stages ----------------
__global__ void __launch_bounds__(256, 2) k_conv2m(float* __restrict__ out) {
    extern __shared__ __align__(128) char dsm[];
    __shared__ int t_bo[1152];
    __shared__ float s_red[256];

    int tid = threadIdx.x, lane = tid & 31, wid = tid >> 5;
    int warp_m = wid & 3, warp_n = wid >> 2;

    for (int k = tid; k < 1152; k += 256) {
        int ic = k / 9, r = k - ic*9;
        int dy = r/3 - 1, dx = r - (r/3)*3 - 1;
        t_bo[k] = ((ic*PPLANE + dy*64 + 64) << 2) | (dx + 1);
    }
    s_red[tid] = 0.f;
    __syncthreads();

    int img = blockIdx.x / 28;
    int t2  = blockIdx.x - img*28;
    int yp0 = 2*t2 + 1;
    size_t ibase = (size_t)img * 128 * PPLANE;
    const __half* HP = g_hp + GUARD;
    const __half* HS = g_hs + GUARD;
    const __half* HM = g_hm + GUARD;

    uint32_t sb = smem_u32(dsm);

    #define C2_CPA(s, buf) do { \
        _Pragma("unroll") for (int i = 0; i < 2; i++) { \
            int id = tid + i*256, row = id >> 2, c = id & 3; \
            const __half* src = g_w2h + row*1152 + (s)*32 + c*8; \
            uint32_t dst = sb + (buf)*C2_STAGE + row*64 + (((c ^ ((row>>1)&3)) << 4)); \
            CP16(dst, src); } } while (0)
    #define C2_CPB(s, buf) do { \
        _Pragma("unroll") for (int i = 0; i < 2; i++) { \
            int id = tid + i*256, krow = id >> 4, G = id & 15; \
            int p = t_bo[(s)*32 + krow]; \
            int sel = p & 3; \
            const __half* base = (sel == 0) ? HM : ((sel == 1) ? HP : HS); \
            int r = G >> 3, gx = G & 7; \
            const __half* src = base + ibase + ((p >> 2) - 64) + (yp0 + r)*64 + gx*8; \
            uint32_t dst = sb + (buf)*C2_STAGE + C2_BOFF + krow*256 + (((G ^ (krow & 7)) << 4)); \
            CP16(dst, src); } } while (0)

    uint32_t arow = warp_m*32 + (lane & 15);
    uint32_t aswz = (arow >> 1) & 3;
    uint32_t arb  = arow * 64;
    uint32_t acol = lane >> 4;
    uint32_t brow = ((lane >> 3) & 1)*8 + (lane & 7);
    uint32_t bswz = lane & 7;
    uint32_t bg0  = warp_n*8 + (lane >> 4);

    float acc[2][8][4];
    #pragma unroll
    for (int a = 0; a < 2; a++)
        #pragma unroll
        for (int b = 0; b < 8; b++)
            #pragma unroll
            for (int c = 0; c < 4; c++) acc[a][b][c] = 0.f;

    C2_CPA(0, 0); C2_CPB(0, 0); CPCOMMIT();
    C2_CPA(1, 1); C2_CPB(1, 1); CPCOMMIT();
    C2_CPA(2, 2); C2_CPB(2, 2); CPCOMMIT();

    for (int s = 0; s < 36; s++) {
        CPWAIT(2);
        __syncthreads();
        int nb = (s + 3) & 3;
        if (s + 3 < 36) { C2_CPA(s + 3, nb); C2_CPB(s + 3, nb); }
        CPCOMMIT();

        uint32_t bufb = sb + (s & 3) * C2_STAGE;
        #pragma unroll
        for (int h = 0; h < 2; h++) {
            uint32_t t[4];
            uint32_t bq[8][2];
            uint32_t bbase = bufb + C2_BOFF + (h*16 + brow)*256;
            #pragma unroll
            for (int j = 0; j < 4; j++) {
                ldsm4t(bbase + (((bg0 + 2*j) ^ bswz) << 4), t);
                bq[2*j][0]   = t[0]; bq[2*j][1]   = t[1];
                bq[2*j+1][0] = t[2]; bq[2*j+1][1] = t[3];
            }
            uint32_t ac = (((h*2) + acol) ^ aswz) << 4;
            uint32_t am[2][4];
            ldsm4(bufb + arb + ac, am[0]);
            ldsm4(bufb + arb + 1024 + ac, am[1]);
            #pragma unroll
            for (int mt = 0; mt < 2; mt++)
                #pragma unroll
                for (int nt = 0; nt < 8; nt++) mma16816(acc[mt][nt], am[mt], bq[nt]);
        }
    }

    int g = lane >> 2, cp = (lane & 3) * 2;
    int yo = 2*t2 + warp_n;
    #pragma unroll
    for (int mt = 0; mt < 2; mt++) {
        #pragma unroll
        for (int hh = 0; hh < 2; hh++) {
            int oc = warp_m*32 + mt*16 + hh*8 + g;
            float sv = 0.f, qv = 0.f;
            float* obase = out + (size_t)(img*128 + oc)*NPIX2 + yo*56;
            #pragma unroll
            for (int nt = 0; nt < 8; nt++) {
                float c0 = acc[mt][nt][hh*2], c1 = acc[mt][nt][hh*2 + 1];
                int x = nt*8 + cp;
                if (x <= 55) { obase[x] = c0; sv += c0; qv += c0*c0; }
                if (x + 1 <= 55) { obase[x + 1] = c1; sv += c1; qv += c1*c1; }
            }
            atomicAdd(&s_red[oc], sv);
            atomicAdd(&s_red[128 + oc], qv);
        }
    }
    __syncthreads();
    if (tid < 128) {
        atomicAdd(&g_sum2[tid], s_red[tid]);
        atomicAdd(&g_sq2[tid],  s_red[128 + tid]);
    }
}

// ---------------- BN2 + ReLU in place (float4) ----------------
__global__ void k_bn2(float4* __restrict__ out,
                      const float* __restrict__ gamma, const float* __restrict__ beta) {
    int i = blockIdx.x * 256 + threadIdx.x;
    if (i >= BATCH * 128 * (NPIX2/4)) return;
    int c = (i / (NPIX2/4)) & 127;
    float mean = g_sum2[c] * (1.f / N2F);
    float var  = g_sq2[c]  * (1.f / N2F) - mean * mean;
    float a = __ldg(gamma + c) * rsqrtf(var + 1e-5f);
    float b = __ldg(beta + c) - a * mean;
    float4 v = out[i];
    v.x = fmaxf(fmaf(a, v.x, b), 0.f);
    v.y = fmaxf(fmaf(a, v.y, b), 0.f);
    v.z = fmaxf(fmaf(a, v.z, b), 0.f);
    v.w = fmaxf(fmaf(a, v.w, b), 0.f);
    out[i] = v;
}

// ---------------- launch ----------------
extern "C" void kernel_launch(void* const* d_in, const int* in_sizes, int n_in,
                              void* d_out, int out_size) {
    const float* inp = (const float*)d_in[0];
    const float* w1  = (const float*)d_in[1];
    const float* g1  = (const float*)d_in[2];
    const float* b1  = (const float*)d_in[3];
    const float* w2  = (const float*)d_in[4];
    const float* g2  = (const float*)d_in[5];
    const float* b2  = (const float*)d_in[6];
    float* out = (float*)d_out;

    WinTab tab;
    int np = 0;
    for (int s = 0; s < 7; s++) {
        int a = 16*s, b = a + 16, c = 224 - b, d = 224 - a;
        float scale = (float)(2.0 - (double)s / 6.0);
        for (int w = 0; w < 4; w++) {
            int t, l, bt, r;
            if      (w == 0) { t = a; l = a; bt = b; r = c; }
            else if (w == 1) { t = b; l = a; bt = d; r = b; }
            else if (w == 2) { t = c; l = b; bt = d; r = d; }
            else             { t = a; l = c; bt = c; r = d; }
            Win& W = tab.w[s*4 + w];
            W.ti = (int)((float)(t  + 6) / scale) - 3;
            W.li = (int)((float)(l  + 6) / scale) - 3;
            int bi = (int)((float)(bt + 6) / scale) + 3;
            int ri = (int)((float)(r  + 6) / scale) + 3;
            W.to = t >> 1; W.lo = l >> 1;
            W.oh = (bt >> 1) - W.to; W.ow = (r >> 1) - W.lo;
            W.fh = (bi - W.ti - 7) / 2 + 1;
            W.fw = (ri - W.li - 7) / 2 + 1;
            W.base = np;
            np += W.fh * W.fw;
        }
    }
    int tpi = (np + 63) / 64;

    cudaFuncSetAttribute(k_conv1m, cudaFuncAttributeMaxDynamicSharedMemorySize, DYN1);
    cudaFuncSetAttribute(k_conv2m, cudaFuncAttributeMaxDynamicSharedMemorySize, C2_DYN);

    k_init<<<576, 256>>>(w1, w2);
    k_pre<<<PREP_BLKS + MAP_BLKS, 256>>>((const float4*)inp, tab);
    k_conv1m<<<dim3(tpi, BATCH), 256, DYN1>>>();
    k_pool<<<BATCH*128, 128>>>(g1, b1);
    k_conv2m<<<BATCH*28, 256, C2_DYN>>>(out);
    k_bn2<<<(BATCH*128*(NPIX2/4) + 255) / 256, 256>>>((float4*)out, g2, b2);
}

// round 14
// speedup vs baseline: 2.1456x; 1.0244x over previous
#include <cuda_runtime.h>
#include <cuda_fp16.h>
#include <cstdint>

// ---------------- constants ----------------
#define IMG   224
#define BATCH 32
#define NPIX1 12544
#define NPIX2 3136
#define N1F   401408.0f
#define N2F   100352.0f

// conv1 smem geometry (fp16x2: Ah, Al, B)
#define RSTRIDE 80
#define ATERM   10240
#define BOFF    20480
#define STAGE1  25600
#define DYN1    51200

// conv2 geometry: two-row CTA, single-term A (8KB) + B (8KB), 4 stages
#define C2_BOFF  8192
#define C2_STAGE 16384
#define C2_DYN   (4*C2_STAGE)

// padded activation plane
#define PSTRIDE 64
#define PPLANE  3712
#define GUARD   128

// packed conv1 output
#define NPMAX 5376

struct Win { int ti, li, to, lo, oh, ow, fh, fw, base; };
struct WinTab { Win w[28]; };

// ---------------- scratch ----------------
__device__ __half g_in16[BATCH*3*IMG*IMG];
__device__ __half g_fpk[BATCH*128*NPMAX];
__device__ __half g_hp[GUARD + BATCH*128*PPLANE + GUARD];
__device__ __half g_hs[GUARD + BATCH*128*PPLANE + GUARD];
__device__ __half g_hm[GUARD + BATCH*128*PPLANE + GUARD];
__device__ __half g_w1h[128*160], g_w1l[128*160];
__device__ __half g_w2h[128*1152];
__device__ unsigned short g_map16[NPIX1];
__device__ int   g_wgt[NPMAX];
__device__ int2  g_pc[NPMAX];
__device__ float g_sum1[128], g_sq1[128], g_sum2[128], g_sq2[128];

// ---------------- helpers ----------------
__device__ __forceinline__ uint32_t smem_u32(const void* p) {
    uint32_t a;
    asm("{ .reg .u64 t; cvta.to.shared.u64 t, %1; cvt.u32.u64 %0, t; }" : "=r"(a) : "l"(p));
    return a;
}
__device__ __forceinline__ void ldsm4(uint32_t addr, uint32_t* r) {
    asm volatile("ldmatrix.sync.aligned.m8n8.x4.shared.b16 {%0,%1,%2,%3}, [%4];"
        : "=r"(r[0]), "=r"(r[1]), "=r"(r[2]), "=r"(r[3]) : "r"(addr));
}
__device__ __forceinline__ void ldsm4t(uint32_t addr, uint32_t* r) {
    asm volatile("ldmatrix.sync.aligned.m8n8.x4.trans.shared.b16 {%0,%1,%2,%3}, [%4];"
        : "=r"(r[0]), "=r"(r[1]), "=r"(r[2]), "=r"(r[3]) : "r"(addr));
}
__device__ __forceinline__ void mma16816(float* c, const uint32_t* a, const uint32_t* b) {
    asm volatile("mma.sync.aligned.m16n8k16.row.col.f32.f16.f16.f32 "
        "{%0,%1,%2,%3}, {%4,%5,%6,%7}, {%8,%9}, {%0,%1,%2,%3};"
        : "+f"(c[0]), "+f"(c[1]), "+f"(c[2]), "+f"(c[3])
        : "r"(a[0]), "r"(a[1]), "r"(a[2]), "r"(a[3]), "r"(b[0]), "r"(b[1]));
}
#define CP16(dst, src) \
    asm volatile("cp.async.cg.shared.global [%0], [%1], 16;" :: "r"(dst), "l"(src) : "memory")
#define CPCOMMIT() asm volatile("cp.async.commit_group;" ::: "memory")
#define CPWAIT(n)  asm volatile("cp.async.wait_group %0;" :: "n"(n) : "memory")

#define CPA(WH, WL, KDIM, s, buf, STAGE) do { \
    _Pragma("unroll") for (int i = 0; i < 4; i++) { \
        int id = tid + i*256, term = id >> 9, rem = id & 511, row = rem >> 2, c = rem & 3; \
        const __half* src = (term ? (WL) : (WH)) + row*(KDIM) + (s)*32 + c*8; \
        uint32_t dst = sb + (buf)*(STAGE) + term*ATERM + row*RSTRIDE + c*16; \
        CP16(dst, src); } \
    CPCOMMIT(); } while (0)

// ---------------- fused setup: weights | stats-zero | input fp16 | map16 | id table ----------------
#define SU_W 576
#define SU_P 4704
#define SU_M 49
#define SU_I 21
__global__ void k_setup(const float4* __restrict__ inp,
                        const float* __restrict__ w1, const float* __restrict__ w2,
                        WinTab tab) {
    int b = blockIdx.x, tid = threadIdx.x;
    if (b < SU_W) {
        int t = b*256 + tid;
        if (t < 128) { g_sum1[t] = 0.f; g_sq1[t] = 0.f; g_sum2[t] = 0.f; g_sq2[t] = 0.f; }
        if (t < 128*160) {
            int oc = t / 160, k = t - oc*160;
            float v = (k < 147) ? w1[oc*147 + k] : 0.f;
            __half h = __float2half_rn(v);
            g_w1h[t] = h;
            g_w1l[t] = __float2half_rn(v - __half2float(h));
        }
        if (t < 128*1152) g_w2h[t] = __float2half_rn(w2[t]);
    } else if (b < SU_W + SU_P) {
        int i = (b - SU_W)*256 + tid;
        float4 v = inp[i];
        __half2 a = __floats2half2_rn(v.x, v.y);
        __half2 c = __floats2half2_rn(v.z, v.w);
        *(uint2*)(g_in16 + i*4) = make_uint2(*(uint32_t*)&a, *(uint32_t*)&c);
    } else if (b < SU_W + SU_P + SU_M) {
        int pix = (b - SU_W - SU_P)*256 + tid;
        int y = pix / 112, x = pix - y*112;
        int bi = y >> 3, bj = x >> 3;
        int sS = min(min(bi, bj), min(13 - bi, 13 - bj));
        int b2 = 8 * (sS + 1), c2v = 112 - b2;
        int w = (y < b2 && x < c2v) ? 0 : (x < b2 ? 1 : (y >= c2v ? 2 : 3));
        Win W = tab.w[sS*4 + w];
        int fy = ((y - W.to) * W.fh) / W.oh;
        int fx = ((x - W.lo) * W.fw) / W.ow;
        g_map16[pix] = (unsigned short)(W.base + fy * W.fw + fx);
    } else {
        int id = (b - SU_W - SU_P - SU_M)*256 + tid;
        int si = 0;
        #pragma unroll
        for (int i = 1; i < 28; i++) if (id >= tab.w[i].base) si = i;
        Win W = tab.w[si];
        int off = id - W.base;
        if (off < W.fh * W.fw) {
            int fy = off / W.fw, fx = off - fy*W.fw;
            int cy = ((fy+1)*W.oh + W.fh - 1)/W.fh - (fy*W.oh + W.fh - 1)/W.fh;
            int cx = ((fx+1)*W.ow + W.fw - 1)/W.fw - (fx*W.ow + W.fw - 1)/W.fw;
            g_wgt[id] = cy * cx;
            g_pc[id] = make_int2(W.ti + 2*fy - 3, W.li + 2*fx - 3);
        } else {
            g_wgt[id] = 0;
            g_pc[id] = make_int2(0, 0);
        }
    }
}

// ---------------- conv1: fp16x2 over packed pixels, fp16 gather ----------------
__global__ void __launch_bounds__(256, 3) k_conv1m() {
    extern __shared__ __align__(128) char dsm[];
    __shared__ int t_c[160];
    __shared__ signed char t_ky[160], t_kx[160];
    __shared__ float s_red[256];
    __shared__ float s_wgt[64];

    int tid = threadIdx.x, lane = tid & 31, wid = tid >> 5;
    int warp_m = wid & 3, warp_n = wid >> 2;

    if (tid < 160) {
        int k = tid;
        if (k < 147) {
            int c = k / 49, r = k - c*49, ky = r / 7, kx = r - ky*7;
            t_c[k] = c * 50176; t_ky[k] = (signed char)ky; t_kx[k] = (signed char)kx;
        } else { t_c[k] = -1; t_ky[k] = 0; t_kx[k] = 0; }
    }
    s_red[tid] = 0.f;

    int img = blockIdx.y;
    int pixbase = blockIdx.x * 64;
    if (tid < 64) s_wgt[tid] = (float)g_wgt[pixbase + tid];
    __syncthreads();

    int pix = pixbase + (tid >> 2);
    int kq = tid & 3;
    int2 pcv = g_pc[pix];
    int iy0 = pcv.x, ix0 = pcv.y;
    const __half* ibase = g_in16 + img * 150528;

    uint32_t sb = smem_u32(dsm);
    uint32_t Aln = (lane & 15)*RSTRIDE + (lane >> 4)*16;
    uint32_t Bln = ((lane >> 4)*8 + (lane & 7))*RSTRIDE + ((lane >> 3) & 1)*16;
    uint32_t bsts = (tid >> 2)*RSTRIDE + kq*16;

    uint32_t hw[4];
    #define C1_LDGB(s) do { int kb = (s)*32 + kq*8; \
        unsigned short bu[8]; \
        _Pragma("unroll") for (int j = 0; j < 8; j++) { \
            int k = kb + j; \
            int iy = iy0 + t_ky[k], ix = ix0 + t_kx[k]; \
            bool v = (t_c[k] >= 0) && ((unsigned)iy < 224u) && ((unsigned)ix < 224u); \
            bu[j] = v ? __half_as_ushort(__ldg(ibase + t_c[k] + iy*224 + ix)) : (unsigned short)0; } \
        _Pragma("unroll") for (int j = 0; j < 4; j++) \
            hw[j] = (uint32_t)bu[2*j] | ((uint32_t)bu[2*j+1] << 16); } while (0)
    #define C1_STSB(buf) do { \
        *(uint4*)(dsm + (buf)*STAGE1 + BOFF + bsts) = make_uint4(hw[0], hw[1], hw[2], hw[3]); } while (0)

    float acc[2][4][4];
    #pragma unroll
    for (int a = 0; a < 2; a++)
        #pragma unroll
        for (int b = 0; b < 4; b++)
            #pragma unroll
            for (int c = 0; c < 4; c++) acc[a][b][c] = 0.f;

    CPA(g_w1h, g_w1l, 160, 0, 0, STAGE1);
    CPA(g_w1h, g_w1l, 160, 1, 1, STAGE1);
    C1_LDGB(0);
    CPWAIT(1);
    C1_STSB(0);
    __syncthreads();

    for (int s = 0; s < 5; s++) {
        int buf = s & 1;
        if (s < 4) C1_LDGB(s + 1);
        {
            uint32_t Ab = sb + buf*STAGE1 + warp_m*(32*RSTRIDE);
            uint32_t Bb = sb + buf*STAGE1 + BOFF + warp_n*(32*RSTRIDE);
            #pragma unroll
            for (int h = 0; h < 2; h++) {
                uint32_t ab = Ab + h*32 + Aln;
                uint32_t bb = Bb + h*32 + Bln;
                uint32_t am[2][4], bq[4][2], t[4];
                ldsm4(bb, t); bq[0][0]=t[0]; bq[0][1]=t[1]; bq[1][0]=t[2]; bq[1][1]=t[3];
                ldsm4(bb + 16*RSTRIDE, t); bq[2][0]=t[0]; bq[2][1]=t[1]; bq[3][0]=t[2]; bq[3][1]=t[3];
                ldsm4(ab, am[0]); ldsm4(ab + 16*RSTRIDE, am[1]);
                #pragma unroll
                for (int mt = 0; mt < 2; mt++)
                    #pragma unroll
                    for (int nt = 0; nt < 4; nt++) mma16816(acc[mt][nt], am[mt], bq[nt]);
                ldsm4(ab + ATERM, am[0]); ldsm4(ab + ATERM + 16*RSTRIDE, am[1]);
                #pragma unroll
                for (int mt = 0; mt < 2; mt++)
                    #pragma unroll
                    for (int nt = 0; nt < 4; nt++) mma16816(acc[mt][nt], am[mt], bq[nt]);
            }
        }
        if (s < 4) {
            CPWAIT(0);
            C1_STSB(buf ^ 1);
            __syncthreads();
            if (s + 2 < 5) CPA(g_w1h, g_w1l, 160, s + 2, buf, STAGE1);
        }
    }

    int g = lane >> 2, cp = (lane & 3) * 2;
    #pragma unroll
    for (int mt = 0; mt < 2; mt++) {
        #pragma unroll
        for (int hh = 0; hh < 2; hh++) {
            int oc = warp_m*32 + mt*16 + hh*8 + g;
            float sv = 0.f, qv = 0.f;
            __half* obase = g_fpk + (size_t)(img*128 + oc)*NPMAX + pixbase;
            #pragma unroll
            for (int nt = 0; nt < 4; nt++) {
                float c0 = acc[mt][nt][hh*2], c1 = acc[mt][nt][hh*2 + 1];
                int pxl = warp_n*32 + nt*8 + cp;
                *(__half2*)(obase + pxl) = __floats2half2_rn(c0, c1);
                float w0 = s_wgt[pxl], w1 = s_wgt[pxl + 1];
                sv += w0*c0 + w1*c1; qv += w0*c0*c0 + w1*c1*c1;
            }
            atomicAdd(&s_red[oc], sv);
            atomicAdd(&s_red[128 + oc], qv);
        }
    }
    __syncthreads();
    if (tid < 128) {
        atomicAdd(&g_sum1[tid], s_red[tid]);
        atomicAdd(&g_sq1[tid],  s_red[128 + tid]);
    }
}

// ---------------- BN1 + ReLU + maxpool v4: warp-autonomous, 4 planes/block ----------------
__global__ void __launch_bounds__(256) k_pool(const float* __restrict__ gamma,
                                              const float* __restrict__ beta) {
    __shared__ __half s_val[4*NPMAX];

    int tid = threadIdx.x;
    int ncb0 = blockIdx.x * 4;

    {   // load 4 packed planes (43 KB)
        const uint4* src = (const uint4*)(g_fpk + (size_t)ncb0 * NPMAX);
        uint4* dst = (uint4*)s_val;
        #pragma unroll 11
        for (int i = tid; i < 4*NPMAX/8; i += 256) dst[i] = src[i];
    }
    __syncthreads();

    int w = tid >> 5, lane = tid & 31;
    int plane = w >> 1, wp = w & 1;
    int ncb = ncb0 + plane;
    int c = ncb & 127;
    float mean = g_sum1[c] * (1.f / N1F);
    float var  = g_sq1[c]  * (1.f / N1F) - mean * mean;
    float a = __ldg(gamma + c) * rsqrtf(var + 1e-5f);
    float bb = __ldg(beta + c) - a * mean;
    bool pos = (a >= 0.f);
    const __half* sp = s_val + plane * NPMAX;

    int x = 28*wp + lane;            // output column (valid for lane<28)
    bool bnd = lane >= 28;
    int ce = max(56*wp - 1, 0);      // boundary column for shfl source
    int c0 = bnd ? (ce & ~1) : 2*x;  // even column (aligned 4B map load)

    const __half NEGI = __ushort_as_half((unsigned short)0xFC00);
    const __half POSI = __ushort_as_half((unsigned short)0x7C00);
    __half cvx0 = NEGI, cvn0 = POSI, cvx1 = NEGI, cvn1 = POSI;

    __half* hpO = g_hp + GUARD + (size_t)ncb * PPLANE;
    __half* hsO = g_hs + GUARD + (size_t)ncb * PPLANE;
    __half* hmO = g_hm + GUARD + (size_t)ncb * PPLANE;

    int srcl = lane ? lane - 1 : 28;

    for (int y = 0; y < 56; y++) {
        const unsigned short* m0 = g_map16 + (2*y)*112;
        uint32_t u0 = __ldg((const uint32_t*)(m0 + c0));
        uint32_t u1 = __ldg((const uint32_t*)(m0 + 112 + c0));
        __half a0 = sp[u0 & 0xffff], a1 = sp[u0 >> 16];
        __half b0 = sp[u1 & 0xffff], b1 = sp[u1 >> 16];
        __half mx0 = __hmax(__hmax(cvx0, a0), b0);
        __half mn0 = __hmin(__hmin(cvn0, a0), b0);
        __half mx1 = __hmax(__hmax(cvx1, a1), b1);
        __half mn1 = __hmin(__hmin(cvn1, a1), b1);
        cvx0 = b0; cvn0 = b0; cvx1 = b1; cvn1 = b1;

        __half sx = mx1, sn = mn1;
        if (bnd && !(ce & 1)) { sx = mx0; sn = mn0; }
        uint32_t pk = ((uint32_t)__half_as_ushort(sx)) | ((uint32_t)__half_as_ushort(sn) << 16);
        uint32_t pv = __shfl_sync(0xFFFFFFFFu, pk, srcl);

        if (lane < 28) {
            float m;
            if (pos) {
                __half px = __ushort_as_half((unsigned short)pv);
                m = fmaf(a, __half2float(__hmax(__hmax(px, mx0), mx1)), bb);
            } else {
                __half pn = __ushort_as_half((unsigned short)(pv >> 16));
                m = fmaf(a, __half2float(__hmin(__hmin(pn, mn0), mn1)), bb);
            }
            __half h = __float2half_rn(fmaxf(m, 0.f));
            int p = (y + 1)*64 + x;
            hpO[p] = h;
            hsO[p - 1] = h;
            hmO[p + 1] = h;
        }
    }
}

// ---------------- conv2: two-row CTA, single-term A, all-16B cp.async, 4 stages ----------------
__global__ void __launch_bounds__(256, 2) k_conv2m(float* __restrict__ out) {
    extern __shared__ __align__(128) char dsm[];
    __shared__ int t_bo[1152];
    __shared__ float s_red[256];

    int tid = threadIdx.x, lane = tid & 31, wid = tid >> 5;
    int warp_m = wid & 3, warp_n = wid >> 2;

    for (int k = tid; k < 1152; k += 256) {
        int ic = k / 9, r = k - ic*9;
        int dy = r/3 - 1, dx = r - (r/3)*3 - 1;
        t_bo[k] = ((ic*PPLANE + dy*64 + 64) << 2) | (dx + 1);
    }
    s_red[tid] = 0.f;
    __syncthreads();

    int img = blockIdx.x / 28;
    int t2  = blockIdx.x - img*28;
    int yp0 = 2*t2 + 1;
    size_t ibase = (size_t)img * 128 * PPLANE;
    const __half* HP = g_hp + GUARD;
    const __half* HS = g_hs + GUARD;
    const __half* HM = g_hm + GUARD;

    uint32_t sb = smem_u32(dsm);

    #define C2_CPA(s, buf) do { \
        _Pragma("unroll") for (int i = 0; i < 2; i++) { \
            int id = tid + i*256, row = id >> 2, c = id & 3; \
            const __half* src = g_w2h + row*1152 + (s)*32 + c*8; \
            uint32_t dst = sb + (buf)*C2_STAGE + row*64 + (((c ^ ((row>>1)&3)) << 4)); \
            CP16(dst, src); } } while (0)
    #define C2_CPB(s, buf) do { \
        _Pragma("unroll") for (int i = 0; i < 2; i++) { \
            int id = tid + i*256, krow = id >> 4, G = id & 15; \
            int p = t_bo[(s)*32 + krow]; \
            int sel = p & 3; \
            const __half* base = (sel == 0) ? HM : ((sel == 1) ? HP : HS); \
            int r = G >> 3, gx = G & 7; \
            const __half* src = base + ibase + ((p >> 2) - 64) + (yp0 + r)*64 + gx*8; \
            uint32_t dst = sb + (buf)*C2_STAGE + C2_BOFF + krow*256 + (((G ^ (krow & 7)) << 4)); \
            CP16(dst, src); } } while (0)

    uint32_t arow = warp_m*32 + (lane & 15);
    uint32_t aswz = (arow >> 1) & 3;
    uint32_t arb  = arow * 64;
    uint32_t acol = lane >> 4;
    uint32_t brow = ((lane >> 3) & 1)*8 + (lane & 7);
    uint32_t bswz = lane & 7;
    uint32_t bg0  = warp_n*8 + (lane >> 4);

    float acc[2][8][4];
    #pragma unroll
    for (int a = 0; a < 2; a++)
        #pragma unroll
        for (int b = 0; b < 8; b++)
            #pragma unroll
            for (int c = 0; c < 4; c++) acc[a][b][c] = 0.f;

    C2_CPA(0, 0); C2_CPB(0, 0); CPCOMMIT();
    C2_CPA(1, 1); C2_CPB(1, 1); CPCOMMIT();
    C2_CPA(2, 2); C2_CPB(2, 2); CPCOMMIT();

    for (int s = 0; s < 36; s++) {
        CPWAIT(2);
        __syncthreads();
        int nb = (s + 3) & 3;
        if (s + 3 < 36) { C2_CPA(s + 3, nb); C2_CPB(s + 3, nb); }
        CPCOMMIT();

        uint32_t bufb = sb + (s & 3) * C2_STAGE;
        #pragma unroll
        for (int h = 0; h < 2; h++) {
            uint32_t t[4];
            uint32_t bq[8][2];
            uint32_t bbase = bufb + C2_BOFF + (h*16 + brow)*256;
            #pragma unroll
            for (int j = 0; j < 4; j++) {
                ldsm4t(bbase + (((bg0 + 2*j) ^ bswz) << 4), t);
                bq[2*j][0]   = t[0]; bq[2*j][1]   = t[1];
                bq[2*j+1][0] = t[2]; bq[2*j+1][1] = t[3];
            }
            uint32_t ac = (((h*2) + acol) ^ aswz) << 4;
            uint32_t am[2][4];
            ldsm4(bufb + arb + ac, am[0]);
            ldsm4(bufb + arb + 1024 + ac, am[1]);
            #pragma unroll
            for (int mt = 0; mt < 2; mt++)
                #pragma unroll
                for (int nt = 0; nt < 8; nt++) mma16816(acc[mt][nt], am[mt], bq[nt]);
        }
    }

    int g = lane >> 2, cp = (lane & 3) * 2;
    int yo = 2*t2 + warp_n;
    #pragma unroll
    for (int mt = 0; mt < 2; mt++) {
        #pragma unroll
        for (int hh = 0; hh < 2; hh++) {
            int oc = warp_m*32 + mt*16 + hh*8 + g;
            float sv = 0.f, qv = 0.f;
            float* obase = out + (size_t)(img*128 + oc)*NPIX2 + yo*56;
            #pragma unroll
            for (int nt = 0; nt < 8; nt++) {
                float c0 = acc[mt][nt][hh*2], c1 = acc[mt][nt][hh*2 + 1];
                int x = nt*8 + cp;
                if (x <= 55) { obase[x] = c0; sv += c0; qv += c0*c0; }
                if (x + 1 <= 55) { obase[x + 1] = c1; sv += c1; qv += c1*c1; }
            }
            atomicAdd(&s_red[oc], sv);
            atomicAdd(&s_red[128 + oc], qv);
        }
    }
    __syncthreads();
    if (tid < 128) {
        atomicAdd(&g_sum2[tid], s_red[tid]);
        atomicAdd(&g_sq2[tid],  s_red[128 + tid]);
    }
}

// ---------------- BN2 + ReLU in place (float4) ----------------
__global__ void k_bn2(float4* __restrict__ out,
                      const float* __restrict__ gamma, const float* __restrict__ beta) {
    int i = blockIdx.x * 256 + threadIdx.x;
    if (i >= BATCH * 128 * (NPIX2/4)) return;
    int c = (i / (NPIX2/4)) & 127;
    float mean = g_sum2[c] * (1.f / N2F);
    float var  = g_sq2[c]  * (1.f / N2F) - mean * mean;
    float a = __ldg(gamma + c) * rsqrtf(var + 1e-5f);
    float b = __ldg(beta + c) - a * mean;
    float4 v = out[i];
    v.x = fmaxf(fmaf(a, v.x, b), 0.f);
    v.y = fmaxf(fmaf(a, v.y, b), 0.f);
    v.z = fmaxf(fmaf(a, v.z, b), 0.f);
    v.w = fmaxf(fmaf(a, v.w, b), 0.f);
    out[i] = v;
}

// ---------------- launch ----------------
extern "C" void kernel_launch(void* const* d_in, const int* in_sizes, int n_in,
                              void* d_out, int out_size) {
    const float* inp = (const float*)d_in[0];
    const float* w1  = (const float*)d_in[1];
    const float* g1  = (const float*)d_in[2];
    const float* b1  = (const float*)d_in[3];
    const float* w2  = (const float*)d_in[4];
    const float* g2  = (const float*)d_in[5];
    const float* b2  = (const float*)d_in[6];
    float* out = (float*)d_out;

    WinTab tab;
    int np = 0;
    for (int s = 0; s < 7; s++) {
        int a = 16*s, b = a + 16, c = 224 - b, d = 224 - a;
        float scale = (float)(2.0 - (double)s / 6.0);
        for (int w = 0; w < 4; w++) {
            int t, l, bt, r;
            if      (w == 0) { t = a; l = a; bt = b; r = c; }
            else if (w == 1) { t = b; l = a; bt = d; r = b; }
            else if (w == 2) { t = c; l = b; bt = d; r = d; }
            else             { t = a; l = c; bt = c; r = d; }
            Win& W = tab.w[s*4 + w];
            W.ti = (int)((float)(t  + 6) / scale) - 3;
            W.li = (int)((float)(l  + 6) / scale) - 3;
            int bi = (int)((float)(bt + 6) / scale) + 3;
            int ri = (int)((float)(r  + 6) / scale) + 3;
            W.to = t >> 1; W.lo = l >> 1;
            W.oh = (bt >> 1) - W.to; W.ow = (r >> 1) - W.lo;
            W.fh = (bi - W.ti - 7) / 2 + 1;
            W.fw = (ri - W.li - 7) / 2 + 1;
            W.base = np;
            np += W.fh * W.fw;
        }
    }
    int tpi = (np + 63) / 64;

    cudaFuncSetAttribute(k_conv1m, cudaFuncAttributeMaxDynamicSharedMemorySize, DYN1);
    cudaFuncSetAttribute(k_conv2m, cudaFuncAttributeMaxDynamicSharedMemorySize, C2_DYN);

    k_setup<<<SU_W + SU_P + SU_M + SU_I, 256>>>((const float4*)inp, w1, w2, tab);
    k_conv1m<<<dim3(tpi, BATCH), 256, DYN1>>>();
    k_pool<<<BATCH*32, 256>>>(g1, b1);
    k_conv2m<<<BATCH*28, 256, C2_DYN>>>(out);
    k_bn2<<<(BATCH*128*(NPIX2/4) + 255) / 256, 256>>>((float4*)out, g2, b2);
}